// round 11
// baseline (speedup 1.0000x reference)
#include <cuda_runtime.h>
#include <cuda_bf16.h>
#include <cstdint>

#define D_MODEL 1024
#define N_HEADS 16
#define HD      64
#define T_SEQ   2048
#define BATCH   2
#define M_ROWS  (BATCH * T_SEQ)   // 4096
#define KPAIRS  (D_MODEL / 2)     // 512 pairs per row

// ---------------------------------------------------------------------------
// Scratch (device globals; no allocation allowed)
// ---------------------------------------------------------------------------
__device__ uint32_t g_Xh[M_ROWS * KPAIRS];          // X pre-split hi plane
__device__ uint32_t g_Xl[M_ROWS * KPAIRS];
__device__ uint32_t g_Wh[4 * D_MODEL * KPAIRS];     // Wq,Wk,Wv,Wo hi planes
__device__ uint32_t g_Wl[4 * D_MODEL * KPAIRS];
__device__ uint32_t g_Qh[BATCH * N_HEADS * T_SEQ * (HD / 2)];  // [b,h,t,dpair]
__device__ uint32_t g_Ql[BATCH * N_HEADS * T_SEQ * (HD / 2)];
__device__ uint32_t g_Kh[BATCH * N_HEADS * T_SEQ * (HD / 2)];
__device__ uint32_t g_Kl[BATCH * N_HEADS * T_SEQ * (HD / 2)];
// V packed pair-of-rows: [b,h,tpair,d] u32 = bf16x2(row 2p, row 2p+1) at col d
__device__ uint32_t g_Vph[BATCH * N_HEADS * (T_SEQ / 2) * HD];
__device__ uint32_t g_Vpl[BATCH * N_HEADS * (T_SEQ / 2) * HD];
__device__ uint32_t g_atth[M_ROWS * KPAIRS];        // attention output packed
__device__ uint32_t g_attl[M_ROWS * KPAIRS];

// ---------------------------------------------------------------------------
// helpers
// ---------------------------------------------------------------------------
__device__ __forceinline__ void split2(float x0, float x1, uint32_t& h, uint32_t& l)
{
    __nv_bfloat162 hh = __floats2bfloat162_rn(x0, x1);
    float2 hf = __bfloat1622float2(hh);
    __nv_bfloat162 ll = __floats2bfloat162_rn(x0 - hf.x, x1 - hf.y);
    h = *reinterpret_cast<uint32_t*>(&hh);
    l = *reinterpret_cast<uint32_t*>(&ll);
}

__device__ __forceinline__ void mma16(float* c,
                                      uint32_t a0, uint32_t a1, uint32_t a2, uint32_t a3,
                                      uint32_t b0, uint32_t b1)
{
    asm volatile(
        "mma.sync.aligned.m16n8k16.row.col.f32.bf16.bf16.f32 "
        "{%0,%1,%2,%3}, {%4,%5,%6,%7}, {%8,%9}, {%0,%1,%2,%3};"
        : "+f"(c[0]), "+f"(c[1]), "+f"(c[2]), "+f"(c[3])
        : "r"(a0), "r"(a1), "r"(a2), "r"(a3), "r"(b0), "r"(b1));
}

__device__ __forceinline__ void ldsm4(uint32_t& r0, uint32_t& r1,
                                      uint32_t& r2, uint32_t& r3, uint32_t addr)
{
    asm volatile("ldmatrix.sync.aligned.m8n8.x4.shared.b16 {%0,%1,%2,%3}, [%4];"
                 : "=r"(r0), "=r"(r1), "=r"(r2), "=r"(r3) : "r"(addr));
}

__device__ __forceinline__ void cp16(void* dst_smem, const void* src)
{
    uint32_t s = (uint32_t)__cvta_generic_to_shared(dst_smem);
    asm volatile("cp.async.cg.shared.global [%0], [%1], 16;\n" :: "r"(s), "l"(src));
}
__device__ __forceinline__ void cp_commit()
{
    asm volatile("cp.async.commit_group;\n" ::);
}
template<int N>
__device__ __forceinline__ void cp_wait()
{
    asm volatile("cp.async.wait_group %0;\n" :: "n"(N));
}

// ---------------------------------------------------------------------------
// Prep kernel: split X and Wq/Wk/Wv/Wo into bf16x2 hi/lo planes (once).
// ---------------------------------------------------------------------------
__global__ void __launch_bounds__(256)
prep_kernel(const float* __restrict__ X,
            const float* __restrict__ Wq, const float* __restrict__ Wk,
            const float* __restrict__ Wv, const float* __restrict__ Wo)
{
    const int seg = blockIdx.y;
    const int idx = blockIdx.x * 256 + threadIdx.x;
    const float* src;
    uint32_t *dh, *dl;
    if (seg < 4) {
        src = X + (size_t)seg * 1048576;
        dh = g_Xh + (size_t)seg * 524288;
        dl = g_Xl + (size_t)seg * 524288;
    } else {
        const float* ws[4] = {Wq, Wk, Wv, Wo};
        src = ws[seg - 4];
        dh = g_Wh + (size_t)(seg - 4) * 524288;
        dl = g_Wl + (size_t)(seg - 4) * 524288;
    }
    float2 v = *(const float2*)(src + 2 * (size_t)idx);
    uint32_t h, l;
    split2(v.x, v.y, h, l);
    dh[idx] = h;
    dl[idx] = l;
}

// ---------------------------------------------------------------------------
// 3xBF16 mma.sync GEMM tile: Y[128,128 @ (m0,n0)] = X @ W^T + bias
// XOR-swizzled smem (RSU=16, chunk' = chunk ^ ((row>>1)&3)); NBUF=3;
// one __syncthreads + one cp_wait per 96-MMA period, prefetch distance 2.
// Output modes: 0 = packed Q/K planes, 1 = V packed pair-of-rows planes,
//               2 = float row-major (final out).
// ---------------------------------------------------------------------------
#define RSU      16                  // u32 per plane row (no pad)
#define PLANE_U  (128 * RSU)         // 2048 u32 per plane
#define BUF_U    (4 * PLANE_U)       // Ah, Al, Bh, Bl = 32 KB
#define NBUF     3
#define NPER     (D_MODEL / 32)      // 32 periods
#define GEMM_SMEM_BYTES (NBUF * BUF_U * 4)   // 98304

__device__ __forceinline__ uint32_t sw_off(int row, int chunk)
{
    return (uint32_t)(row * RSU + ((chunk ^ ((row >> 1) & 3)) << 2));
}

__device__ __forceinline__ void gemm_tile(int m0, int n0,
                                          const uint32_t* __restrict__ Xh,
                                          const uint32_t* __restrict__ Xl,
                                          const uint32_t* __restrict__ Wh,
                                          const uint32_t* __restrict__ Wl,
                                          const float* __restrict__ bias,
                                          uint32_t* __restrict__ Yh,
                                          uint32_t* __restrict__ Yl,
                                          float* __restrict__ Yf,
                                          int mode)
{
    extern __shared__ uint32_t smem[];
    const uint32_t sbase = (uint32_t)__cvta_generic_to_shared(smem);

    const int tid  = threadIdx.x;
    const int lane = tid & 31;
    const int wid  = tid >> 5;
    const int wm   = wid >> 2;
    const int wn   = wid & 3;
    const int g    = lane >> 2;
    const int t    = lane & 3;

    const int lrow = tid >> 2;
    const int lcix = tid & 3;
    const uint32_t ldst0 = sw_off(lrow,      lcix);
    const uint32_t ldst1 = sw_off(lrow + 64, lcix);

    const uint32_t* srcs[4] = {
        Xh + (size_t)m0 * KPAIRS, Xl + (size_t)m0 * KPAIRS,
        Wh + (size_t)n0 * KPAIRS, Wl + (size_t)n0 * KPAIRS };

    const int a_row = (lane & 7) + ((lane >> 3) & 1) * 8;
    const int hiA   = lane >> 4;
    int baseA[4], swA[4];
#pragma unroll
    for (int mt = 0; mt < 4; mt++) {
        int rg = wm * 64 + mt * 16 + a_row;
        baseA[mt] = rg * RSU;
        swA[mt]   = (rg >> 1) & 3;
    }
    const int b_row = (lane & 7) + ((lane >> 4) ? 8 : 0);
    const int hiB   = (lane >> 3) & 1;
    const int rgB0  = wn * 32 + b_row;
    const int rgB1  = rgB0 + 16;
    const int baseB0 = rgB0 * RSU, swB0 = (rgB0 >> 1) & 3;
    const int baseB1 = rgB1 * RSU, swB1 = (rgB1 >> 1) & 3;

    float acc[4][4][4];
#pragma unroll
    for (int i = 0; i < 4; i++)
#pragma unroll
        for (int j = 0; j < 4; j++)
#pragma unroll
            for (int q = 0; q < 4; q++) acc[i][j][q] = 0.f;

    auto load_buf = [&](int b, int p) {
        uint32_t* base = smem + b * BUF_U;
        const int koff = p * 16;
#pragma unroll
        for (int pi = 0; pi < 4; pi++) {
            const uint32_t* sp = srcs[pi] + koff + lcix * 4;
            uint32_t* dp = base + pi * PLANE_U;
            cp16(dp + ldst0, sp + (size_t)lrow * KPAIRS);
            cp16(dp + ldst1, sp + (size_t)(lrow + 64) * KPAIRS);
        }
        cp_commit();
    };

    // prologue
    load_buf(0, 0);
    load_buf(1, 1);

    for (int p = 0; p < NPER; p++) {
        cp_wait<1>();
        __syncthreads();
        if (p + 2 < NPER) load_buf((p + 2) % 3, p + 2);
        else              cp_commit();

        const uint32_t stb = sbase + (uint32_t)((p % 3) * BUF_U) * 4;

#pragma unroll
        for (int ks = 0; ks < 2; ks++) {
            uint32_t Ah[4][4], Al[4][4];
#pragma unroll
            for (int mt = 0; mt < 4; mt++) {
                uint32_t offA = (uint32_t)(baseA[mt] +
                                (((2 * ks + hiA) ^ swA[mt]) << 2)) * 4;
                ldsm4(Ah[mt][0], Ah[mt][1], Ah[mt][2], Ah[mt][3], stb + offA);
                ldsm4(Al[mt][0], Al[mt][1], Al[mt][2], Al[mt][3],
                      stb + PLANE_U * 4 + offA);
            }
            uint32_t offB0 = (uint32_t)(baseB0 + (((2 * ks + hiB) ^ swB0) << 2)) * 4;
            uint32_t offB1 = (uint32_t)(baseB1 + (((2 * ks + hiB) ^ swB1) << 2)) * 4;
            uint32_t Bh[4][2], Bl[4][2];
            ldsm4(Bh[0][0], Bh[0][1], Bh[1][0], Bh[1][1],
                  stb + 2 * PLANE_U * 4 + offB0);
            ldsm4(Bh[2][0], Bh[2][1], Bh[3][0], Bh[3][1],
                  stb + 2 * PLANE_U * 4 + offB1);
            ldsm4(Bl[0][0], Bl[0][1], Bl[1][0], Bl[1][1],
                  stb + 3 * PLANE_U * 4 + offB0);
            ldsm4(Bl[2][0], Bl[2][1], Bl[3][0], Bl[3][1],
                  stb + 3 * PLANE_U * 4 + offB1);

#pragma unroll
            for (int mt = 0; mt < 4; mt++)
#pragma unroll
                for (int nt = 0; nt < 4; nt++)
                    mma16(acc[mt][nt], Ah[mt][0], Ah[mt][1], Ah[mt][2], Ah[mt][3],
                          Bh[nt][0], Bh[nt][1]);
#pragma unroll
            for (int mt = 0; mt < 4; mt++)
#pragma unroll
                for (int nt = 0; nt < 4; nt++)
                    mma16(acc[mt][nt], Ah[mt][0], Ah[mt][1], Ah[mt][2], Ah[mt][3],
                          Bl[nt][0], Bl[nt][1]);
#pragma unroll
            for (int mt = 0; mt < 4; mt++)
#pragma unroll
                for (int nt = 0; nt < 4; nt++)
                    mma16(acc[mt][nt], Al[mt][0], Al[mt][1], Al[mt][2], Al[mt][3],
                          Bh[nt][0], Bh[nt][1]);
        }
    }

    // epilogue
#pragma unroll
    for (int mt = 0; mt < 4; mt++) {
        int rm = m0 + wm * 64 + mt * 16 + g;
#pragma unroll
        for (int nt = 0; nt < 4; nt++) {
            int cn = n0 + wn * 32 + nt * 8 + 2 * t;
            float bb0 = bias[cn];
            float bb1 = bias[cn + 1];
            float2 v0 = make_float2(acc[mt][nt][0] + bb0, acc[mt][nt][1] + bb1);
            float2 v1 = make_float2(acc[mt][nt][2] + bb0, acc[mt][nt][3] + bb1);
            if (mode == 0) {
                int head = cn >> 6;
                int pr   = (cn & 63) >> 1;
#pragma unroll
                for (int rr = 0; rr < 2; rr++) {
                    int row = rm + rr * 8;
                    float2 v = rr ? v1 : v0;
                    int bb = row >> 11;
                    int tt = row & (T_SEQ - 1);
                    size_t base = (((size_t)bb * N_HEADS + head) * T_SEQ + tt) * (HD / 2) + pr;
                    uint32_t hh, ll;
                    split2(v.x, v.y, hh, ll);
                    Yh[base] = hh;
                    Yl[base] = ll;
                }
            } else if (mode == 1) {
                // V: pair adjacent rows (rm even for even g) via shuffle,
                // store packed pair-of-rows planes [b,h,tpair,d]
                int head = cn >> 6;
                int d    = cn & 63;
                float p0x = __shfl_down_sync(0xffffffffu, v0.x, 4);
                float p0y = __shfl_down_sync(0xffffffffu, v0.y, 4);
                float p1x = __shfl_down_sync(0xffffffffu, v1.x, 4);
                float p1y = __shfl_down_sync(0xffffffffu, v1.y, 4);
                if ((g & 1) == 0) {
                    int bb = rm >> 11;
                    int tt = rm & (T_SEQ - 1);
                    size_t idx0 = (((size_t)bb * N_HEADS + head) * (T_SEQ / 2)
                                   + (tt >> 1)) * HD + d;
                    size_t idx1 = idx0 + 4 * HD;   // rows rm+8, rm+9
                    uint32_t hh, ll;
                    split2(v0.x, p0x, hh, ll); Yh[idx0] = hh;     Yl[idx0] = ll;
                    split2(v0.y, p0y, hh, ll); Yh[idx0 + 1] = hh; Yl[idx0 + 1] = ll;
                    split2(v1.x, p1x, hh, ll); Yh[idx1] = hh;     Yl[idx1] = ll;
                    split2(v1.y, p1y, hh, ll); Yh[idx1 + 1] = hh; Yl[idx1 + 1] = ll;
                }
            } else {
                *(float2*)(Yf + (size_t)rm * D_MODEL + cn) = v0;
                *(float2*)(Yf + (size_t)(rm + 8) * D_MODEL + cn) = v1;
            }
        }
    }
}

// persistent qkv: 768 tiles (z-major), grid = 296
__global__ void __launch_bounds__(256, 2)
qkv_kernel(const float* __restrict__ bq, const float* __restrict__ bk,
           const float* __restrict__ bv)
{
    for (int tile = blockIdx.x; tile < 768; tile += gridDim.x) {
        const int z   = tile >> 8;
        const int rem = tile & 255;
        const int m0  = (rem >> 3) << 7;
        const int n0  = (rem & 7) << 7;
        __syncthreads();   // protect smem reuse across tile iterations
        const float* bias = (z == 0) ? bq : (z == 1) ? bk : bv;
        const uint32_t* Wh = g_Wh + (size_t)z * D_MODEL * KPAIRS;
        const uint32_t* Wl = g_Wl + (size_t)z * D_MODEL * KPAIRS;
        if (z == 0)
            gemm_tile(m0, n0, g_Xh, g_Xl, Wh, Wl, bias, g_Qh, g_Ql, nullptr, 0);
        else if (z == 1)
            gemm_tile(m0, n0, g_Xh, g_Xl, Wh, Wl, bias, g_Kh, g_Kl, nullptr, 0);
        else
            gemm_tile(m0, n0, g_Xh, g_Xl, Wh, Wl, bias, g_Vph, g_Vpl, nullptr, 1);
    }
}

__global__ void __launch_bounds__(256, 2)
out_kernel(const float* __restrict__ bo, float* __restrict__ out)
{
    gemm_tile(blockIdx.y * 128, blockIdx.x * 128,
              g_atth, g_attl,
              g_Wh + (size_t)3 * D_MODEL * KPAIRS,
              g_Wl + (size_t)3 * D_MODEL * KPAIRS,
              bo, nullptr, nullptr, out, 2);
}

// ---------------------------------------------------------------------------
// Tensor-core flash attention, 3xBF16 mma.sync, FIXED-MAX softmax.
// Q/K/V all pre-split packed; entire tile load is cp.async. No split ALU
// in the loop except P.
// ---------------------------------------------------------------------------
#define QH_OFF 0
#define QL_OFF 4608
#define KH_OFF 9216
#define KL_OFF 11520
#define VH_OFF 13824
#define VL_OFF 16128
#define PH_OFF 18432
#define PL_OFF 23040
#define ATT_U32 27648
#define ATT_SMEM_BYTES (ATT_U32 * 4)   // 110592

__global__ void __launch_bounds__(256, 2) attn_kernel()
{
    extern __shared__ uint32_t su[];
    uint32_t* Qh = su + QH_OFF;
    uint32_t* Ql = su + QL_OFF;
    uint32_t* Kh = su + KH_OFF;
    uint32_t* Kl = su + KL_OFF;
    uint32_t* Vh = su + VH_OFF;
    uint32_t* Vl = su + VL_OFF;
    uint32_t* Ph = su + PH_OFF;
    uint32_t* Pl = su + PL_OFF;

    const int tid  = threadIdx.x;
    const int lane = tid & 31;
    const int w    = tid >> 5;
    const int g    = lane >> 2;
    const int t    = lane & 3;

    const int bh = blockIdx.y;
    const int ib = (int)gridDim.x - 1 - (int)blockIdx.x;
    const int i0 = ib * 128;

    const uint32_t* Qh_g = g_Qh + (size_t)bh * T_SEQ * (HD / 2);
    const uint32_t* Ql_g = g_Ql + (size_t)bh * T_SEQ * (HD / 2);
    const uint32_t* Kh_g = g_Kh + (size_t)bh * T_SEQ * (HD / 2);
    const uint32_t* Kl_g = g_Kl + (size_t)bh * T_SEQ * (HD / 2);
    const uint32_t* Vph_g = g_Vph + (size_t)bh * (T_SEQ / 2) * HD;
    const uint32_t* Vpl_g = g_Vpl + (size_t)bh * (T_SEQ / 2) * HD;

#pragma unroll
    for (int rep = 0; rep < 4; rep++) {
        int idx = tid + rep * 256;
        int r = idx >> 3;
        int c = (idx & 7) * 4;
        cp16(Qh + r * 36 + c, Qh_g + (size_t)(i0 + r) * 32 + c);
        cp16(Ql + r * 36 + c, Ql_g + (size_t)(i0 + r) * 32 + c);
    }
    cp_commit();

    const int i_r0 = i0 + w * 16 + g;
    const int i_r1 = i_r0 + 8;
    const int warp_hi = i0 + w * 16 + 15;

    // p = exp2(qk*C1 + (j-i)*C2 - C3) = exp(qk/8 - (i-j) - 4)
    const float C1 = 0.18033688011f;   // 0.125 * log2(e)
    const float C2 = 1.44269504089f;   // log2(e)
    const float C3 = 5.77078016356f;   // 4 * log2(e)

    float l0r = 0.f, l1r = 0.f;
    float o[8][4];
#pragma unroll
    for (int nt = 0; nt < 8; nt++)
#pragma unroll
        for (int q = 0; q < 4; q++) o[nt][q] = 0.f;

    const int nTiles = (i0 + 128) / 64;
    const int rw0 = w * 16 + g;
    const int rw1 = rw0 + 8;

    for (int jt = 0; jt < nTiles; jt++) {
        const int j0 = jt * 64;
        __syncthreads();

        // K tiles (64 rows x 8 chunks x 2 planes)
#pragma unroll
        for (int rep = 0; rep < 2; rep++) {
            int idx = tid + rep * 256;
            int r = idx >> 3;
            int c = (idx & 7) * 4;
            cp16(Kh + r * 36 + c, Kh_g + (size_t)(j0 + r) * 32 + c);
            cp16(Kl + r * 36 + c, Kl_g + (size_t)(j0 + r) * 32 + c);
        }
        // V tiles: packed pair-of-rows, direct cp.async (32 rows x 16 chunks x 2)
#pragma unroll
        for (int rep = 0; rep < 2; rep++) {
            int idx = tid + rep * 256;     // 0..511
            int p = idx >> 4;              // pair row 0..31
            int c = (idx & 15) * 4;        // col 0,4,..,60
            cp16(Vh + p * 72 + c, Vph_g + ((size_t)(j0 >> 1) + p) * HD + c);
            cp16(Vl + p * 72 + c, Vpl_g + ((size_t)(j0 >> 1) + p) * HD + c);
        }
        cp_commit();
        cp_wait<0>();
        __syncthreads();

        if (j0 > warp_hi) continue;

        // ---- S = Q @ K^T ----
        float s[8][4];
#pragma unroll
        for (int nt = 0; nt < 8; nt++)
#pragma unroll
            for (int q = 0; q < 4; q++) s[nt][q] = 0.f;

#pragma unroll
        for (int ks = 0; ks < 4; ks++) {
            const int kp = ks * 8 + t;
            uint32_t a0h = Qh[rw0 * 36 + kp],     a0l = Ql[rw0 * 36 + kp];
            uint32_t a1h = Qh[rw1 * 36 + kp],     a1l = Ql[rw1 * 36 + kp];
            uint32_t a2h = Qh[rw0 * 36 + kp + 4], a2l = Ql[rw0 * 36 + kp + 4];
            uint32_t a3h = Qh[rw1 * 36 + kp + 4], a3l = Ql[rw1 * 36 + kp + 4];
#pragma unroll
            for (int nt = 0; nt < 8; nt++) {
                int rn = nt * 8 + g;
                uint32_t b0h = Kh[rn * 36 + kp],     b0l = Kl[rn * 36 + kp];
                uint32_t b1h = Kh[rn * 36 + kp + 4], b1l = Kl[rn * 36 + kp + 4];
                mma16(s[nt], a0h, a1h, a2h, a3h, b0h, b1h);
                mma16(s[nt], a0h, a1h, a2h, a3h, b0l, b1l);
                mma16(s[nt], a0l, a1l, a2l, a3l, b0h, b1h);
            }
        }

        // ---- mask + decay + exp (fixed max) ----
#pragma unroll
        for (int nt = 0; nt < 8; nt++) {
            int jb = j0 + nt * 8 + 2 * t;
            float d0 = fmaf((float)(jb - i_r0), C2, -C3);
            float d1 = fmaf((float)(jb - i_r1), C2, -C3);
            float p0 = (jb     <= i_r0) ? exp2f(fmaf(s[nt][0], C1, d0))      : 0.f;
            float p1 = (jb + 1 <= i_r0) ? exp2f(fmaf(s[nt][1], C1, d0 + C2)) : 0.f;
            float p2 = (jb     <= i_r1) ? exp2f(fmaf(s[nt][2], C1, d1))      : 0.f;
            float p3 = (jb + 1 <= i_r1) ? exp2f(fmaf(s[nt][3], C1, d1 + C2)) : 0.f;
            l0r += p0 + p1;
            l1r += p2 + p3;
            uint32_t hh, ll;
            split2(p0, p1, hh, ll);
            Ph[rw0 * 36 + nt * 4 + t] = hh;
            Pl[rw0 * 36 + nt * 4 + t] = ll;
            split2(p2, p3, hh, ll);
            Ph[rw1 * 36 + nt * 4 + t] = hh;
            Pl[rw1 * 36 + nt * 4 + t] = ll;
        }

        __syncwarp();

        // ---- O += P @ V ----
#pragma unroll
        for (int ks = 0; ks < 4; ks++) {
            const int kp = ks * 8 + t;
            uint32_t a0h = Ph[rw0 * 36 + kp],     a0l = Pl[rw0 * 36 + kp];
            uint32_t a1h = Ph[rw1 * 36 + kp],     a1l = Pl[rw1 * 36 + kp];
            uint32_t a2h = Ph[rw0 * 36 + kp + 4], a2l = Pl[rw0 * 36 + kp + 4];
            uint32_t a3h = Ph[rw1 * 36 + kp + 4], a3l = Pl[rw1 * 36 + kp + 4];
#pragma unroll
            for (int nt = 0; nt < 8; nt++) {
                int n = nt * 8 + g;
                uint32_t b0h = Vh[kp * 72 + n],       b0l = Vl[kp * 72 + n];
                uint32_t b1h = Vh[(kp + 4) * 72 + n], b1l = Vl[(kp + 4) * 72 + n];
                mma16(o[nt], a0h, a1h, a2h, a3h, b0h, b1h);
                mma16(o[nt], a0h, a1h, a2h, a3h, b0l, b1l);
                mma16(o[nt], a0l, a1l, a2l, a3l, b0h, b1h);
            }
        }
        __syncwarp();
    }

    // ---- final row-sum reduce + normalize + split + store packed ----
    l0r += __shfl_xor_sync(0xffffffffu, l0r, 1);
    l0r += __shfl_xor_sync(0xffffffffu, l0r, 2);
    l1r += __shfl_xor_sync(0xffffffffu, l1r, 1);
    l1r += __shfl_xor_sync(0xffffffffu, l1r, 2);

    const int b = bh >> 4;
    const int hh_ = bh & 15;
    const float inv0 = 1.0f / l0r;
    const float inv1 = 1.0f / l1r;
    size_t pb0 = ((size_t)b * T_SEQ + i_r0) * KPAIRS + hh_ * 32;
    size_t pb1 = ((size_t)b * T_SEQ + i_r1) * KPAIRS + hh_ * 32;
#pragma unroll
    for (int nt = 0; nt < 8; nt++) {
        int p = nt * 4 + t;
        uint32_t uh, ul;
        split2(o[nt][0] * inv0, o[nt][1] * inv0, uh, ul);
        g_atth[pb0 + p] = uh;
        g_attl[pb0 + p] = ul;
        split2(o[nt][2] * inv1, o[nt][3] * inv1, uh, ul);
        g_atth[pb1 + p] = uh;
        g_attl[pb1 + p] = ul;
    }
}

// ---------------------------------------------------------------------------
// Launch
// ---------------------------------------------------------------------------
extern "C" void kernel_launch(void* const* d_in, const int* in_sizes, int n_in,
                              void* d_out, int out_size)
{
    const float* x  = (const float*)d_in[0];
    const float* Wq = (const float*)d_in[1];
    const float* bq = (const float*)d_in[2];
    const float* Wk = (const float*)d_in[3];
    const float* bk = (const float*)d_in[4];
    const float* Wv = (const float*)d_in[5];
    const float* bv = (const float*)d_in[6];
    const float* Wo = (const float*)d_in[7];
    const float* bo = (const float*)d_in[8];
    float* out = (float*)d_out;

    cudaFuncSetAttribute(qkv_kernel,
                         cudaFuncAttributeMaxDynamicSharedMemorySize, GEMM_SMEM_BYTES);
    cudaFuncSetAttribute(out_kernel,
                         cudaFuncAttributeMaxDynamicSharedMemorySize, GEMM_SMEM_BYTES);
    cudaFuncSetAttribute(attn_kernel,
                         cudaFuncAttributeMaxDynamicSharedMemorySize, ATT_SMEM_BYTES);

    // pre-split X and all weights to bf16 hi/lo planes
    dim3 gp(2048, 8);
    prep_kernel<<<gp, 256>>>(x, Wq, Wk, Wv, Wo);

    // QKV projections: persistent (296 CTAs = 148 SM x 2), 768 tiles
    qkv_kernel<<<296, 256, GEMM_SMEM_BYTES>>>(bq, bk, bv);

    // attention
    dim3 ga(T_SEQ / 128, BATCH * N_HEADS);
    attn_kernel<<<ga, 256, ATT_SMEM_BYTES>>>();

    // output projection
    dim3 go(D_MODEL / 128, M_ROWS / 128);
    out_kernel<<<go, 256, GEMM_SMEM_BYTES>>>(bo, out);
}

// round 12
// speedup vs baseline: 1.0158x; 1.0158x over previous
#include <cuda_runtime.h>
#include <cuda_bf16.h>
#include <cstdint>

#define D_MODEL 1024
#define N_HEADS 16
#define HD      64
#define T_SEQ   2048
#define BATCH   2
#define M_ROWS  (BATCH * T_SEQ)   // 4096
#define KPAIRS  (D_MODEL / 2)     // 512 pairs per row

// ---------------------------------------------------------------------------
// Scratch (device globals; no allocation allowed)
// ---------------------------------------------------------------------------
__device__ uint32_t g_Xh[M_ROWS * KPAIRS];          // X pre-split hi plane
__device__ uint32_t g_Xl[M_ROWS * KPAIRS];
__device__ uint32_t g_Wh[4 * D_MODEL * KPAIRS];     // Wq,Wk,Wv,Wo hi planes
__device__ uint32_t g_Wl[4 * D_MODEL * KPAIRS];
__device__ uint32_t g_Qh[BATCH * N_HEADS * T_SEQ * (HD / 2)];  // [b,h,t,dpair]
__device__ uint32_t g_Ql[BATCH * N_HEADS * T_SEQ * (HD / 2)];
__device__ uint32_t g_Kh[BATCH * N_HEADS * T_SEQ * (HD / 2)];
__device__ uint32_t g_Kl[BATCH * N_HEADS * T_SEQ * (HD / 2)];
// V packed pair-of-rows: [b,h,tpair,d] u32 = bf16x2(row 2p, row 2p+1) at col d
__device__ uint32_t g_Vph[BATCH * N_HEADS * (T_SEQ / 2) * HD];
__device__ uint32_t g_Vpl[BATCH * N_HEADS * (T_SEQ / 2) * HD];
__device__ uint32_t g_atth[M_ROWS * KPAIRS];        // attention output packed
__device__ uint32_t g_attl[M_ROWS * KPAIRS];

// ---------------------------------------------------------------------------
// helpers
// ---------------------------------------------------------------------------
__device__ __forceinline__ void split2(float x0, float x1, uint32_t& h, uint32_t& l)
{
    __nv_bfloat162 hh = __floats2bfloat162_rn(x0, x1);
    float2 hf = __bfloat1622float2(hh);
    __nv_bfloat162 ll = __floats2bfloat162_rn(x0 - hf.x, x1 - hf.y);
    h = *reinterpret_cast<uint32_t*>(&hh);
    l = *reinterpret_cast<uint32_t*>(&ll);
}

__device__ __forceinline__ void mma16(float* c,
                                      uint32_t a0, uint32_t a1, uint32_t a2, uint32_t a3,
                                      uint32_t b0, uint32_t b1)
{
    asm volatile(
        "mma.sync.aligned.m16n8k16.row.col.f32.bf16.bf16.f32 "
        "{%0,%1,%2,%3}, {%4,%5,%6,%7}, {%8,%9}, {%0,%1,%2,%3};"
        : "+f"(c[0]), "+f"(c[1]), "+f"(c[2]), "+f"(c[3])
        : "r"(a0), "r"(a1), "r"(a2), "r"(a3), "r"(b0), "r"(b1));
}

__device__ __forceinline__ void ldsm4(uint32_t& r0, uint32_t& r1,
                                      uint32_t& r2, uint32_t& r3, uint32_t addr)
{
    asm volatile("ldmatrix.sync.aligned.m8n8.x4.shared.b16 {%0,%1,%2,%3}, [%4];"
                 : "=r"(r0), "=r"(r1), "=r"(r2), "=r"(r3) : "r"(addr));
}

__device__ __forceinline__ void cp16(void* dst_smem, const void* src)
{
    uint32_t s = (uint32_t)__cvta_generic_to_shared(dst_smem);
    asm volatile("cp.async.cg.shared.global [%0], [%1], 16;\n" :: "r"(s), "l"(src));
}
__device__ __forceinline__ void cp_commit()
{
    asm volatile("cp.async.commit_group;\n" ::);
}
template<int N>
__device__ __forceinline__ void cp_wait()
{
    asm volatile("cp.async.wait_group %0;\n" :: "n"(N));
}

// ---------------------------------------------------------------------------
// Prep kernel: split X and Wq/Wk/Wv/Wo into bf16x2 hi/lo planes (once).
// ---------------------------------------------------------------------------
__global__ void __launch_bounds__(256)
prep_kernel(const float* __restrict__ X,
            const float* __restrict__ Wq, const float* __restrict__ Wk,
            const float* __restrict__ Wv, const float* __restrict__ Wo)
{
    const int seg = blockIdx.y;
    const int idx = blockIdx.x * 256 + threadIdx.x;
    const float* src;
    uint32_t *dh, *dl;
    if (seg < 4) {
        src = X + (size_t)seg * 1048576;
        dh = g_Xh + (size_t)seg * 524288;
        dl = g_Xl + (size_t)seg * 524288;
    } else {
        const float* ws[4] = {Wq, Wk, Wv, Wo};
        src = ws[seg - 4];
        dh = g_Wh + (size_t)(seg - 4) * 524288;
        dl = g_Wl + (size_t)(seg - 4) * 524288;
    }
    float2 v = *(const float2*)(src + 2 * (size_t)idx);
    uint32_t h, l;
    split2(v.x, v.y, h, l);
    dh[idx] = h;
    dl[idx] = l;
}

// ---------------------------------------------------------------------------
// 3xBF16 mma.sync GEMM tile: Y[128,128 @ (m0,n0)] = X @ W^T + bias
// XOR-swizzled smem (RSU=16, chunk' = chunk ^ ((row>>1)&3)); NBUF=3;
// one __syncthreads + one cp_wait per 96-MMA period, prefetch distance 2.
// Output modes: 0 = packed Q/K planes, 1 = V packed pair-of-rows planes,
//               2 = float row-major (final out).
// ---------------------------------------------------------------------------
#define RSU      16                  // u32 per plane row (no pad)
#define PLANE_U  (128 * RSU)         // 2048 u32 per plane
#define BUF_U    (4 * PLANE_U)       // Ah, Al, Bh, Bl = 32 KB
#define NBUF     3
#define NPER     (D_MODEL / 32)      // 32 periods
#define GEMM_SMEM_BYTES (NBUF * BUF_U * 4)   // 98304

__device__ __forceinline__ uint32_t sw_off(int row, int chunk)
{
    return (uint32_t)(row * RSU + ((chunk ^ ((row >> 1) & 3)) << 2));
}

__device__ __forceinline__ void gemm_tile(int m0, int n0,
                                          const uint32_t* __restrict__ Xh,
                                          const uint32_t* __restrict__ Xl,
                                          const uint32_t* __restrict__ Wh,
                                          const uint32_t* __restrict__ Wl,
                                          const float* __restrict__ bias,
                                          uint32_t* __restrict__ Yh,
                                          uint32_t* __restrict__ Yl,
                                          float* __restrict__ Yf,
                                          int mode)
{
    extern __shared__ uint32_t smem[];
    const uint32_t sbase = (uint32_t)__cvta_generic_to_shared(smem);

    const int tid  = threadIdx.x;
    const int lane = tid & 31;
    const int wid  = tid >> 5;
    const int wm   = wid >> 2;
    const int wn   = wid & 3;
    const int g    = lane >> 2;
    const int t    = lane & 3;

    const int lrow = tid >> 2;
    const int lcix = tid & 3;
    const uint32_t ldst0 = sw_off(lrow,      lcix);
    const uint32_t ldst1 = sw_off(lrow + 64, lcix);

    const uint32_t* srcs[4] = {
        Xh + (size_t)m0 * KPAIRS, Xl + (size_t)m0 * KPAIRS,
        Wh + (size_t)n0 * KPAIRS, Wl + (size_t)n0 * KPAIRS };

    const int a_row = (lane & 7) + ((lane >> 3) & 1) * 8;
    const int hiA   = lane >> 4;
    int baseA[4], swA[4];
#pragma unroll
    for (int mt = 0; mt < 4; mt++) {
        int rg = wm * 64 + mt * 16 + a_row;
        baseA[mt] = rg * RSU;
        swA[mt]   = (rg >> 1) & 3;
    }
    const int b_row = (lane & 7) + ((lane >> 4) ? 8 : 0);
    const int hiB   = (lane >> 3) & 1;
    const int rgB0  = wn * 32 + b_row;
    const int rgB1  = rgB0 + 16;
    const int baseB0 = rgB0 * RSU, swB0 = (rgB0 >> 1) & 3;
    const int baseB1 = rgB1 * RSU, swB1 = (rgB1 >> 1) & 3;

    float acc[4][4][4];
#pragma unroll
    for (int i = 0; i < 4; i++)
#pragma unroll
        for (int j = 0; j < 4; j++)
#pragma unroll
            for (int q = 0; q < 4; q++) acc[i][j][q] = 0.f;

    auto load_buf = [&](int b, int p) {
        uint32_t* base = smem + b * BUF_U;
        const int koff = p * 16;
#pragma unroll
        for (int pi = 0; pi < 4; pi++) {
            const uint32_t* sp = srcs[pi] + koff + lcix * 4;
            uint32_t* dp = base + pi * PLANE_U;
            cp16(dp + ldst0, sp + (size_t)lrow * KPAIRS);
            cp16(dp + ldst1, sp + (size_t)(lrow + 64) * KPAIRS);
        }
        cp_commit();
    };

    // prologue
    load_buf(0, 0);
    load_buf(1, 1);

    for (int p = 0; p < NPER; p++) {
        cp_wait<1>();
        __syncthreads();
        if (p + 2 < NPER) load_buf((p + 2) % 3, p + 2);
        else              cp_commit();

        const uint32_t stb = sbase + (uint32_t)((p % 3) * BUF_U) * 4;

#pragma unroll
        for (int ks = 0; ks < 2; ks++) {
            uint32_t Ah[4][4], Al[4][4];
#pragma unroll
            for (int mt = 0; mt < 4; mt++) {
                uint32_t offA = (uint32_t)(baseA[mt] +
                                (((2 * ks + hiA) ^ swA[mt]) << 2)) * 4;
                ldsm4(Ah[mt][0], Ah[mt][1], Ah[mt][2], Ah[mt][3], stb + offA);
                ldsm4(Al[mt][0], Al[mt][1], Al[mt][2], Al[mt][3],
                      stb + PLANE_U * 4 + offA);
            }
            uint32_t offB0 = (uint32_t)(baseB0 + (((2 * ks + hiB) ^ swB0) << 2)) * 4;
            uint32_t offB1 = (uint32_t)(baseB1 + (((2 * ks + hiB) ^ swB1) << 2)) * 4;
            uint32_t Bh[4][2], Bl[4][2];
            ldsm4(Bh[0][0], Bh[0][1], Bh[1][0], Bh[1][1],
                  stb + 2 * PLANE_U * 4 + offB0);
            ldsm4(Bh[2][0], Bh[2][1], Bh[3][0], Bh[3][1],
                  stb + 2 * PLANE_U * 4 + offB1);
            ldsm4(Bl[0][0], Bl[0][1], Bl[1][0], Bl[1][1],
                  stb + 3 * PLANE_U * 4 + offB0);
            ldsm4(Bl[2][0], Bl[2][1], Bl[3][0], Bl[3][1],
                  stb + 3 * PLANE_U * 4 + offB1);

#pragma unroll
            for (int mt = 0; mt < 4; mt++)
#pragma unroll
                for (int nt = 0; nt < 4; nt++)
                    mma16(acc[mt][nt], Ah[mt][0], Ah[mt][1], Ah[mt][2], Ah[mt][3],
                          Bh[nt][0], Bh[nt][1]);
#pragma unroll
            for (int mt = 0; mt < 4; mt++)
#pragma unroll
                for (int nt = 0; nt < 4; nt++)
                    mma16(acc[mt][nt], Ah[mt][0], Ah[mt][1], Ah[mt][2], Ah[mt][3],
                          Bl[nt][0], Bl[nt][1]);
#pragma unroll
            for (int mt = 0; mt < 4; mt++)
#pragma unroll
                for (int nt = 0; nt < 4; nt++)
                    mma16(acc[mt][nt], Al[mt][0], Al[mt][1], Al[mt][2], Al[mt][3],
                          Bh[nt][0], Bh[nt][1]);
        }
    }

    // epilogue
#pragma unroll
    for (int mt = 0; mt < 4; mt++) {
        int rm = m0 + wm * 64 + mt * 16 + g;
#pragma unroll
        for (int nt = 0; nt < 4; nt++) {
            int cn = n0 + wn * 32 + nt * 8 + 2 * t;
            float bb0 = bias[cn];
            float bb1 = bias[cn + 1];
            float2 v0 = make_float2(acc[mt][nt][0] + bb0, acc[mt][nt][1] + bb1);
            float2 v1 = make_float2(acc[mt][nt][2] + bb0, acc[mt][nt][3] + bb1);
            if (mode == 0) {
                int head = cn >> 6;
                int pr   = (cn & 63) >> 1;
#pragma unroll
                for (int rr = 0; rr < 2; rr++) {
                    int row = rm + rr * 8;
                    float2 v = rr ? v1 : v0;
                    int bb = row >> 11;
                    int tt = row & (T_SEQ - 1);
                    size_t base = (((size_t)bb * N_HEADS + head) * T_SEQ + tt) * (HD / 2) + pr;
                    uint32_t hh, ll;
                    split2(v.x, v.y, hh, ll);
                    Yh[base] = hh;
                    Yl[base] = ll;
                }
            } else if (mode == 1) {
                // V: pair adjacent rows via shuffle, store packed
                // pair-of-rows planes [b,h,tpair,d]
                int head = cn >> 6;
                int d    = cn & 63;
                float p0x = __shfl_down_sync(0xffffffffu, v0.x, 4);
                float p0y = __shfl_down_sync(0xffffffffu, v0.y, 4);
                float p1x = __shfl_down_sync(0xffffffffu, v1.x, 4);
                float p1y = __shfl_down_sync(0xffffffffu, v1.y, 4);
                if ((g & 1) == 0) {
                    int bb = rm >> 11;
                    int tt = rm & (T_SEQ - 1);
                    size_t idx0 = (((size_t)bb * N_HEADS + head) * (T_SEQ / 2)
                                   + (tt >> 1)) * HD + d;
                    size_t idx1 = idx0 + 4 * HD;   // rows rm+8, rm+9
                    uint32_t hh, ll;
                    split2(v0.x, p0x, hh, ll); Yh[idx0] = hh;     Yl[idx0] = ll;
                    split2(v0.y, p0y, hh, ll); Yh[idx0 + 1] = hh; Yl[idx0 + 1] = ll;
                    split2(v1.x, p1x, hh, ll); Yh[idx1] = hh;     Yl[idx1] = ll;
                    split2(v1.y, p1y, hh, ll); Yh[idx1 + 1] = hh; Yl[idx1 + 1] = ll;
                }
            } else {
                *(float2*)(Yf + (size_t)rm * D_MODEL + cn) = v0;
                *(float2*)(Yf + (size_t)(rm + 8) * D_MODEL + cn) = v1;
            }
        }
    }
}

// grid-launched qkv (proven faster than persistent): z = {Q,K,V}
__global__ void __launch_bounds__(256, 2)
qkv_kernel(const float* __restrict__ bq, const float* __restrict__ bk,
           const float* __restrict__ bv)
{
    const int z  = blockIdx.z;
    const int m0 = blockIdx.y * 128;
    const int n0 = blockIdx.x * 128;
    const float* bias = (z == 0) ? bq : (z == 1) ? bk : bv;
    const uint32_t* Wh = g_Wh + (size_t)z * D_MODEL * KPAIRS;
    const uint32_t* Wl = g_Wl + (size_t)z * D_MODEL * KPAIRS;
    if (z == 0)
        gemm_tile(m0, n0, g_Xh, g_Xl, Wh, Wl, bias, g_Qh, g_Ql, nullptr, 0);
    else if (z == 1)
        gemm_tile(m0, n0, g_Xh, g_Xl, Wh, Wl, bias, g_Kh, g_Kl, nullptr, 0);
    else
        gemm_tile(m0, n0, g_Xh, g_Xl, Wh, Wl, bias, g_Vph, g_Vpl, nullptr, 1);
}

__global__ void __launch_bounds__(256, 2)
out_kernel(const float* __restrict__ bo, float* __restrict__ out)
{
    gemm_tile(blockIdx.y * 128, blockIdx.x * 128,
              g_atth, g_attl,
              g_Wh + (size_t)3 * D_MODEL * KPAIRS,
              g_Wl + (size_t)3 * D_MODEL * KPAIRS,
              bo, nullptr, nullptr, out, 2);
}

// ---------------------------------------------------------------------------
// Tensor-core flash attention, 3xBF16 mma.sync, FIXED-MAX softmax.
// Q/K/V all pre-split packed; entire tile load is cp.async. No split ALU
// in the loop except P.
// ---------------------------------------------------------------------------
#define QH_OFF 0
#define QL_OFF 4608
#define KH_OFF 9216
#define KL_OFF 11520
#define VH_OFF 13824
#define VL_OFF 16128
#define PH_OFF 18432
#define PL_OFF 23040
#define ATT_U32 27648
#define ATT_SMEM_BYTES (ATT_U32 * 4)   // 110592

__global__ void __launch_bounds__(256, 2) attn_kernel()
{
    extern __shared__ uint32_t su[];
    uint32_t* Qh = su + QH_OFF;
    uint32_t* Ql = su + QL_OFF;
    uint32_t* Kh = su + KH_OFF;
    uint32_t* Kl = su + KL_OFF;
    uint32_t* Vh = su + VH_OFF;
    uint32_t* Vl = su + VL_OFF;
    uint32_t* Ph = su + PH_OFF;
    uint32_t* Pl = su + PL_OFF;

    const int tid  = threadIdx.x;
    const int lane = tid & 31;
    const int w    = tid >> 5;
    const int g    = lane >> 2;
    const int t    = lane & 3;

    const int bh = blockIdx.y;
    const int ib = (int)gridDim.x - 1 - (int)blockIdx.x;
    const int i0 = ib * 128;

    const uint32_t* Qh_g = g_Qh + (size_t)bh * T_SEQ * (HD / 2);
    const uint32_t* Ql_g = g_Ql + (size_t)bh * T_SEQ * (HD / 2);
    const uint32_t* Kh_g = g_Kh + (size_t)bh * T_SEQ * (HD / 2);
    const uint32_t* Kl_g = g_Kl + (size_t)bh * T_SEQ * (HD / 2);
    const uint32_t* Vph_g = g_Vph + (size_t)bh * (T_SEQ / 2) * HD;
    const uint32_t* Vpl_g = g_Vpl + (size_t)bh * (T_SEQ / 2) * HD;

#pragma unroll
    for (int rep = 0; rep < 4; rep++) {
        int idx = tid + rep * 256;
        int r = idx >> 3;
        int c = (idx & 7) * 4;
        cp16(Qh + r * 36 + c, Qh_g + (size_t)(i0 + r) * 32 + c);
        cp16(Ql + r * 36 + c, Ql_g + (size_t)(i0 + r) * 32 + c);
    }
    cp_commit();

    const int i_r0 = i0 + w * 16 + g;
    const int i_r1 = i_r0 + 8;
    const int warp_hi = i0 + w * 16 + 15;

    // p = exp2(qk*C1 + (j-i)*C2 - C3) = exp(qk/8 - (i-j) - 4)
    const float C1 = 0.18033688011f;   // 0.125 * log2(e)
    const float C2 = 1.44269504089f;   // log2(e)
    const float C3 = 5.77078016356f;   // 4 * log2(e)

    float l0r = 0.f, l1r = 0.f;
    float o[8][4];
#pragma unroll
    for (int nt = 0; nt < 8; nt++)
#pragma unroll
        for (int q = 0; q < 4; q++) o[nt][q] = 0.f;

    const int nTiles = (i0 + 128) / 64;
    const int rw0 = w * 16 + g;
    const int rw1 = rw0 + 8;

    for (int jt = 0; jt < nTiles; jt++) {
        const int j0 = jt * 64;
        __syncthreads();

        // K tiles (64 rows x 8 chunks x 2 planes)
#pragma unroll
        for (int rep = 0; rep < 2; rep++) {
            int idx = tid + rep * 256;
            int r = idx >> 3;
            int c = (idx & 7) * 4;
            cp16(Kh + r * 36 + c, Kh_g + (size_t)(j0 + r) * 32 + c);
            cp16(Kl + r * 36 + c, Kl_g + (size_t)(j0 + r) * 32 + c);
        }
        // V tiles: packed pair-of-rows, direct cp.async (32 rows x 16 chunks x 2)
#pragma unroll
        for (int rep = 0; rep < 2; rep++) {
            int idx = tid + rep * 256;     // 0..511
            int p = idx >> 4;              // pair row 0..31
            int c = (idx & 15) * 4;        // col 0,4,..,60
            cp16(Vh + p * 72 + c, Vph_g + ((size_t)(j0 >> 1) + p) * HD + c);
            cp16(Vl + p * 72 + c, Vpl_g + ((size_t)(j0 >> 1) + p) * HD + c);
        }
        cp_commit();
        cp_wait<0>();
        __syncthreads();

        if (j0 > warp_hi) continue;

        // ---- S = Q @ K^T ----
        float s[8][4];
#pragma unroll
        for (int nt = 0; nt < 8; nt++)
#pragma unroll
            for (int q = 0; q < 4; q++) s[nt][q] = 0.f;

#pragma unroll
        for (int ks = 0; ks < 4; ks++) {
            const int kp = ks * 8 + t;
            uint32_t a0h = Qh[rw0 * 36 + kp],     a0l = Ql[rw0 * 36 + kp];
            uint32_t a1h = Qh[rw1 * 36 + kp],     a1l = Ql[rw1 * 36 + kp];
            uint32_t a2h = Qh[rw0 * 36 + kp + 4], a2l = Ql[rw0 * 36 + kp + 4];
            uint32_t a3h = Qh[rw1 * 36 + kp + 4], a3l = Ql[rw1 * 36 + kp + 4];
#pragma unroll
            for (int nt = 0; nt < 8; nt++) {
                int rn = nt * 8 + g;
                uint32_t b0h = Kh[rn * 36 + kp],     b0l = Kl[rn * 36 + kp];
                uint32_t b1h = Kh[rn * 36 + kp + 4], b1l = Kl[rn * 36 + kp + 4];
                mma16(s[nt], a0h, a1h, a2h, a3h, b0h, b1h);
                mma16(s[nt], a0h, a1h, a2h, a3h, b0l, b1l);
                mma16(s[nt], a0l, a1l, a2l, a3l, b0h, b1h);
            }
        }

        // ---- mask + decay + exp (fixed max) ----
#pragma unroll
        for (int nt = 0; nt < 8; nt++) {
            int jb = j0 + nt * 8 + 2 * t;
            float d0 = fmaf((float)(jb - i_r0), C2, -C3);
            float d1 = fmaf((float)(jb - i_r1), C2, -C3);
            float p0 = (jb     <= i_r0) ? exp2f(fmaf(s[nt][0], C1, d0))      : 0.f;
            float p1 = (jb + 1 <= i_r0) ? exp2f(fmaf(s[nt][1], C1, d0 + C2)) : 0.f;
            float p2 = (jb     <= i_r1) ? exp2f(fmaf(s[nt][2], C1, d1))      : 0.f;
            float p3 = (jb + 1 <= i_r1) ? exp2f(fmaf(s[nt][3], C1, d1 + C2)) : 0.f;
            l0r += p0 + p1;
            l1r += p2 + p3;
            uint32_t hh, ll;
            split2(p0, p1, hh, ll);
            Ph[rw0 * 36 + nt * 4 + t] = hh;
            Pl[rw0 * 36 + nt * 4 + t] = ll;
            split2(p2, p3, hh, ll);
            Ph[rw1 * 36 + nt * 4 + t] = hh;
            Pl[rw1 * 36 + nt * 4 + t] = ll;
        }

        __syncwarp();

        // ---- O += P @ V ----
#pragma unroll
        for (int ks = 0; ks < 4; ks++) {
            const int kp = ks * 8 + t;
            uint32_t a0h = Ph[rw0 * 36 + kp],     a0l = Pl[rw0 * 36 + kp];
            uint32_t a1h = Ph[rw1 * 36 + kp],     a1l = Pl[rw1 * 36 + kp];
            uint32_t a2h = Ph[rw0 * 36 + kp + 4], a2l = Pl[rw0 * 36 + kp + 4];
            uint32_t a3h = Ph[rw1 * 36 + kp + 4], a3l = Pl[rw1 * 36 + kp + 4];
#pragma unroll
            for (int nt = 0; nt < 8; nt++) {
                int n = nt * 8 + g;
                uint32_t b0h = Vh[kp * 72 + n],       b0l = Vl[kp * 72 + n];
                uint32_t b1h = Vh[(kp + 4) * 72 + n], b1l = Vl[(kp + 4) * 72 + n];
                mma16(o[nt], a0h, a1h, a2h, a3h, b0h, b1h);
                mma16(o[nt], a0h, a1h, a2h, a3h, b0l, b1l);
                mma16(o[nt], a0l, a1l, a2l, a3l, b0h, b1h);
            }
        }
        __syncwarp();
    }

    // ---- final row-sum reduce + normalize + split + store packed ----
    l0r += __shfl_xor_sync(0xffffffffu, l0r, 1);
    l0r += __shfl_xor_sync(0xffffffffu, l0r, 2);
    l1r += __shfl_xor_sync(0xffffffffu, l1r, 1);
    l1r += __shfl_xor_sync(0xffffffffu, l1r, 2);

    const int b = bh >> 4;
    const int hh_ = bh & 15;
    const float inv0 = 1.0f / l0r;
    const float inv1 = 1.0f / l1r;
    size_t pb0 = ((size_t)b * T_SEQ + i_r0) * KPAIRS + hh_ * 32;
    size_t pb1 = ((size_t)b * T_SEQ + i_r1) * KPAIRS + hh_ * 32;
#pragma unroll
    for (int nt = 0; nt < 8; nt++) {
        int p = nt * 4 + t;
        uint32_t uh, ul;
        split2(o[nt][0] * inv0, o[nt][1] * inv0, uh, ul);
        g_atth[pb0 + p] = uh;
        g_attl[pb0 + p] = ul;
        split2(o[nt][2] * inv1, o[nt][3] * inv1, uh, ul);
        g_atth[pb1 + p] = uh;
        g_attl[pb1 + p] = ul;
    }
}

// ---------------------------------------------------------------------------
// Launch
// ---------------------------------------------------------------------------
extern "C" void kernel_launch(void* const* d_in, const int* in_sizes, int n_in,
                              void* d_out, int out_size)
{
    const float* x  = (const float*)d_in[0];
    const float* Wq = (const float*)d_in[1];
    const float* bq = (const float*)d_in[2];
    const float* Wk = (const float*)d_in[3];
    const float* bk = (const float*)d_in[4];
    const float* Wv = (const float*)d_in[5];
    const float* bv = (const float*)d_in[6];
    const float* Wo = (const float*)d_in[7];
    const float* bo = (const float*)d_in[8];
    float* out = (float*)d_out;

    cudaFuncSetAttribute(qkv_kernel,
                         cudaFuncAttributeMaxDynamicSharedMemorySize, GEMM_SMEM_BYTES);
    cudaFuncSetAttribute(out_kernel,
                         cudaFuncAttributeMaxDynamicSharedMemorySize, GEMM_SMEM_BYTES);
    cudaFuncSetAttribute(attn_kernel,
                         cudaFuncAttributeMaxDynamicSharedMemorySize, ATT_SMEM_BYTES);

    // pre-split X and all weights to bf16 hi/lo planes
    dim3 gp(2048, 8);
    prep_kernel<<<gp, 256>>>(x, Wq, Wk, Wv, Wo);

    // QKV projections (grid-launched, z = {Q,K,V})
    dim3 gq(D_MODEL / 128, M_ROWS / 128, 3);
    qkv_kernel<<<gq, 256, GEMM_SMEM_BYTES>>>(bq, bk, bv);

    // attention
    dim3 ga(T_SEQ / 128, BATCH * N_HEADS);
    attn_kernel<<<ga, 256, ATT_SMEM_BYTES>>>();

    // output projection
    dim3 go(D_MODEL / 128, M_ROWS / 128);
    out_kernel<<<go, 256, GEMM_SMEM_BYTES>>>(bo, out);
}

// round 13
// speedup vs baseline: 1.0483x; 1.0320x over previous
#include <cuda_runtime.h>
#include <cuda_bf16.h>
#include <cstdint>

#define D_MODEL 1024
#define N_HEADS 16
#define HD      64
#define T_SEQ   2048
#define BATCH   2
#define M_ROWS  (BATCH * T_SEQ)   // 4096
#define KPAIRS  (D_MODEL / 2)     // 512 pairs per row

// ---------------------------------------------------------------------------
// Scratch (device globals; no allocation allowed)
// ---------------------------------------------------------------------------
__device__ uint32_t g_Xh[M_ROWS * KPAIRS];          // X pre-split hi plane
__device__ uint32_t g_Xl[M_ROWS * KPAIRS];
__device__ uint32_t g_Wh[4 * D_MODEL * KPAIRS];     // Wq,Wk,Wv,Wo hi planes
__device__ uint32_t g_Wl[4 * D_MODEL * KPAIRS];
__device__ uint32_t g_Qh[BATCH * N_HEADS * T_SEQ * (HD / 2)];  // [b,h,t,dpair]
__device__ uint32_t g_Ql[BATCH * N_HEADS * T_SEQ * (HD / 2)];
__device__ uint32_t g_Kh[BATCH * N_HEADS * T_SEQ * (HD / 2)];
__device__ uint32_t g_Kl[BATCH * N_HEADS * T_SEQ * (HD / 2)];
// V packed pair-of-rows: [b,h,tpair,d] u32 = bf16x2(row 2p, row 2p+1) at col d
__device__ uint32_t g_Vph[BATCH * N_HEADS * (T_SEQ / 2) * HD];
__device__ uint32_t g_Vpl[BATCH * N_HEADS * (T_SEQ / 2) * HD];
__device__ uint32_t g_atth[M_ROWS * KPAIRS];        // attention output packed
__device__ uint32_t g_attl[M_ROWS * KPAIRS];

// ---------------------------------------------------------------------------
// helpers
// ---------------------------------------------------------------------------
__device__ __forceinline__ void split2(float x0, float x1, uint32_t& h, uint32_t& l)
{
    __nv_bfloat162 hh = __floats2bfloat162_rn(x0, x1);
    float2 hf = __bfloat1622float2(hh);
    __nv_bfloat162 ll = __floats2bfloat162_rn(x0 - hf.x, x1 - hf.y);
    h = *reinterpret_cast<uint32_t*>(&hh);
    l = *reinterpret_cast<uint32_t*>(&ll);
}

__device__ __forceinline__ void mma16(float* c,
                                      uint32_t a0, uint32_t a1, uint32_t a2, uint32_t a3,
                                      uint32_t b0, uint32_t b1)
{
    asm volatile(
        "mma.sync.aligned.m16n8k16.row.col.f32.bf16.bf16.f32 "
        "{%0,%1,%2,%3}, {%4,%5,%6,%7}, {%8,%9}, {%0,%1,%2,%3};"
        : "+f"(c[0]), "+f"(c[1]), "+f"(c[2]), "+f"(c[3])
        : "r"(a0), "r"(a1), "r"(a2), "r"(a3), "r"(b0), "r"(b1));
}

__device__ __forceinline__ void ldsm4(uint32_t& r0, uint32_t& r1,
                                      uint32_t& r2, uint32_t& r3, uint32_t addr)
{
    asm volatile("ldmatrix.sync.aligned.m8n8.x4.shared.b16 {%0,%1,%2,%3}, [%4];"
                 : "=r"(r0), "=r"(r1), "=r"(r2), "=r"(r3) : "r"(addr));
}

__device__ __forceinline__ void cp16(void* dst_smem, const void* src)
{
    uint32_t s = (uint32_t)__cvta_generic_to_shared(dst_smem);
    asm volatile("cp.async.cg.shared.global [%0], [%1], 16;\n" :: "r"(s), "l"(src));
}
__device__ __forceinline__ void cp_commit()
{
    asm volatile("cp.async.commit_group;\n" ::);
}
template<int N>
__device__ __forceinline__ void cp_wait()
{
    asm volatile("cp.async.wait_group %0;\n" :: "n"(N));
}

// ---------------------------------------------------------------------------
// Prep kernel: split X and Wq/Wk/Wv/Wo into bf16x2 hi/lo planes (once).
// ---------------------------------------------------------------------------
__global__ void __launch_bounds__(256)
prep_kernel(const float* __restrict__ X,
            const float* __restrict__ Wq, const float* __restrict__ Wk,
            const float* __restrict__ Wv, const float* __restrict__ Wo)
{
    const int seg = blockIdx.y;
    const int idx = blockIdx.x * 256 + threadIdx.x;
    const float* src;
    uint32_t *dh, *dl;
    if (seg < 4) {
        src = X + (size_t)seg * 1048576;
        dh = g_Xh + (size_t)seg * 524288;
        dl = g_Xl + (size_t)seg * 524288;
    } else {
        const float* ws[4] = {Wq, Wk, Wv, Wo};
        src = ws[seg - 4];
        dh = g_Wh + (size_t)(seg - 4) * 524288;
        dl = g_Wl + (size_t)(seg - 4) * 524288;
    }
    float2 v = *(const float2*)(src + 2 * (size_t)idx);
    uint32_t h, l;
    split2(v.x, v.y, h, l);
    dh[idx] = h;
    dl[idx] = l;
}

// ---------------------------------------------------------------------------
// 3xBF16 mma.sync GEMM tile: Y[128,128 @ (m0,n0)] = X @ W^T + bias
// XOR-swizzled smem (RSU=16, chunk' = chunk ^ ((row>>1)&3)); NBUF=3;
// one __syncthreads + one cp_wait per 96-MMA period, prefetch distance 2.
// Output modes: 0 = packed Q/K planes, 1 = V packed pair-of-rows planes,
//               2 = float row-major (final out).
// ---------------------------------------------------------------------------
#define RSU      16                  // u32 per plane row (no pad)
#define PLANE_U  (128 * RSU)         // 2048 u32 per plane
#define BUF_U    (4 * PLANE_U)       // Ah, Al, Bh, Bl = 32 KB
#define NBUF     3
#define NPER     (D_MODEL / 32)      // 32 periods
#define GEMM_SMEM_BYTES (NBUF * BUF_U * 4)   // 98304

__device__ __forceinline__ uint32_t sw_off(int row, int chunk)
{
    return (uint32_t)(row * RSU + ((chunk ^ ((row >> 1) & 3)) << 2));
}

__device__ __forceinline__ void gemm_tile(int m0, int n0,
                                          const uint32_t* __restrict__ Xh,
                                          const uint32_t* __restrict__ Xl,
                                          const uint32_t* __restrict__ Wh,
                                          const uint32_t* __restrict__ Wl,
                                          const float* __restrict__ bias,
                                          uint32_t* __restrict__ Yh,
                                          uint32_t* __restrict__ Yl,
                                          float* __restrict__ Yf,
                                          int mode)
{
    extern __shared__ uint32_t smem[];
    const uint32_t sbase = (uint32_t)__cvta_generic_to_shared(smem);

    const int tid  = threadIdx.x;
    const int lane = tid & 31;
    const int wid  = tid >> 5;
    const int wm   = wid >> 2;
    const int wn   = wid & 3;
    const int g    = lane >> 2;
    const int t    = lane & 3;

    const int lrow = tid >> 2;
    const int lcix = tid & 3;
    const uint32_t ldst0 = sw_off(lrow,      lcix);
    const uint32_t ldst1 = sw_off(lrow + 64, lcix);

    const uint32_t* srcs[4] = {
        Xh + (size_t)m0 * KPAIRS, Xl + (size_t)m0 * KPAIRS,
        Wh + (size_t)n0 * KPAIRS, Wl + (size_t)n0 * KPAIRS };

    const int a_row = (lane & 7) + ((lane >> 3) & 1) * 8;
    const int hiA   = lane >> 4;
    int baseA[4], swA[4];
#pragma unroll
    for (int mt = 0; mt < 4; mt++) {
        int rg = wm * 64 + mt * 16 + a_row;
        baseA[mt] = rg * RSU;
        swA[mt]   = (rg >> 1) & 3;
    }
    const int b_row = (lane & 7) + ((lane >> 4) ? 8 : 0);
    const int hiB   = (lane >> 3) & 1;
    const int rgB0  = wn * 32 + b_row;
    const int rgB1  = rgB0 + 16;
    const int baseB0 = rgB0 * RSU, swB0 = (rgB0 >> 1) & 3;
    const int baseB1 = rgB1 * RSU, swB1 = (rgB1 >> 1) & 3;

    float acc[4][4][4];
#pragma unroll
    for (int i = 0; i < 4; i++)
#pragma unroll
        for (int j = 0; j < 4; j++)
#pragma unroll
            for (int q = 0; q < 4; q++) acc[i][j][q] = 0.f;

    auto load_buf = [&](int b, int p) {
        uint32_t* base = smem + b * BUF_U;
        const int koff = p * 16;
#pragma unroll
        for (int pi = 0; pi < 4; pi++) {
            const uint32_t* sp = srcs[pi] + koff + lcix * 4;
            uint32_t* dp = base + pi * PLANE_U;
            cp16(dp + ldst0, sp + (size_t)lrow * KPAIRS);
            cp16(dp + ldst1, sp + (size_t)(lrow + 64) * KPAIRS);
        }
        cp_commit();
    };

    // prologue
    load_buf(0, 0);
    load_buf(1, 1);

    for (int p = 0; p < NPER; p++) {
        cp_wait<1>();
        __syncthreads();
        if (p + 2 < NPER) load_buf((p + 2) % 3, p + 2);
        else              cp_commit();

        const uint32_t stb = sbase + (uint32_t)((p % 3) * BUF_U) * 4;

#pragma unroll
        for (int ks = 0; ks < 2; ks++) {
            uint32_t Ah[4][4], Al[4][4];
#pragma unroll
            for (int mt = 0; mt < 4; mt++) {
                uint32_t offA = (uint32_t)(baseA[mt] +
                                (((2 * ks + hiA) ^ swA[mt]) << 2)) * 4;
                ldsm4(Ah[mt][0], Ah[mt][1], Ah[mt][2], Ah[mt][3], stb + offA);
                ldsm4(Al[mt][0], Al[mt][1], Al[mt][2], Al[mt][3],
                      stb + PLANE_U * 4 + offA);
            }
            uint32_t offB0 = (uint32_t)(baseB0 + (((2 * ks + hiB) ^ swB0) << 2)) * 4;
            uint32_t offB1 = (uint32_t)(baseB1 + (((2 * ks + hiB) ^ swB1) << 2)) * 4;
            uint32_t Bh[4][2], Bl[4][2];
            ldsm4(Bh[0][0], Bh[0][1], Bh[1][0], Bh[1][1],
                  stb + 2 * PLANE_U * 4 + offB0);
            ldsm4(Bh[2][0], Bh[2][1], Bh[3][0], Bh[3][1],
                  stb + 2 * PLANE_U * 4 + offB1);
            ldsm4(Bl[0][0], Bl[0][1], Bl[1][0], Bl[1][1],
                  stb + 3 * PLANE_U * 4 + offB0);
            ldsm4(Bl[2][0], Bl[2][1], Bl[3][0], Bl[3][1],
                  stb + 3 * PLANE_U * 4 + offB1);

#pragma unroll
            for (int mt = 0; mt < 4; mt++)
#pragma unroll
                for (int nt = 0; nt < 4; nt++)
                    mma16(acc[mt][nt], Ah[mt][0], Ah[mt][1], Ah[mt][2], Ah[mt][3],
                          Bh[nt][0], Bh[nt][1]);
#pragma unroll
            for (int mt = 0; mt < 4; mt++)
#pragma unroll
                for (int nt = 0; nt < 4; nt++)
                    mma16(acc[mt][nt], Ah[mt][0], Ah[mt][1], Ah[mt][2], Ah[mt][3],
                          Bl[nt][0], Bl[nt][1]);
#pragma unroll
            for (int mt = 0; mt < 4; mt++)
#pragma unroll
                for (int nt = 0; nt < 4; nt++)
                    mma16(acc[mt][nt], Al[mt][0], Al[mt][1], Al[mt][2], Al[mt][3],
                          Bh[nt][0], Bh[nt][1]);
        }
    }

    // epilogue
#pragma unroll
    for (int mt = 0; mt < 4; mt++) {
        int rm = m0 + wm * 64 + mt * 16 + g;
#pragma unroll
        for (int nt = 0; nt < 4; nt++) {
            int cn = n0 + wn * 32 + nt * 8 + 2 * t;
            float bb0 = bias[cn];
            float bb1 = bias[cn + 1];
            float2 v0 = make_float2(acc[mt][nt][0] + bb0, acc[mt][nt][1] + bb1);
            float2 v1 = make_float2(acc[mt][nt][2] + bb0, acc[mt][nt][3] + bb1);
            if (mode == 0) {
                int head = cn >> 6;
                int pr   = (cn & 63) >> 1;
#pragma unroll
                for (int rr = 0; rr < 2; rr++) {
                    int row = rm + rr * 8;
                    float2 v = rr ? v1 : v0;
                    int bb = row >> 11;
                    int tt = row & (T_SEQ - 1);
                    size_t base = (((size_t)bb * N_HEADS + head) * T_SEQ + tt) * (HD / 2) + pr;
                    uint32_t hh, ll;
                    split2(v.x, v.y, hh, ll);
                    Yh[base] = hh;
                    Yl[base] = ll;
                }
            } else if (mode == 1) {
                // V: pair adjacent rows via shuffle, store packed
                // pair-of-rows planes [b,h,tpair,d]
                int head = cn >> 6;
                int d    = cn & 63;
                float p0x = __shfl_down_sync(0xffffffffu, v0.x, 4);
                float p0y = __shfl_down_sync(0xffffffffu, v0.y, 4);
                float p1x = __shfl_down_sync(0xffffffffu, v1.x, 4);
                float p1y = __shfl_down_sync(0xffffffffu, v1.y, 4);
                if ((g & 1) == 0) {
                    int bb = rm >> 11;
                    int tt = rm & (T_SEQ - 1);
                    size_t idx0 = (((size_t)bb * N_HEADS + head) * (T_SEQ / 2)
                                   + (tt >> 1)) * HD + d;
                    size_t idx1 = idx0 + 4 * HD;   // rows rm+8, rm+9
                    uint32_t hh, ll;
                    split2(v0.x, p0x, hh, ll); Yh[idx0] = hh;     Yl[idx0] = ll;
                    split2(v0.y, p0y, hh, ll); Yh[idx0 + 1] = hh; Yl[idx0 + 1] = ll;
                    split2(v1.x, p1x, hh, ll); Yh[idx1] = hh;     Yl[idx1] = ll;
                    split2(v1.y, p1y, hh, ll); Yh[idx1 + 1] = hh; Yl[idx1 + 1] = ll;
                }
            } else {
                *(float2*)(Yf + (size_t)rm * D_MODEL + cn) = v0;
                *(float2*)(Yf + (size_t)(rm + 8) * D_MODEL + cn) = v1;
            }
        }
    }
}

// grid-launched qkv: z = {Q,K,V}
__global__ void __launch_bounds__(256, 2)
qkv_kernel(const float* __restrict__ bq, const float* __restrict__ bk,
           const float* __restrict__ bv)
{
    const int z  = blockIdx.z;
    const int m0 = blockIdx.y * 128;
    const int n0 = blockIdx.x * 128;
    const float* bias = (z == 0) ? bq : (z == 1) ? bk : bv;
    const uint32_t* Wh = g_Wh + (size_t)z * D_MODEL * KPAIRS;
    const uint32_t* Wl = g_Wl + (size_t)z * D_MODEL * KPAIRS;
    if (z == 0)
        gemm_tile(m0, n0, g_Xh, g_Xl, Wh, Wl, bias, g_Qh, g_Ql, nullptr, 0);
    else if (z == 1)
        gemm_tile(m0, n0, g_Xh, g_Xl, Wh, Wl, bias, g_Kh, g_Kl, nullptr, 0);
    else
        gemm_tile(m0, n0, g_Xh, g_Xl, Wh, Wl, bias, g_Vph, g_Vpl, nullptr, 1);
}

__global__ void __launch_bounds__(256, 2)
out_kernel(const float* __restrict__ bo, float* __restrict__ out)
{
    gemm_tile(blockIdx.y * 128, blockIdx.x * 128,
              g_atth, g_attl,
              g_Wh + (size_t)3 * D_MODEL * KPAIRS,
              g_Wl + (size_t)3 * D_MODEL * KPAIRS,
              bo, nullptr, nullptr, out, 2);
}

// ---------------------------------------------------------------------------
// Tensor-core flash attention, 3xBF16 mma.sync, FIXED-MAX softmax,
// WINDOWED kv sweep:
//   p(i,j) = exp(qk/8 - (i-j) - 4): the exponential decay bounds the
//   weight of a token at distance D by exp(6 - D). Tokens beyond D=64
//   contribute < 1e-25 of the row sum, so each 128-row q block only
//   needs kv tiles j0 in {i0-64, i0, i0+64} (clipped at 0). Every row
//   keeps >= 64 positions of history; truncation error ~1e-25.
// ---------------------------------------------------------------------------
#define QH_OFF 0
#define QL_OFF 4608
#define KH_OFF 9216
#define KL_OFF 11520
#define VH_OFF 13824
#define VL_OFF 16128
#define PH_OFF 18432
#define PL_OFF 23040
#define ATT_U32 27648
#define ATT_SMEM_BYTES (ATT_U32 * 4)   // 110592

__global__ void __launch_bounds__(256, 2) attn_kernel()
{
    extern __shared__ uint32_t su[];
    uint32_t* Qh = su + QH_OFF;
    uint32_t* Ql = su + QL_OFF;
    uint32_t* Kh = su + KH_OFF;
    uint32_t* Kl = su + KL_OFF;
    uint32_t* Vh = su + VH_OFF;
    uint32_t* Vl = su + VL_OFF;
    uint32_t* Ph = su + PH_OFF;
    uint32_t* Pl = su + PL_OFF;

    const int tid  = threadIdx.x;
    const int lane = tid & 31;
    const int w    = tid >> 5;
    const int g    = lane >> 2;
    const int t    = lane & 3;

    const int bh = blockIdx.y;
    const int i0 = (int)blockIdx.x * 128;

    const uint32_t* Qh_g = g_Qh + (size_t)bh * T_SEQ * (HD / 2);
    const uint32_t* Ql_g = g_Ql + (size_t)bh * T_SEQ * (HD / 2);
    const uint32_t* Kh_g = g_Kh + (size_t)bh * T_SEQ * (HD / 2);
    const uint32_t* Kl_g = g_Kl + (size_t)bh * T_SEQ * (HD / 2);
    const uint32_t* Vph_g = g_Vph + (size_t)bh * (T_SEQ / 2) * HD;
    const uint32_t* Vpl_g = g_Vpl + (size_t)bh * (T_SEQ / 2) * HD;

#pragma unroll
    for (int rep = 0; rep < 4; rep++) {
        int idx = tid + rep * 256;
        int r = idx >> 3;
        int c = (idx & 7) * 4;
        cp16(Qh + r * 36 + c, Qh_g + (size_t)(i0 + r) * 32 + c);
        cp16(Ql + r * 36 + c, Ql_g + (size_t)(i0 + r) * 32 + c);
    }
    cp_commit();

    const int i_r0 = i0 + w * 16 + g;
    const int i_r1 = i_r0 + 8;
    const int warp_hi = i0 + w * 16 + 15;

    // p = exp2(qk*C1 + (j-i)*C2 - C3) = exp(qk/8 - (i-j) - 4)
    const float C1 = 0.18033688011f;   // 0.125 * log2(e)
    const float C2 = 1.44269504089f;   // log2(e)
    const float C3 = 5.77078016356f;   // 4 * log2(e)

    float l0r = 0.f, l1r = 0.f;
    float o[8][4];
#pragma unroll
    for (int nt = 0; nt < 8; nt++)
#pragma unroll
        for (int q = 0; q < 4; q++) o[nt][q] = 0.f;

    const int rw0 = w * 16 + g;
    const int rw1 = rw0 + 8;

    // windowed sweep: only tiles within decay reach (see header comment)
    const int j0_lo = (i0 >= 64) ? (i0 - 64) : 0;
    const int j0_hi = i0 + 64;                    // last tile any row needs

    for (int j0 = j0_lo; j0 <= j0_hi; j0 += 64) {
        __syncthreads();

        // K tiles (64 rows x 8 chunks x 2 planes)
#pragma unroll
        for (int rep = 0; rep < 2; rep++) {
            int idx = tid + rep * 256;
            int r = idx >> 3;
            int c = (idx & 7) * 4;
            cp16(Kh + r * 36 + c, Kh_g + (size_t)(j0 + r) * 32 + c);
            cp16(Kl + r * 36 + c, Kl_g + (size_t)(j0 + r) * 32 + c);
        }
        // V tiles: packed pair-of-rows, direct cp.async (32 rows x 16 chunks x 2)
#pragma unroll
        for (int rep = 0; rep < 2; rep++) {
            int idx = tid + rep * 256;     // 0..511
            int p = idx >> 4;              // pair row 0..31
            int c = (idx & 15) * 4;        // col 0,4,..,60
            cp16(Vh + p * 72 + c, Vph_g + ((size_t)(j0 >> 1) + p) * HD + c);
            cp16(Vl + p * 72 + c, Vpl_g + ((size_t)(j0 >> 1) + p) * HD + c);
        }
        cp_commit();
        cp_wait<0>();
        __syncthreads();

        if (j0 > warp_hi) continue;   // warp fully masked for this tile

        // ---- S = Q @ K^T ----
        float s[8][4];
#pragma unroll
        for (int nt = 0; nt < 8; nt++)
#pragma unroll
            for (int q = 0; q < 4; q++) s[nt][q] = 0.f;

#pragma unroll
        for (int ks = 0; ks < 4; ks++) {
            const int kp = ks * 8 + t;
            uint32_t a0h = Qh[rw0 * 36 + kp],     a0l = Ql[rw0 * 36 + kp];
            uint32_t a1h = Qh[rw1 * 36 + kp],     a1l = Ql[rw1 * 36 + kp];
            uint32_t a2h = Qh[rw0 * 36 + kp + 4], a2l = Ql[rw0 * 36 + kp + 4];
            uint32_t a3h = Qh[rw1 * 36 + kp + 4], a3l = Ql[rw1 * 36 + kp + 4];
#pragma unroll
            for (int nt = 0; nt < 8; nt++) {
                int rn = nt * 8 + g;
                uint32_t b0h = Kh[rn * 36 + kp],     b0l = Kl[rn * 36 + kp];
                uint32_t b1h = Kh[rn * 36 + kp + 4], b1l = Kl[rn * 36 + kp + 4];
                mma16(s[nt], a0h, a1h, a2h, a3h, b0h, b1h);
                mma16(s[nt], a0h, a1h, a2h, a3h, b0l, b1l);
                mma16(s[nt], a0l, a1l, a2l, a3l, b0h, b1h);
            }
        }

        // ---- mask + decay + exp (fixed max) ----
#pragma unroll
        for (int nt = 0; nt < 8; nt++) {
            int jb = j0 + nt * 8 + 2 * t;
            float d0 = fmaf((float)(jb - i_r0), C2, -C3);
            float d1 = fmaf((float)(jb - i_r1), C2, -C3);
            float p0 = (jb     <= i_r0) ? exp2f(fmaf(s[nt][0], C1, d0))      : 0.f;
            float p1 = (jb + 1 <= i_r0) ? exp2f(fmaf(s[nt][1], C1, d0 + C2)) : 0.f;
            float p2 = (jb     <= i_r1) ? exp2f(fmaf(s[nt][2], C1, d1))      : 0.f;
            float p3 = (jb + 1 <= i_r1) ? exp2f(fmaf(s[nt][3], C1, d1 + C2)) : 0.f;
            l0r += p0 + p1;
            l1r += p2 + p3;
            uint32_t hh, ll;
            split2(p0, p1, hh, ll);
            Ph[rw0 * 36 + nt * 4 + t] = hh;
            Pl[rw0 * 36 + nt * 4 + t] = ll;
            split2(p2, p3, hh, ll);
            Ph[rw1 * 36 + nt * 4 + t] = hh;
            Pl[rw1 * 36 + nt * 4 + t] = ll;
        }

        __syncwarp();

        // ---- O += P @ V ----
#pragma unroll
        for (int ks = 0; ks < 4; ks++) {
            const int kp = ks * 8 + t;
            uint32_t a0h = Ph[rw0 * 36 + kp],     a0l = Pl[rw0 * 36 + kp];
            uint32_t a1h = Ph[rw1 * 36 + kp],     a1l = Pl[rw1 * 36 + kp];
            uint32_t a2h = Ph[rw0 * 36 + kp + 4], a2l = Pl[rw0 * 36 + kp + 4];
            uint32_t a3h = Ph[rw1 * 36 + kp + 4], a3l = Pl[rw1 * 36 + kp + 4];
#pragma unroll
            for (int nt = 0; nt < 8; nt++) {
                int n = nt * 8 + g;
                uint32_t b0h = Vh[kp * 72 + n],       b0l = Vl[kp * 72 + n];
                uint32_t b1h = Vh[(kp + 4) * 72 + n], b1l = Vl[(kp + 4) * 72 + n];
                mma16(o[nt], a0h, a1h, a2h, a3h, b0h, b1h);
                mma16(o[nt], a0h, a1h, a2h, a3h, b0l, b1l);
                mma16(o[nt], a0l, a1l, a2l, a3l, b0h, b1h);
            }
        }
        __syncwarp();
    }

    // ---- final row-sum reduce + normalize + split + store packed ----
    l0r += __shfl_xor_sync(0xffffffffu, l0r, 1);
    l0r += __shfl_xor_sync(0xffffffffu, l0r, 2);
    l1r += __shfl_xor_sync(0xffffffffu, l1r, 1);
    l1r += __shfl_xor_sync(0xffffffffu, l1r, 2);

    const int b = bh >> 4;
    const int hh_ = bh & 15;
    const float inv0 = 1.0f / l0r;
    const float inv1 = 1.0f / l1r;
    size_t pb0 = ((size_t)b * T_SEQ + i_r0) * KPAIRS + hh_ * 32;
    size_t pb1 = ((size_t)b * T_SEQ + i_r1) * KPAIRS + hh_ * 32;
#pragma unroll
    for (int nt = 0; nt < 8; nt++) {
        int p = nt * 4 + t;
        uint32_t uh, ul;
        split2(o[nt][0] * inv0, o[nt][1] * inv0, uh, ul);
        g_atth[pb0 + p] = uh;
        g_attl[pb0 + p] = ul;
        split2(o[nt][2] * inv1, o[nt][3] * inv1, uh, ul);
        g_atth[pb1 + p] = uh;
        g_attl[pb1 + p] = ul;
    }
}

// ---------------------------------------------------------------------------
// Launch
// ---------------------------------------------------------------------------
extern "C" void kernel_launch(void* const* d_in, const int* in_sizes, int n_in,
                              void* d_out, int out_size)
{
    const float* x  = (const float*)d_in[0];
    const float* Wq = (const float*)d_in[1];
    const float* bq = (const float*)d_in[2];
    const float* Wk = (const float*)d_in[3];
    const float* bk = (const float*)d_in[4];
    const float* Wv = (const float*)d_in[5];
    const float* bv = (const float*)d_in[6];
    const float* Wo = (const float*)d_in[7];
    const float* bo = (const float*)d_in[8];
    float* out = (float*)d_out;

    cudaFuncSetAttribute(qkv_kernel,
                         cudaFuncAttributeMaxDynamicSharedMemorySize, GEMM_SMEM_BYTES);
    cudaFuncSetAttribute(out_kernel,
                         cudaFuncAttributeMaxDynamicSharedMemorySize, GEMM_SMEM_BYTES);
    cudaFuncSetAttribute(attn_kernel,
                         cudaFuncAttributeMaxDynamicSharedMemorySize, ATT_SMEM_BYTES);

    // pre-split X and all weights to bf16 hi/lo planes
    dim3 gp(2048, 8);
    prep_kernel<<<gp, 256>>>(x, Wq, Wk, Wv, Wo);

    // QKV projections (grid-launched, z = {Q,K,V})
    dim3 gq(D_MODEL / 128, M_ROWS / 128, 3);
    qkv_kernel<<<gq, 256, GEMM_SMEM_BYTES>>>(bq, bk, bv);

    // attention (windowed: <= 3 kv tiles per q block)
    dim3 ga(T_SEQ / 128, BATCH * N_HEADS);
    attn_kernel<<<ga, 256, ATT_SMEM_BYTES>>>();

    // output projection
    dim3 go(D_MODEL / 128, M_ROWS / 128);
    out_kernel<<<go, 256, GEMM_SMEM_BYTES>>>(bo, out);
}

// round 14
// speedup vs baseline: 1.5948x; 1.5213x over previous
#include <cuda_runtime.h>
#include <cuda_bf16.h>
#include <cstdint>

#define D_MODEL 1024
#define N_HEADS 16
#define HD      64
#define T_SEQ   2048
#define BATCH   2
#define M_ROWS  (BATCH * T_SEQ)   // 4096
#define KPAIRS  (D_MODEL / 2)     // 512 pairs per row

// ---------------------------------------------------------------------------
// Scratch (device globals; no allocation allowed)
// ---------------------------------------------------------------------------
__device__ uint32_t g_Xh[M_ROWS * KPAIRS];          // X pre-split hi plane
__device__ uint32_t g_Xl[M_ROWS * KPAIRS];
__device__ uint32_t g_Wh[4 * D_MODEL * KPAIRS];     // Wq,Wk,Wv,Wo hi planes
__device__ uint32_t g_Wl[4 * D_MODEL * KPAIRS];
__device__ uint32_t g_Qh[BATCH * N_HEADS * T_SEQ * (HD / 2)];  // [b,h,t,dpair]
__device__ uint32_t g_Ql[BATCH * N_HEADS * T_SEQ * (HD / 2)];
__device__ uint32_t g_Kh[BATCH * N_HEADS * T_SEQ * (HD / 2)];
__device__ uint32_t g_Kl[BATCH * N_HEADS * T_SEQ * (HD / 2)];
// V packed pair-of-rows: [b,h,tpair,d] u32 = bf16x2(row 2p, row 2p+1) at col d
__device__ uint32_t g_Vph[BATCH * N_HEADS * (T_SEQ / 2) * HD];
__device__ uint32_t g_Vpl[BATCH * N_HEADS * (T_SEQ / 2) * HD];
__device__ uint32_t g_atth[M_ROWS * KPAIRS];        // attention output packed
__device__ uint32_t g_attl[M_ROWS * KPAIRS];

// ---------------------------------------------------------------------------
// helpers
// ---------------------------------------------------------------------------
__device__ __forceinline__ void split2(float x0, float x1, uint32_t& h, uint32_t& l)
{
    __nv_bfloat162 hh = __floats2bfloat162_rn(x0, x1);
    float2 hf = __bfloat1622float2(hh);
    __nv_bfloat162 ll = __floats2bfloat162_rn(x0 - hf.x, x1 - hf.y);
    h = *reinterpret_cast<uint32_t*>(&hh);
    l = *reinterpret_cast<uint32_t*>(&ll);
}

__device__ __forceinline__ void mma16(float* c,
                                      uint32_t a0, uint32_t a1, uint32_t a2, uint32_t a3,
                                      uint32_t b0, uint32_t b1)
{
    asm volatile(
        "mma.sync.aligned.m16n8k16.row.col.f32.bf16.bf16.f32 "
        "{%0,%1,%2,%3}, {%4,%5,%6,%7}, {%8,%9}, {%0,%1,%2,%3};"
        : "+f"(c[0]), "+f"(c[1]), "+f"(c[2]), "+f"(c[3])
        : "r"(a0), "r"(a1), "r"(a2), "r"(a3), "r"(b0), "r"(b1));
}

__device__ __forceinline__ void ldsm4(uint32_t& r0, uint32_t& r1,
                                      uint32_t& r2, uint32_t& r3, uint32_t addr)
{
    asm volatile("ldmatrix.sync.aligned.m8n8.x4.shared.b16 {%0,%1,%2,%3}, [%4];"
                 : "=r"(r0), "=r"(r1), "=r"(r2), "=r"(r3) : "r"(addr));
}

__device__ __forceinline__ void cp16(void* dst_smem, const void* src)
{
    uint32_t s = (uint32_t)__cvta_generic_to_shared(dst_smem);
    asm volatile("cp.async.cg.shared.global [%0], [%1], 16;\n" :: "r"(s), "l"(src));
}
__device__ __forceinline__ void cp_commit()
{
    asm volatile("cp.async.commit_group;\n" ::);
}
template<int N>
__device__ __forceinline__ void cp_wait()
{
    asm volatile("cp.async.wait_group %0;\n" :: "n"(N));
}

// ---------------------------------------------------------------------------
// Prep kernel: split X and Wq/Wk/Wv/Wo into bf16x2 hi/lo planes (once).
// ---------------------------------------------------------------------------
__global__ void __launch_bounds__(256)
prep_kernel(const float* __restrict__ X,
            const float* __restrict__ Wq, const float* __restrict__ Wk,
            const float* __restrict__ Wv, const float* __restrict__ Wo)
{
    const int seg = blockIdx.y;
    const int idx = blockIdx.x * 256 + threadIdx.x;
    const float* src;
    uint32_t *dh, *dl;
    if (seg < 4) {
        src = X + (size_t)seg * 1048576;
        dh = g_Xh + (size_t)seg * 524288;
        dl = g_Xl + (size_t)seg * 524288;
    } else {
        const float* ws[4] = {Wq, Wk, Wv, Wo};
        src = ws[seg - 4];
        dh = g_Wh + (size_t)(seg - 4) * 524288;
        dl = g_Wl + (size_t)(seg - 4) * 524288;
    }
    float2 v = *(const float2*)(src + 2 * (size_t)idx);
    uint32_t h, l;
    split2(v.x, v.y, h, l);
    dh[idx] = h;
    dl[idx] = l;
}

// ---------------------------------------------------------------------------
// 3xBF16 mma.sync GEMM tile: Y[128,128 @ (m0,n0)] = X @ W^T + bias
// XOR-swizzled smem (RSU=16, chunk' = chunk ^ ((row>>1)&3)); NBUF=3;
// one __syncthreads + one cp_wait per 96-MMA period, prefetch distance 2.
// Output modes: 0 = packed Q/K planes, 1 = V packed pair-of-rows planes,
//               2 = float row-major (final out).
// ---------------------------------------------------------------------------
#define RSU      16                  // u32 per plane row (no pad)
#define PLANE_U  (128 * RSU)         // 2048 u32 per plane
#define BUF_U    (4 * PLANE_U)       // Ah, Al, Bh, Bl = 32 KB
#define NBUF     3
#define NPER     (D_MODEL / 32)      // 32 periods
#define GEMM_SMEM_BYTES (NBUF * BUF_U * 4)   // 98304

__device__ __forceinline__ uint32_t sw_off(int row, int chunk)
{
    return (uint32_t)(row * RSU + ((chunk ^ ((row >> 1) & 3)) << 2));
}

__device__ __forceinline__ void gemm_tile(int m0, int n0,
                                          const uint32_t* __restrict__ Xh,
                                          const uint32_t* __restrict__ Xl,
                                          const uint32_t* __restrict__ Wh,
                                          const uint32_t* __restrict__ Wl,
                                          const float* __restrict__ bias,
                                          uint32_t* __restrict__ Yh,
                                          uint32_t* __restrict__ Yl,
                                          float* __restrict__ Yf,
                                          int mode)
{
    extern __shared__ uint32_t smem[];
    const uint32_t sbase = (uint32_t)__cvta_generic_to_shared(smem);

    const int tid  = threadIdx.x;
    const int lane = tid & 31;
    const int wid  = tid >> 5;
    const int wm   = wid >> 2;
    const int wn   = wid & 3;
    const int g    = lane >> 2;
    const int t    = lane & 3;

    const int lrow = tid >> 2;
    const int lcix = tid & 3;
    const uint32_t ldst0 = sw_off(lrow,      lcix);
    const uint32_t ldst1 = sw_off(lrow + 64, lcix);

    const uint32_t* srcs[4] = {
        Xh + (size_t)m0 * KPAIRS, Xl + (size_t)m0 * KPAIRS,
        Wh + (size_t)n0 * KPAIRS, Wl + (size_t)n0 * KPAIRS };

    const int a_row = (lane & 7) + ((lane >> 3) & 1) * 8;
    const int hiA   = lane >> 4;
    int baseA[4], swA[4];
#pragma unroll
    for (int mt = 0; mt < 4; mt++) {
        int rg = wm * 64 + mt * 16 + a_row;
        baseA[mt] = rg * RSU;
        swA[mt]   = (rg >> 1) & 3;
    }
    const int b_row = (lane & 7) + ((lane >> 4) ? 8 : 0);
    const int hiB   = (lane >> 3) & 1;
    const int rgB0  = wn * 32 + b_row;
    const int rgB1  = rgB0 + 16;
    const int baseB0 = rgB0 * RSU, swB0 = (rgB0 >> 1) & 3;
    const int baseB1 = rgB1 * RSU, swB1 = (rgB1 >> 1) & 3;

    float acc[4][4][4];
#pragma unroll
    for (int i = 0; i < 4; i++)
#pragma unroll
        for (int j = 0; j < 4; j++)
#pragma unroll
            for (int q = 0; q < 4; q++) acc[i][j][q] = 0.f;

    auto load_buf = [&](int b, int p) {
        uint32_t* base = smem + b * BUF_U;
        const int koff = p * 16;
#pragma unroll
        for (int pi = 0; pi < 4; pi++) {
            const uint32_t* sp = srcs[pi] + koff + lcix * 4;
            uint32_t* dp = base + pi * PLANE_U;
            cp16(dp + ldst0, sp + (size_t)lrow * KPAIRS);
            cp16(dp + ldst1, sp + (size_t)(lrow + 64) * KPAIRS);
        }
        cp_commit();
    };

    // prologue
    load_buf(0, 0);
    load_buf(1, 1);

    for (int p = 0; p < NPER; p++) {
        cp_wait<1>();
        __syncthreads();
        if (p + 2 < NPER) load_buf((p + 2) % 3, p + 2);
        else              cp_commit();

        const uint32_t stb = sbase + (uint32_t)((p % 3) * BUF_U) * 4;

#pragma unroll
        for (int ks = 0; ks < 2; ks++) {
            uint32_t Ah[4][4], Al[4][4];
#pragma unroll
            for (int mt = 0; mt < 4; mt++) {
                uint32_t offA = (uint32_t)(baseA[mt] +
                                (((2 * ks + hiA) ^ swA[mt]) << 2)) * 4;
                ldsm4(Ah[mt][0], Ah[mt][1], Ah[mt][2], Ah[mt][3], stb + offA);
                ldsm4(Al[mt][0], Al[mt][1], Al[mt][2], Al[mt][3],
                      stb + PLANE_U * 4 + offA);
            }
            uint32_t offB0 = (uint32_t)(baseB0 + (((2 * ks + hiB) ^ swB0) << 2)) * 4;
            uint32_t offB1 = (uint32_t)(baseB1 + (((2 * ks + hiB) ^ swB1) << 2)) * 4;
            uint32_t Bh[4][2], Bl[4][2];
            ldsm4(Bh[0][0], Bh[0][1], Bh[1][0], Bh[1][1],
                  stb + 2 * PLANE_U * 4 + offB0);
            ldsm4(Bh[2][0], Bh[2][1], Bh[3][0], Bh[3][1],
                  stb + 2 * PLANE_U * 4 + offB1);
            ldsm4(Bl[0][0], Bl[0][1], Bl[1][0], Bl[1][1],
                  stb + 3 * PLANE_U * 4 + offB0);
            ldsm4(Bl[2][0], Bl[2][1], Bl[3][0], Bl[3][1],
                  stb + 3 * PLANE_U * 4 + offB1);

#pragma unroll
            for (int mt = 0; mt < 4; mt++)
#pragma unroll
                for (int nt = 0; nt < 4; nt++)
                    mma16(acc[mt][nt], Ah[mt][0], Ah[mt][1], Ah[mt][2], Ah[mt][3],
                          Bh[nt][0], Bh[nt][1]);
#pragma unroll
            for (int mt = 0; mt < 4; mt++)
#pragma unroll
                for (int nt = 0; nt < 4; nt++)
                    mma16(acc[mt][nt], Ah[mt][0], Ah[mt][1], Ah[mt][2], Ah[mt][3],
                          Bl[nt][0], Bl[nt][1]);
#pragma unroll
            for (int mt = 0; mt < 4; mt++)
#pragma unroll
                for (int nt = 0; nt < 4; nt++)
                    mma16(acc[mt][nt], Al[mt][0], Al[mt][1], Al[mt][2], Al[mt][3],
                          Bh[nt][0], Bh[nt][1]);
        }
    }

    // epilogue
#pragma unroll
    for (int mt = 0; mt < 4; mt++) {
        int rm = m0 + wm * 64 + mt * 16 + g;
#pragma unroll
        for (int nt = 0; nt < 4; nt++) {
            int cn = n0 + wn * 32 + nt * 8 + 2 * t;
            float bb0 = bias[cn];
            float bb1 = bias[cn + 1];
            float2 v0 = make_float2(acc[mt][nt][0] + bb0, acc[mt][nt][1] + bb1);
            float2 v1 = make_float2(acc[mt][nt][2] + bb0, acc[mt][nt][3] + bb1);
            if (mode == 0) {
                int head = cn >> 6;
                int pr   = (cn & 63) >> 1;
#pragma unroll
                for (int rr = 0; rr < 2; rr++) {
                    int row = rm + rr * 8;
                    float2 v = rr ? v1 : v0;
                    int bb = row >> 11;
                    int tt = row & (T_SEQ - 1);
                    size_t base = (((size_t)bb * N_HEADS + head) * T_SEQ + tt) * (HD / 2) + pr;
                    uint32_t hh, ll;
                    split2(v.x, v.y, hh, ll);
                    Yh[base] = hh;
                    Yl[base] = ll;
                }
            } else if (mode == 1) {
                // V: pair adjacent rows via shuffle, store packed
                // pair-of-rows planes [b,h,tpair,d]
                int head = cn >> 6;
                int d    = cn & 63;
                float p0x = __shfl_down_sync(0xffffffffu, v0.x, 4);
                float p0y = __shfl_down_sync(0xffffffffu, v0.y, 4);
                float p1x = __shfl_down_sync(0xffffffffu, v1.x, 4);
                float p1y = __shfl_down_sync(0xffffffffu, v1.y, 4);
                if ((g & 1) == 0) {
                    int bb = rm >> 11;
                    int tt = rm & (T_SEQ - 1);
                    size_t idx0 = (((size_t)bb * N_HEADS + head) * (T_SEQ / 2)
                                   + (tt >> 1)) * HD + d;
                    size_t idx1 = idx0 + 4 * HD;   // rows rm+8, rm+9
                    uint32_t hh, ll;
                    split2(v0.x, p0x, hh, ll); Yh[idx0] = hh;     Yl[idx0] = ll;
                    split2(v0.y, p0y, hh, ll); Yh[idx0 + 1] = hh; Yl[idx0 + 1] = ll;
                    split2(v1.x, p1x, hh, ll); Yh[idx1] = hh;     Yl[idx1] = ll;
                    split2(v1.y, p1y, hh, ll); Yh[idx1 + 1] = hh; Yl[idx1 + 1] = ll;
                }
            } else {
                *(float2*)(Yf + (size_t)rm * D_MODEL + cn) = v0;
                *(float2*)(Yf + (size_t)(rm + 8) * D_MODEL + cn) = v1;
            }
        }
    }
}

// grid-launched qkv: z = {Q,K,V}
__global__ void __launch_bounds__(256, 2)
qkv_kernel(const float* __restrict__ bq, const float* __restrict__ bk,
           const float* __restrict__ bv)
{
    const int z  = blockIdx.z;
    const int m0 = blockIdx.y * 128;
    const int n0 = blockIdx.x * 128;
    const float* bias = (z == 0) ? bq : (z == 1) ? bk : bv;
    const uint32_t* Wh = g_Wh + (size_t)z * D_MODEL * KPAIRS;
    const uint32_t* Wl = g_Wl + (size_t)z * D_MODEL * KPAIRS;
    if (z == 0)
        gemm_tile(m0, n0, g_Xh, g_Xl, Wh, Wl, bias, g_Qh, g_Ql, nullptr, 0);
    else if (z == 1)
        gemm_tile(m0, n0, g_Xh, g_Xl, Wh, Wl, bias, g_Kh, g_Kl, nullptr, 0);
    else
        gemm_tile(m0, n0, g_Xh, g_Xl, Wh, Wl, bias, g_Vph, g_Vpl, nullptr, 1);
}

__global__ void __launch_bounds__(256, 2)
out_kernel(const float* __restrict__ bo, float* __restrict__ out)
{
    gemm_tile(blockIdx.y * 128, blockIdx.x * 128,
              g_atth, g_attl,
              g_Wh + (size_t)3 * D_MODEL * KPAIRS,
              g_Wl + (size_t)3 * D_MODEL * KPAIRS,
              bo, nullptr, nullptr, out, 2);
}

// ---------------------------------------------------------------------------
// Tensor-core flash attention, 3xBF16 mma.sync, FIXED-MAX softmax,
// WINDOWED kv sweep, Q-in-registers, DOUBLE-BUFFERED K/V prefetch.
//   p(i,j) = exp(qk/8 - (i-j) - 4); tokens beyond distance 64 contribute
//   < 1e-25 of the row sum, so only kv tiles {i0-64, i0, i0+64} matter.
// Q fragments live in registers (loaded once via a staging buffer), which
// frees enough smem for two K/V buffers: tile j+1's cp.async is issued
// before waiting on tile j, hiding global latency under compute.
// ---------------------------------------------------------------------------
#define P_OFF   0        // Ph [128][36], Pl at +4608
#define KV0_OFF 9216     // per KV buf: Kh +0, Kl +2304, Vh +4608, Vl +6912
#define KV1_OFF 18432    //   (K planes 64x36, V planes 32x72; 9216 u32 each)
#define ATT_U32 27648
#define ATT_SMEM_BYTES (ATT_U32 * 4)   // 110592

__global__ void __launch_bounds__(256, 2) attn_kernel()
{
    extern __shared__ uint32_t su[];
    uint32_t* Ph = su + P_OFF;
    uint32_t* Pl = su + P_OFF + 4608;

    const int tid  = threadIdx.x;
    const int lane = tid & 31;
    const int w    = tid >> 5;
    const int g    = lane >> 2;
    const int t    = lane & 3;

    const int bh = blockIdx.y;
    const int i0 = (int)blockIdx.x * 128;

    const uint32_t* Qh_g = g_Qh + (size_t)bh * T_SEQ * (HD / 2);
    const uint32_t* Ql_g = g_Ql + (size_t)bh * T_SEQ * (HD / 2);
    const uint32_t* Kh_g = g_Kh + (size_t)bh * T_SEQ * (HD / 2);
    const uint32_t* Kl_g = g_Kl + (size_t)bh * T_SEQ * (HD / 2);
    const uint32_t* Vph_g = g_Vph + (size_t)bh * (T_SEQ / 2) * HD;
    const uint32_t* Vpl_g = g_Vpl + (size_t)bh * (T_SEQ / 2) * HD;

    // ---- stage Q into KV1 region, then lift fragments to registers ----
#pragma unroll
    for (int rep = 0; rep < 4; rep++) {
        int idx = tid + rep * 256;
        int r = idx >> 3;
        int c = (idx & 7) * 4;
        cp16(su + KV1_OFF + r * 36 + c,        Qh_g + (size_t)(i0 + r) * 32 + c);
        cp16(su + KV1_OFF + 4608 + r * 36 + c, Ql_g + (size_t)(i0 + r) * 32 + c);
    }
    cp_commit();
    cp_wait<0>();
    __syncthreads();

    const int rw0 = w * 16 + g;
    const int rw1 = rw0 + 8;

    uint32_t qh[4][4], ql[4][4];
#pragma unroll
    for (int ks = 0; ks < 4; ks++) {
        const int kp = ks * 8 + t;
        qh[ks][0] = su[KV1_OFF + rw0 * 36 + kp];
        qh[ks][1] = su[KV1_OFF + rw1 * 36 + kp];
        qh[ks][2] = su[KV1_OFF + rw0 * 36 + kp + 4];
        qh[ks][3] = su[KV1_OFF + rw1 * 36 + kp + 4];
        ql[ks][0] = su[KV1_OFF + 4608 + rw0 * 36 + kp];
        ql[ks][1] = su[KV1_OFF + 4608 + rw1 * 36 + kp];
        ql[ks][2] = su[KV1_OFF + 4608 + rw0 * 36 + kp + 4];
        ql[ks][3] = su[KV1_OFF + 4608 + rw1 * 36 + kp + 4];
    }
    __syncthreads();   // everyone done reading Q before KV1 is reused

    const int i_r0 = i0 + w * 16 + g;
    const int i_r1 = i_r0 + 8;
    const int warp_hi = i0 + w * 16 + 15;

    // p = exp2(qk*C1 + (j-i)*C2 - C3) = exp(qk/8 - (i-j) - 4)
    const float C1 = 0.18033688011f;   // 0.125 * log2(e)
    const float C2 = 1.44269504089f;   // log2(e)
    const float C3 = 5.77078016356f;   // 4 * log2(e)

    float l0r = 0.f, l1r = 0.f;
    float o[8][4];
#pragma unroll
    for (int nt = 0; nt < 8; nt++)
#pragma unroll
        for (int q = 0; q < 4; q++) o[nt][q] = 0.f;

    // KV tile loader: buffer base kb (KV0_OFF or KV1_OFF), tile start j0
    auto load_kv = [&](int kb, int j0) {
#pragma unroll
        for (int rep = 0; rep < 2; rep++) {
            int idx = tid + rep * 256;     // 0..511
            int r = idx >> 3;
            int c = (idx & 7) * 4;
            cp16(su + kb + r * 36 + c,        Kh_g + (size_t)(j0 + r) * 32 + c);
            cp16(su + kb + 2304 + r * 36 + c, Kl_g + (size_t)(j0 + r) * 32 + c);
        }
#pragma unroll
        for (int rep = 0; rep < 2; rep++) {
            int idx = tid + rep * 256;     // 0..511
            int p = idx >> 4;              // pair row 0..31
            int c = (idx & 15) * 4;
            cp16(su + kb + 4608 + p * 72 + c,
                 Vph_g + ((size_t)(j0 >> 1) + p) * HD + c);
            cp16(su + kb + 6912 + p * 72 + c,
                 Vpl_g + ((size_t)(j0 >> 1) + p) * HD + c);
        }
        cp_commit();
    };

    // windowed sweep: tiles within decay reach
    const int j0_lo = (i0 >= 64) ? (i0 - 64) : 0;
    const int nT    = (i0 + 64 - j0_lo) / 64 + 1;   // 2 or 3 tiles

    load_kv(KV0_OFF, j0_lo);   // prefetch first tile

    for (int jt = 0; jt < nT; jt++) {
        const int j0 = j0_lo + jt * 64;
        const int kb = (jt & 1) ? KV1_OFF : KV0_OFF;
        const int ko = (jt & 1) ? KV0_OFF : KV1_OFF;

        __syncthreads();   // all warps done computing from buffer ko
        if (jt + 1 < nT) load_kv(ko, j0 + 64);
        else             cp_commit();      // keep group count uniform
        cp_wait<1>();      // tile jt's load complete (prefetch in flight)
        __syncthreads();   // publish buffer kb

        if (j0 > warp_hi) continue;   // warp fully masked for this tile

        const uint32_t* Kh = su + kb;
        const uint32_t* Kl = su + kb + 2304;
        const uint32_t* Vh = su + kb + 4608;
        const uint32_t* Vl = su + kb + 6912;

        // ---- S = Q @ K^T (Q from registers) ----
        float s[8][4];
#pragma unroll
        for (int nt = 0; nt < 8; nt++)
#pragma unroll
            for (int q = 0; q < 4; q++) s[nt][q] = 0.f;

#pragma unroll
        for (int ks = 0; ks < 4; ks++) {
            const int kp = ks * 8 + t;
#pragma unroll
            for (int nt = 0; nt < 8; nt++) {
                int rn = nt * 8 + g;
                uint32_t b0h = Kh[rn * 36 + kp],     b0l = Kl[rn * 36 + kp];
                uint32_t b1h = Kh[rn * 36 + kp + 4], b1l = Kl[rn * 36 + kp + 4];
                mma16(s[nt], qh[ks][0], qh[ks][1], qh[ks][2], qh[ks][3], b0h, b1h);
                mma16(s[nt], qh[ks][0], qh[ks][1], qh[ks][2], qh[ks][3], b0l, b1l);
                mma16(s[nt], ql[ks][0], ql[ks][1], ql[ks][2], ql[ks][3], b0h, b1h);
            }
        }

        // ---- mask + decay + exp (fixed max) ----
#pragma unroll
        for (int nt = 0; nt < 8; nt++) {
            int jb = j0 + nt * 8 + 2 * t;
            float d0 = fmaf((float)(jb - i_r0), C2, -C3);
            float d1 = fmaf((float)(jb - i_r1), C2, -C3);
            float p0 = (jb     <= i_r0) ? exp2f(fmaf(s[nt][0], C1, d0))      : 0.f;
            float p1 = (jb + 1 <= i_r0) ? exp2f(fmaf(s[nt][1], C1, d0 + C2)) : 0.f;
            float p2 = (jb     <= i_r1) ? exp2f(fmaf(s[nt][2], C1, d1))      : 0.f;
            float p3 = (jb + 1 <= i_r1) ? exp2f(fmaf(s[nt][3], C1, d1 + C2)) : 0.f;
            l0r += p0 + p1;
            l1r += p2 + p3;
            uint32_t hh, ll;
            split2(p0, p1, hh, ll);
            Ph[rw0 * 36 + nt * 4 + t] = hh;
            Pl[rw0 * 36 + nt * 4 + t] = ll;
            split2(p2, p3, hh, ll);
            Ph[rw1 * 36 + nt * 4 + t] = hh;
            Pl[rw1 * 36 + nt * 4 + t] = ll;
        }

        __syncwarp();

        // ---- O += P @ V ----
#pragma unroll
        for (int ks = 0; ks < 4; ks++) {
            const int kp = ks * 8 + t;
            uint32_t a0h = Ph[rw0 * 36 + kp],     a0l = Pl[rw0 * 36 + kp];
            uint32_t a1h = Ph[rw1 * 36 + kp],     a1l = Pl[rw1 * 36 + kp];
            uint32_t a2h = Ph[rw0 * 36 + kp + 4], a2l = Pl[rw0 * 36 + kp + 4];
            uint32_t a3h = Ph[rw1 * 36 + kp + 4], a3l = Pl[rw1 * 36 + kp + 4];
#pragma unroll
            for (int nt = 0; nt < 8; nt++) {
                int n = nt * 8 + g;
                uint32_t b0h = Vh[kp * 72 + n],       b0l = Vl[kp * 72 + n];
                uint32_t b1h = Vh[(kp + 4) * 72 + n], b1l = Vl[(kp + 4) * 72 + n];
                mma16(o[nt], a0h, a1h, a2h, a3h, b0h, b1h);
                mma16(o[nt], a0h, a1h, a2h, a3h, b0l, b1l);
                mma16(o[nt], a0l, a1l, a2l, a3l, b0h, b1h);
            }
        }
        __syncwarp();
    }

    // ---- final row-sum reduce + normalize + split + store packed ----
    l0r += __shfl_xor_sync(0xffffffffu, l0r, 1);
    l0r += __shfl_xor_sync(0xffffffffu, l0r, 2);
    l1r += __shfl_xor_sync(0xffffffffu, l1r, 1);
    l1r += __shfl_xor_sync(0xffffffffu, l1r, 2);

    const int b = bh >> 4;
    const int hh_ = bh & 15;
    const float inv0 = 1.0f / l0r;
    const float inv1 = 1.0f / l1r;
    size_t pb0 = ((size_t)b * T_SEQ + i_r0) * KPAIRS + hh_ * 32;
    size_t pb1 = ((size_t)b * T_SEQ + i_r1) * KPAIRS + hh_ * 32;
#pragma unroll
    for (int nt = 0; nt < 8; nt++) {
        int p = nt * 4 + t;
        uint32_t uh, ul;
        split2(o[nt][0] * inv0, o[nt][1] * inv0, uh, ul);
        g_atth[pb0 + p] = uh;
        g_attl[pb0 + p] = ul;
        split2(o[nt][2] * inv1, o[nt][3] * inv1, uh, ul);
        g_atth[pb1 + p] = uh;
        g_attl[pb1 + p] = ul;
    }
}

// ---------------------------------------------------------------------------
// Launch
// ---------------------------------------------------------------------------
extern "C" void kernel_launch(void* const* d_in, const int* in_sizes, int n_in,
                              void* d_out, int out_size)
{
    const float* x  = (const float*)d_in[0];
    const float* Wq = (const float*)d_in[1];
    const float* bq = (const float*)d_in[2];
    const float* Wk = (const float*)d_in[3];
    const float* bk = (const float*)d_in[4];
    const float* Wv = (const float*)d_in[5];
    const float* bv = (const float*)d_in[6];
    const float* Wo = (const float*)d_in[7];
    const float* bo = (const float*)d_in[8];
    float* out = (float*)d_out;

    cudaFuncSetAttribute(qkv_kernel,
                         cudaFuncAttributeMaxDynamicSharedMemorySize, GEMM_SMEM_BYTES);
    cudaFuncSetAttribute(out_kernel,
                         cudaFuncAttributeMaxDynamicSharedMemorySize, GEMM_SMEM_BYTES);
    cudaFuncSetAttribute(attn_kernel,
                         cudaFuncAttributeMaxDynamicSharedMemorySize, ATT_SMEM_BYTES);

    // pre-split X and all weights to bf16 hi/lo planes
    dim3 gp(2048, 8);
    prep_kernel<<<gp, 256>>>(x, Wq, Wk, Wv, Wo);

    // QKV projections (grid-launched, z = {Q,K,V})
    dim3 gq(D_MODEL / 128, M_ROWS / 128, 3);
    qkv_kernel<<<gq, 256, GEMM_SMEM_BYTES>>>(bq, bk, bv);

    // attention (windowed + double-buffered)
    dim3 ga(T_SEQ / 128, BATCH * N_HEADS);
    attn_kernel<<<ga, 256, ATT_SMEM_BYTES>>>();

    // output projection
    dim3 go(D_MODEL / 128, M_ROWS / 128);
    out_kernel<<<go, 256, GEMM_SMEM_BYTES>>>(bo, out);
}

// round 15
// speedup vs baseline: 1.6423x; 1.0298x over previous
#include <cuda_runtime.h>
#include <cuda_bf16.h>
#include <cstdint>

#define D_MODEL 1024
#define N_HEADS 16
#define HD      64
#define T_SEQ   2048
#define BATCH   2
#define M_ROWS  (BATCH * T_SEQ)   // 4096
#define KPAIRS  (D_MODEL / 2)     // 512 pairs per row

// ---------------------------------------------------------------------------
// Scratch (device globals; no allocation allowed)
// ---------------------------------------------------------------------------
__device__ uint32_t g_Xh[M_ROWS * KPAIRS];          // X pre-split hi plane
__device__ uint32_t g_Xl[M_ROWS * KPAIRS];
__device__ uint32_t g_Wh[4 * D_MODEL * KPAIRS];     // Wq,Wk,Wv,Wo hi planes
__device__ uint32_t g_Wl[4 * D_MODEL * KPAIRS];
__device__ uint32_t g_Qh[BATCH * N_HEADS * T_SEQ * (HD / 2)];  // [b,h,t,dpair]
__device__ uint32_t g_Ql[BATCH * N_HEADS * T_SEQ * (HD / 2)];
__device__ uint32_t g_Kh[BATCH * N_HEADS * T_SEQ * (HD / 2)];
__device__ uint32_t g_Kl[BATCH * N_HEADS * T_SEQ * (HD / 2)];
// V packed pair-of-rows: [b,h,tpair,d] u32 = bf16x2(row 2p, row 2p+1) at col d
__device__ uint32_t g_Vph[BATCH * N_HEADS * (T_SEQ / 2) * HD];
__device__ uint32_t g_Vpl[BATCH * N_HEADS * (T_SEQ / 2) * HD];
__device__ uint32_t g_atth[M_ROWS * KPAIRS];        // attention output packed
__device__ uint32_t g_attl[M_ROWS * KPAIRS];

// ---------------------------------------------------------------------------
// helpers
// ---------------------------------------------------------------------------
__device__ __forceinline__ void split2(float x0, float x1, uint32_t& h, uint32_t& l)
{
    __nv_bfloat162 hh = __floats2bfloat162_rn(x0, x1);
    float2 hf = __bfloat1622float2(hh);
    __nv_bfloat162 ll = __floats2bfloat162_rn(x0 - hf.x, x1 - hf.y);
    h = *reinterpret_cast<uint32_t*>(&hh);
    l = *reinterpret_cast<uint32_t*>(&ll);
}

__device__ __forceinline__ void mma16(float* c,
                                      uint32_t a0, uint32_t a1, uint32_t a2, uint32_t a3,
                                      uint32_t b0, uint32_t b1)
{
    asm volatile(
        "mma.sync.aligned.m16n8k16.row.col.f32.bf16.bf16.f32 "
        "{%0,%1,%2,%3}, {%4,%5,%6,%7}, {%8,%9}, {%0,%1,%2,%3};"
        : "+f"(c[0]), "+f"(c[1]), "+f"(c[2]), "+f"(c[3])
        : "r"(a0), "r"(a1), "r"(a2), "r"(a3), "r"(b0), "r"(b1));
}

__device__ __forceinline__ void ldsm4(uint32_t& r0, uint32_t& r1,
                                      uint32_t& r2, uint32_t& r3, uint32_t addr)
{
    asm volatile("ldmatrix.sync.aligned.m8n8.x4.shared.b16 {%0,%1,%2,%3}, [%4];"
                 : "=r"(r0), "=r"(r1), "=r"(r2), "=r"(r3) : "r"(addr));
}

__device__ __forceinline__ void cp16(void* dst_smem, const void* src)
{
    uint32_t s = (uint32_t)__cvta_generic_to_shared(dst_smem);
    asm volatile("cp.async.cg.shared.global [%0], [%1], 16;\n" :: "r"(s), "l"(src));
}
__device__ __forceinline__ void cp_commit()
{
    asm volatile("cp.async.commit_group;\n" ::);
}
template<int N>
__device__ __forceinline__ void cp_wait()
{
    asm volatile("cp.async.wait_group %0;\n" :: "n"(N));
}

// ---------------------------------------------------------------------------
// Prep kernel: split X and Wq/Wk/Wv/Wo into bf16x2 hi/lo planes (once).
// float4 per thread (2 pairs).
// ---------------------------------------------------------------------------
__global__ void __launch_bounds__(256)
prep_kernel(const float* __restrict__ X,
            const float* __restrict__ Wq, const float* __restrict__ Wk,
            const float* __restrict__ Wv, const float* __restrict__ Wo)
{
    const int seg = blockIdx.y;
    const int idx = blockIdx.x * 256 + threadIdx.x;   // float4 index in segment
    const float* src;
    uint32_t *dh, *dl;
    if (seg < 4) {
        src = X + (size_t)seg * 1048576;
        dh = g_Xh + (size_t)seg * 524288;
        dl = g_Xl + (size_t)seg * 524288;
    } else {
        const float* ws[4] = {Wq, Wk, Wv, Wo};
        src = ws[seg - 4];
        dh = g_Wh + (size_t)(seg - 4) * 524288;
        dl = g_Wl + (size_t)(seg - 4) * 524288;
    }
    float4 v = *(const float4*)(src + 4 * (size_t)idx);
    uint32_t h0, l0, h1, l1;
    split2(v.x, v.y, h0, l0);
    split2(v.z, v.w, h1, l1);
    *(uint2*)(dh + 2 * (size_t)idx) = make_uint2(h0, h1);
    *(uint2*)(dl + 2 * (size_t)idx) = make_uint2(l0, l1);
}

// ---------------------------------------------------------------------------
// 3xBF16 mma.sync GEMM tile: Y[128,128 @ (m0,n0)] = X @ W^T + bias
// (frozen from R12/R14 — XOR-swizzled smem, NBUF=3, 1 barrier/period)
// ---------------------------------------------------------------------------
#define RSU      16
#define PLANE_U  (128 * RSU)
#define BUF_U    (4 * PLANE_U)
#define NBUF     3
#define NPER     (D_MODEL / 32)
#define GEMM_SMEM_BYTES (NBUF * BUF_U * 4)   // 98304

__device__ __forceinline__ uint32_t sw_off(int row, int chunk)
{
    return (uint32_t)(row * RSU + ((chunk ^ ((row >> 1) & 3)) << 2));
}

__device__ __forceinline__ void gemm_tile(int m0, int n0,
                                          const uint32_t* __restrict__ Xh,
                                          const uint32_t* __restrict__ Xl,
                                          const uint32_t* __restrict__ Wh,
                                          const uint32_t* __restrict__ Wl,
                                          const float* __restrict__ bias,
                                          uint32_t* __restrict__ Yh,
                                          uint32_t* __restrict__ Yl,
                                          float* __restrict__ Yf,
                                          int mode)
{
    extern __shared__ uint32_t smem[];
    const uint32_t sbase = (uint32_t)__cvta_generic_to_shared(smem);

    const int tid  = threadIdx.x;
    const int lane = tid & 31;
    const int wid  = tid >> 5;
    const int wm   = wid >> 2;
    const int wn   = wid & 3;
    const int g    = lane >> 2;
    const int t    = lane & 3;

    const int lrow = tid >> 2;
    const int lcix = tid & 3;
    const uint32_t ldst0 = sw_off(lrow,      lcix);
    const uint32_t ldst1 = sw_off(lrow + 64, lcix);

    const uint32_t* srcs[4] = {
        Xh + (size_t)m0 * KPAIRS, Xl + (size_t)m0 * KPAIRS,
        Wh + (size_t)n0 * KPAIRS, Wl + (size_t)n0 * KPAIRS };

    const int a_row = (lane & 7) + ((lane >> 3) & 1) * 8;
    const int hiA   = lane >> 4;
    int baseA[4], swA[4];
#pragma unroll
    for (int mt = 0; mt < 4; mt++) {
        int rg = wm * 64 + mt * 16 + a_row;
        baseA[mt] = rg * RSU;
        swA[mt]   = (rg >> 1) & 3;
    }
    const int b_row = (lane & 7) + ((lane >> 4) ? 8 : 0);
    const int hiB   = (lane >> 3) & 1;
    const int rgB0  = wn * 32 + b_row;
    const int rgB1  = rgB0 + 16;
    const int baseB0 = rgB0 * RSU, swB0 = (rgB0 >> 1) & 3;
    const int baseB1 = rgB1 * RSU, swB1 = (rgB1 >> 1) & 3;

    float acc[4][4][4];
#pragma unroll
    for (int i = 0; i < 4; i++)
#pragma unroll
        for (int j = 0; j < 4; j++)
#pragma unroll
            for (int q = 0; q < 4; q++) acc[i][j][q] = 0.f;

    auto load_buf = [&](int b, int p) {
        uint32_t* base = smem + b * BUF_U;
        const int koff = p * 16;
#pragma unroll
        for (int pi = 0; pi < 4; pi++) {
            const uint32_t* sp = srcs[pi] + koff + lcix * 4;
            uint32_t* dp = base + pi * PLANE_U;
            cp16(dp + ldst0, sp + (size_t)lrow * KPAIRS);
            cp16(dp + ldst1, sp + (size_t)(lrow + 64) * KPAIRS);
        }
        cp_commit();
    };

    load_buf(0, 0);
    load_buf(1, 1);

    for (int p = 0; p < NPER; p++) {
        cp_wait<1>();
        __syncthreads();
        if (p + 2 < NPER) load_buf((p + 2) % 3, p + 2);
        else              cp_commit();

        const uint32_t stb = sbase + (uint32_t)((p % 3) * BUF_U) * 4;

#pragma unroll
        for (int ks = 0; ks < 2; ks++) {
            uint32_t Ah[4][4], Al[4][4];
#pragma unroll
            for (int mt = 0; mt < 4; mt++) {
                uint32_t offA = (uint32_t)(baseA[mt] +
                                (((2 * ks + hiA) ^ swA[mt]) << 2)) * 4;
                ldsm4(Ah[mt][0], Ah[mt][1], Ah[mt][2], Ah[mt][3], stb + offA);
                ldsm4(Al[mt][0], Al[mt][1], Al[mt][2], Al[mt][3],
                      stb + PLANE_U * 4 + offA);
            }
            uint32_t offB0 = (uint32_t)(baseB0 + (((2 * ks + hiB) ^ swB0) << 2)) * 4;
            uint32_t offB1 = (uint32_t)(baseB1 + (((2 * ks + hiB) ^ swB1) << 2)) * 4;
            uint32_t Bh[4][2], Bl[4][2];
            ldsm4(Bh[0][0], Bh[0][1], Bh[1][0], Bh[1][1],
                  stb + 2 * PLANE_U * 4 + offB0);
            ldsm4(Bh[2][0], Bh[2][1], Bh[3][0], Bh[3][1],
                  stb + 2 * PLANE_U * 4 + offB1);
            ldsm4(Bl[0][0], Bl[0][1], Bl[1][0], Bl[1][1],
                  stb + 3 * PLANE_U * 4 + offB0);
            ldsm4(Bl[2][0], Bl[2][1], Bl[3][0], Bl[3][1],
                  stb + 3 * PLANE_U * 4 + offB1);

#pragma unroll
            for (int mt = 0; mt < 4; mt++)
#pragma unroll
                for (int nt = 0; nt < 4; nt++)
                    mma16(acc[mt][nt], Ah[mt][0], Ah[mt][1], Ah[mt][2], Ah[mt][3],
                          Bh[nt][0], Bh[nt][1]);
#pragma unroll
            for (int mt = 0; mt < 4; mt++)
#pragma unroll
                for (int nt = 0; nt < 4; nt++)
                    mma16(acc[mt][nt], Ah[mt][0], Ah[mt][1], Ah[mt][2], Ah[mt][3],
                          Bl[nt][0], Bl[nt][1]);
#pragma unroll
            for (int mt = 0; mt < 4; mt++)
#pragma unroll
                for (int nt = 0; nt < 4; nt++)
                    mma16(acc[mt][nt], Al[mt][0], Al[mt][1], Al[mt][2], Al[mt][3],
                          Bh[nt][0], Bh[nt][1]);
        }
    }

    // epilogue
#pragma unroll
    for (int mt = 0; mt < 4; mt++) {
        int rm = m0 + wm * 64 + mt * 16 + g;
#pragma unroll
        for (int nt = 0; nt < 4; nt++) {
            int cn = n0 + wn * 32 + nt * 8 + 2 * t;
            float bb0 = bias[cn];
            float bb1 = bias[cn + 1];
            float2 v0 = make_float2(acc[mt][nt][0] + bb0, acc[mt][nt][1] + bb1);
            float2 v1 = make_float2(acc[mt][nt][2] + bb0, acc[mt][nt][3] + bb1);
            if (mode == 0) {
                int head = cn >> 6;
                int pr   = (cn & 63) >> 1;
#pragma unroll
                for (int rr = 0; rr < 2; rr++) {
                    int row = rm + rr * 8;
                    float2 v = rr ? v1 : v0;
                    int bb = row >> 11;
                    int tt = row & (T_SEQ - 1);
                    size_t base = (((size_t)bb * N_HEADS + head) * T_SEQ + tt) * (HD / 2) + pr;
                    uint32_t hh, ll;
                    split2(v.x, v.y, hh, ll);
                    Yh[base] = hh;
                    Yl[base] = ll;
                }
            } else if (mode == 1) {
                int head = cn >> 6;
                int d    = cn & 63;
                float p0x = __shfl_down_sync(0xffffffffu, v0.x, 4);
                float p0y = __shfl_down_sync(0xffffffffu, v0.y, 4);
                float p1x = __shfl_down_sync(0xffffffffu, v1.x, 4);
                float p1y = __shfl_down_sync(0xffffffffu, v1.y, 4);
                if ((g & 1) == 0) {
                    int bb = rm >> 11;
                    int tt = rm & (T_SEQ - 1);
                    size_t idx0 = (((size_t)bb * N_HEADS + head) * (T_SEQ / 2)
                                   + (tt >> 1)) * HD + d;
                    size_t idx1 = idx0 + 4 * HD;
                    uint32_t hh, ll;
                    split2(v0.x, p0x, hh, ll); Yh[idx0] = hh;     Yl[idx0] = ll;
                    split2(v0.y, p0y, hh, ll); Yh[idx0 + 1] = hh; Yl[idx0 + 1] = ll;
                    split2(v1.x, p1x, hh, ll); Yh[idx1] = hh;     Yl[idx1] = ll;
                    split2(v1.y, p1y, hh, ll); Yh[idx1 + 1] = hh; Yl[idx1 + 1] = ll;
                }
            } else {
                *(float2*)(Yf + (size_t)rm * D_MODEL + cn) = v0;
                *(float2*)(Yf + (size_t)(rm + 8) * D_MODEL + cn) = v1;
            }
        }
    }
}

// grid-launched qkv: z = {Q,K,V}
__global__ void __launch_bounds__(256, 2)
qkv_kernel(const float* __restrict__ bq, const float* __restrict__ bk,
           const float* __restrict__ bv)
{
    const int z  = blockIdx.z;
    const int m0 = blockIdx.y * 128;
    const int n0 = blockIdx.x * 128;
    const float* bias = (z == 0) ? bq : (z == 1) ? bk : bv;
    const uint32_t* Wh = g_Wh + (size_t)z * D_MODEL * KPAIRS;
    const uint32_t* Wl = g_Wl + (size_t)z * D_MODEL * KPAIRS;
    if (z == 0)
        gemm_tile(m0, n0, g_Xh, g_Xl, Wh, Wl, bias, g_Qh, g_Ql, nullptr, 0);
    else if (z == 1)
        gemm_tile(m0, n0, g_Xh, g_Xl, Wh, Wl, bias, g_Kh, g_Kl, nullptr, 0);
    else
        gemm_tile(m0, n0, g_Xh, g_Xl, Wh, Wl, bias, g_Vph, g_Vpl, nullptr, 1);
}

__global__ void __launch_bounds__(256, 2)
out_kernel(const float* __restrict__ bo, float* __restrict__ out)
{
    gemm_tile(blockIdx.y * 128, blockIdx.x * 128,
              g_atth, g_attl,
              g_Wh + (size_t)3 * D_MODEL * KPAIRS,
              g_Wl + (size_t)3 * D_MODEL * KPAIRS,
              bo, nullptr, nullptr, out, 2);
}

// ---------------------------------------------------------------------------
// Tensor-core flash attention, 3xBF16 mma.sync, FIXED-MAX softmax,
// WINDOWED kv sweep, Q-in-registers, DOUBLE-BUFFERED K/V prefetch,
// PER-WARP tile skip:
//   p(i,j) = exp(qk/8 - (i-j) - 4); weight at distance D <= exp(6-D).
//   Block window: tiles {i0-64, i0, i0+64}. Per warp, a tile is skipped
//   when its farthest column is >64 behind the warp's lowest row
//   (j0 < warp_lo - 127) or entirely above the causal diagonal
//   (j0 > warp_hi). Each warp computes exactly 2 tiles.
// ---------------------------------------------------------------------------
#define P_OFF   0        // Ph [128][36], Pl at +4608
#define KV0_OFF 9216     // per KV buf: Kh +0, Kl +2304, Vh +4608, Vl +6912
#define KV1_OFF 18432
#define ATT_U32 27648
#define ATT_SMEM_BYTES (ATT_U32 * 4)   // 110592

__global__ void __launch_bounds__(256, 2) attn_kernel()
{
    extern __shared__ uint32_t su[];
    uint32_t* Ph = su + P_OFF;
    uint32_t* Pl = su + P_OFF + 4608;

    const int tid  = threadIdx.x;
    const int lane = tid & 31;
    const int w    = tid >> 5;
    const int g    = lane >> 2;
    const int t    = lane & 3;

    const int bh = blockIdx.y;
    const int i0 = (int)blockIdx.x * 128;

    const uint32_t* Qh_g = g_Qh + (size_t)bh * T_SEQ * (HD / 2);
    const uint32_t* Ql_g = g_Ql + (size_t)bh * T_SEQ * (HD / 2);
    const uint32_t* Kh_g = g_Kh + (size_t)bh * T_SEQ * (HD / 2);
    const uint32_t* Kl_g = g_Kl + (size_t)bh * T_SEQ * (HD / 2);
    const uint32_t* Vph_g = g_Vph + (size_t)bh * (T_SEQ / 2) * HD;
    const uint32_t* Vpl_g = g_Vpl + (size_t)bh * (T_SEQ / 2) * HD;

    // ---- stage Q into KV1 region, then lift fragments to registers ----
#pragma unroll
    for (int rep = 0; rep < 4; rep++) {
        int idx = tid + rep * 256;
        int r = idx >> 3;
        int c = (idx & 7) * 4;
        cp16(su + KV1_OFF + r * 36 + c,        Qh_g + (size_t)(i0 + r) * 32 + c);
        cp16(su + KV1_OFF + 4608 + r * 36 + c, Ql_g + (size_t)(i0 + r) * 32 + c);
    }
    cp_commit();
    cp_wait<0>();
    __syncthreads();

    const int rw0 = w * 16 + g;
    const int rw1 = rw0 + 8;

    uint32_t qh[4][4], ql[4][4];
#pragma unroll
    for (int ks = 0; ks < 4; ks++) {
        const int kp = ks * 8 + t;
        qh[ks][0] = su[KV1_OFF + rw0 * 36 + kp];
        qh[ks][1] = su[KV1_OFF + rw1 * 36 + kp];
        qh[ks][2] = su[KV1_OFF + rw0 * 36 + kp + 4];
        qh[ks][3] = su[KV1_OFF + rw1 * 36 + kp + 4];
        ql[ks][0] = su[KV1_OFF + 4608 + rw0 * 36 + kp];
        ql[ks][1] = su[KV1_OFF + 4608 + rw1 * 36 + kp];
        ql[ks][2] = su[KV1_OFF + 4608 + rw0 * 36 + kp + 4];
        ql[ks][3] = su[KV1_OFF + 4608 + rw1 * 36 + kp + 4];
    }
    __syncthreads();   // everyone done reading Q before KV1 is reused

    const int i_r0 = i0 + w * 16 + g;
    const int i_r1 = i_r0 + 8;
    const int warp_lo = i0 + w * 16;
    const int warp_hi = warp_lo + 15;

    // p = exp2(qk*C1 + (j-i)*C2 - C3) = exp(qk/8 - (i-j) - 4)
    const float C1 = 0.18033688011f;   // 0.125 * log2(e)
    const float C2 = 1.44269504089f;   // log2(e)
    const float C3 = 5.77078016356f;   // 4 * log2(e)

    float l0r = 0.f, l1r = 0.f;
    float o[8][4];
#pragma unroll
    for (int nt = 0; nt < 8; nt++)
#pragma unroll
        for (int q = 0; q < 4; q++) o[nt][q] = 0.f;

    auto load_kv = [&](int kb, int j0) {
#pragma unroll
        for (int rep = 0; rep < 2; rep++) {
            int idx = tid + rep * 256;
            int r = idx >> 3;
            int c = (idx & 7) * 4;
            cp16(su + kb + r * 36 + c,        Kh_g + (size_t)(j0 + r) * 32 + c);
            cp16(su + kb + 2304 + r * 36 + c, Kl_g + (size_t)(j0 + r) * 32 + c);
        }
#pragma unroll
        for (int rep = 0; rep < 2; rep++) {
            int idx = tid + rep * 256;
            int p = idx >> 4;
            int c = (idx & 15) * 4;
            cp16(su + kb + 4608 + p * 72 + c,
                 Vph_g + ((size_t)(j0 >> 1) + p) * HD + c);
            cp16(su + kb + 6912 + p * 72 + c,
                 Vpl_g + ((size_t)(j0 >> 1) + p) * HD + c);
        }
        cp_commit();
    };

    const int j0_lo = (i0 >= 64) ? (i0 - 64) : 0;
    const int nT    = (i0 + 64 - j0_lo) / 64 + 1;   // 2 or 3 tiles

    load_kv(KV0_OFF, j0_lo);   // prefetch first tile

    for (int jt = 0; jt < nT; jt++) {
        const int j0 = j0_lo + jt * 64;
        const int kb = (jt & 1) ? KV1_OFF : KV0_OFF;
        const int ko = (jt & 1) ? KV0_OFF : KV1_OFF;

        __syncthreads();   // all warps done computing from buffer ko
        if (jt + 1 < nT) load_kv(ko, j0 + 64);
        else             cp_commit();
        cp_wait<1>();
        __syncthreads();   // publish buffer kb

        // per-warp skip: fully above diagonal OR fully beyond decay reach
        if (j0 > warp_hi || j0 < warp_lo - 127) continue;

        const uint32_t* Kh = su + kb;
        const uint32_t* Kl = su + kb + 2304;
        const uint32_t* Vh = su + kb + 4608;
        const uint32_t* Vl = su + kb + 6912;

        // ---- S = Q @ K^T (Q from registers) ----
        float s[8][4];
#pragma unroll
        for (int nt = 0; nt < 8; nt++)
#pragma unroll
            for (int q = 0; q < 4; q++) s[nt][q] = 0.f;

#pragma unroll
        for (int ks = 0; ks < 4; ks++) {
            const int kp = ks * 8 + t;
#pragma unroll
            for (int nt = 0; nt < 8; nt++) {
                int rn = nt * 8 + g;
                uint32_t b0h = Kh[rn * 36 + kp],     b0l = Kl[rn * 36 + kp];
                uint32_t b1h = Kh[rn * 36 + kp + 4], b1l = Kl[rn * 36 + kp + 4];
                mma16(s[nt], qh[ks][0], qh[ks][1], qh[ks][2], qh[ks][3], b0h, b1h);
                mma16(s[nt], qh[ks][0], qh[ks][1], qh[ks][2], qh[ks][3], b0l, b1l);
                mma16(s[nt], ql[ks][0], ql[ks][1], ql[ks][2], ql[ks][3], b0h, b1h);
            }
        }

        // ---- mask + decay + exp (fixed max) ----
#pragma unroll
        for (int nt = 0; nt < 8; nt++) {
            int jb = j0 + nt * 8 + 2 * t;
            float d0 = fmaf((float)(jb - i_r0), C2, -C3);
            float d1 = fmaf((float)(jb - i_r1), C2, -C3);
            float p0 = (jb     <= i_r0) ? exp2f(fmaf(s[nt][0], C1, d0))      : 0.f;
            float p1 = (jb + 1 <= i_r0) ? exp2f(fmaf(s[nt][1], C1, d0 + C2)) : 0.f;
            float p2 = (jb     <= i_r1) ? exp2f(fmaf(s[nt][2], C1, d1))      : 0.f;
            float p3 = (jb + 1 <= i_r1) ? exp2f(fmaf(s[nt][3], C1, d1 + C2)) : 0.f;
            l0r += p0 + p1;
            l1r += p2 + p3;
            uint32_t hh, ll;
            split2(p0, p1, hh, ll);
            Ph[rw0 * 36 + nt * 4 + t] = hh;
            Pl[rw0 * 36 + nt * 4 + t] = ll;
            split2(p2, p3, hh, ll);
            Ph[rw1 * 36 + nt * 4 + t] = hh;
            Pl[rw1 * 36 + nt * 4 + t] = ll;
        }

        __syncwarp();

        // ---- O += P @ V ----
#pragma unroll
        for (int ks = 0; ks < 4; ks++) {
            const int kp = ks * 8 + t;
            uint32_t a0h = Ph[rw0 * 36 + kp],     a0l = Pl[rw0 * 36 + kp];
            uint32_t a1h = Ph[rw1 * 36 + kp],     a1l = Pl[rw1 * 36 + kp];
            uint32_t a2h = Ph[rw0 * 36 + kp + 4], a2l = Pl[rw0 * 36 + kp + 4];
            uint32_t a3h = Ph[rw1 * 36 + kp + 4], a3l = Pl[rw1 * 36 + kp + 4];
#pragma unroll
            for (int nt = 0; nt < 8; nt++) {
                int n = nt * 8 + g;
                uint32_t b0h = Vh[kp * 72 + n],       b0l = Vl[kp * 72 + n];
                uint32_t b1h = Vh[(kp + 4) * 72 + n], b1l = Vl[(kp + 4) * 72 + n];
                mma16(o[nt], a0h, a1h, a2h, a3h, b0h, b1h);
                mma16(o[nt], a0h, a1h, a2h, a3h, b0l, b1l);
                mma16(o[nt], a0l, a1l, a2l, a3l, b0h, b1h);
            }
        }
        __syncwarp();
    }

    // ---- final row-sum reduce + normalize + split + store packed ----
    l0r += __shfl_xor_sync(0xffffffffu, l0r, 1);
    l0r += __shfl_xor_sync(0xffffffffu, l0r, 2);
    l1r += __shfl_xor_sync(0xffffffffu, l1r, 1);
    l1r += __shfl_xor_sync(0xffffffffu, l1r, 2);

    const int b = bh >> 4;
    const int hh_ = bh & 15;
    const float inv0 = 1.0f / l0r;
    const float inv1 = 1.0f / l1r;
    size_t pb0 = ((size_t)b * T_SEQ + i_r0) * KPAIRS + hh_ * 32;
    size_t pb1 = ((size_t)b * T_SEQ + i_r1) * KPAIRS + hh_ * 32;
#pragma unroll
    for (int nt = 0; nt < 8; nt++) {
        int p = nt * 4 + t;
        uint32_t uh, ul;
        split2(o[nt][0] * inv0, o[nt][1] * inv0, uh, ul);
        g_atth[pb0 + p] = uh;
        g_attl[pb0 + p] = ul;
        split2(o[nt][2] * inv1, o[nt][3] * inv1, uh, ul);
        g_atth[pb1 + p] = uh;
        g_attl[pb1 + p] = ul;
    }
}

// ---------------------------------------------------------------------------
// Launch
// ---------------------------------------------------------------------------
extern "C" void kernel_launch(void* const* d_in, const int* in_sizes, int n_in,
                              void* d_out, int out_size)
{
    const float* x  = (const float*)d_in[0];
    const float* Wq = (const float*)d_in[1];
    const float* bq = (const float*)d_in[2];
    const float* Wk = (const float*)d_in[3];
    const float* bk = (const float*)d_in[4];
    const float* Wv = (const float*)d_in[5];
    const float* bv = (const float*)d_in[6];
    const float* Wo = (const float*)d_in[7];
    const float* bo = (const float*)d_in[8];
    float* out = (float*)d_out;

    cudaFuncSetAttribute(qkv_kernel,
                         cudaFuncAttributeMaxDynamicSharedMemorySize, GEMM_SMEM_BYTES);
    cudaFuncSetAttribute(out_kernel,
                         cudaFuncAttributeMaxDynamicSharedMemorySize, GEMM_SMEM_BYTES);
    cudaFuncSetAttribute(attn_kernel,
                         cudaFuncAttributeMaxDynamicSharedMemorySize, ATT_SMEM_BYTES);

    // pre-split X and all weights to bf16 hi/lo planes (float4 per thread)
    dim3 gp(1024, 8);
    prep_kernel<<<gp, 256>>>(x, Wq, Wk, Wv, Wo);

    // QKV projections (grid-launched, z = {Q,K,V})
    dim3 gq(D_MODEL / 128, M_ROWS / 128, 3);
    qkv_kernel<<<gq, 256, GEMM_SMEM_BYTES>>>(bq, bk, bv);

    // attention (windowed + double-buffered + per-warp skip)
    dim3 ga(T_SEQ / 128, BATCH * N_HEADS);
    attn_kernel<<<ga, 256, ATT_SMEM_BYTES>>>();

    // output projection
    dim3 go(D_MODEL / 128, M_ROWS / 128);
    out_kernel<<<go, 256, GEMM_SMEM_BYTES>>>(bo, out);
}

// round 16
// speedup vs baseline: 1.6759x; 1.0205x over previous
#include <cuda_runtime.h>
#include <cuda_bf16.h>
#include <cstdint>

#define D_MODEL 1024
#define N_HEADS 16
#define HD      64
#define T_SEQ   2048
#define BATCH   2
#define M_ROWS  (BATCH * T_SEQ)   // 4096
#define KPAIRS  (D_MODEL / 2)     // 512 pairs per row

// ---------------------------------------------------------------------------
// Scratch (device globals; no allocation allowed)
// ---------------------------------------------------------------------------
__device__ uint32_t g_Xh[M_ROWS * KPAIRS];          // X pre-split hi plane
__device__ uint32_t g_Xl[M_ROWS * KPAIRS];
__device__ uint32_t g_Wh[4 * D_MODEL * KPAIRS];     // Wq,Wk,Wv,Wo hi planes
__device__ uint32_t g_Wl[4 * D_MODEL * KPAIRS];
__device__ uint32_t g_Qh[BATCH * N_HEADS * T_SEQ * (HD / 2)];  // [b,h,t,dpair]
__device__ uint32_t g_Ql[BATCH * N_HEADS * T_SEQ * (HD / 2)];
__device__ uint32_t g_Kh[BATCH * N_HEADS * T_SEQ * (HD / 2)];
__device__ uint32_t g_Kl[BATCH * N_HEADS * T_SEQ * (HD / 2)];
// V packed pair-of-rows: [b,h,tpair,d] u32 = bf16x2(row 2p, row 2p+1) at col d
__device__ uint32_t g_Vph[BATCH * N_HEADS * (T_SEQ / 2) * HD];
__device__ uint32_t g_Vpl[BATCH * N_HEADS * (T_SEQ / 2) * HD];
__device__ uint32_t g_atth[M_ROWS * KPAIRS];        // attention output packed
__device__ uint32_t g_attl[M_ROWS * KPAIRS];

// ---------------------------------------------------------------------------
// helpers
// ---------------------------------------------------------------------------
__device__ __forceinline__ void split2(float x0, float x1, uint32_t& h, uint32_t& l)
{
    __nv_bfloat162 hh = __floats2bfloat162_rn(x0, x1);
    float2 hf = __bfloat1622float2(hh);
    __nv_bfloat162 ll = __floats2bfloat162_rn(x0 - hf.x, x1 - hf.y);
    h = *reinterpret_cast<uint32_t*>(&hh);
    l = *reinterpret_cast<uint32_t*>(&ll);
}

__device__ __forceinline__ void mma16(float* c,
                                      uint32_t a0, uint32_t a1, uint32_t a2, uint32_t a3,
                                      uint32_t b0, uint32_t b1)
{
    asm volatile(
        "mma.sync.aligned.m16n8k16.row.col.f32.bf16.bf16.f32 "
        "{%0,%1,%2,%3}, {%4,%5,%6,%7}, {%8,%9}, {%0,%1,%2,%3};"
        : "+f"(c[0]), "+f"(c[1]), "+f"(c[2]), "+f"(c[3])
        : "r"(a0), "r"(a1), "r"(a2), "r"(a3), "r"(b0), "r"(b1));
}

__device__ __forceinline__ void ldsm4(uint32_t& r0, uint32_t& r1,
                                      uint32_t& r2, uint32_t& r3, uint32_t addr)
{
    asm volatile("ldmatrix.sync.aligned.m8n8.x4.shared.b16 {%0,%1,%2,%3}, [%4];"
                 : "=r"(r0), "=r"(r1), "=r"(r2), "=r"(r3) : "r"(addr));
}

__device__ __forceinline__ void cp16(void* dst_smem, const void* src)
{
    uint32_t s = (uint32_t)__cvta_generic_to_shared(dst_smem);
    asm volatile("cp.async.cg.shared.global [%0], [%1], 16;\n" :: "r"(s), "l"(src));
}
__device__ __forceinline__ void cp_commit()
{
    asm volatile("cp.async.commit_group;\n" ::);
}
template<int N>
__device__ __forceinline__ void cp_wait()
{
    asm volatile("cp.async.wait_group %0;\n" :: "n"(N));
}

// ---------------------------------------------------------------------------
// Prep kernel: split X and Wq/Wk/Wv/Wo into bf16x2 hi/lo planes (once).
// float4 per thread (2 pairs).
// ---------------------------------------------------------------------------
__global__ void __launch_bounds__(256)
prep_kernel(const float* __restrict__ X,
            const float* __restrict__ Wq, const float* __restrict__ Wk,
            const float* __restrict__ Wv, const float* __restrict__ Wo)
{
    const int seg = blockIdx.y;
    const int idx = blockIdx.x * 256 + threadIdx.x;   // float4 index in segment
    const float* src;
    uint32_t *dh, *dl;
    if (seg < 4) {
        src = X + (size_t)seg * 1048576;
        dh = g_Xh + (size_t)seg * 524288;
        dl = g_Xl + (size_t)seg * 524288;
    } else {
        const float* ws[4] = {Wq, Wk, Wv, Wo};
        src = ws[seg - 4];
        dh = g_Wh + (size_t)(seg - 4) * 524288;
        dl = g_Wl + (size_t)(seg - 4) * 524288;
    }
    float4 v = *(const float4*)(src + 4 * (size_t)idx);
    uint32_t h0, l0, h1, l1;
    split2(v.x, v.y, h0, l0);
    split2(v.z, v.w, h1, l1);
    *(uint2*)(dh + 2 * (size_t)idx) = make_uint2(h0, h1);
    *(uint2*)(dl + 2 * (size_t)idx) = make_uint2(l0, l1);
}

// ---------------------------------------------------------------------------
// 3xBF16 mma.sync GEMM tile: Y[128,128 @ (m0,n0)] = X @ W^T + bias
// 128 threads, 4 warps (2x2), warp tile 64x64 (mt=4, nt=8):
// MMA:LDSM ratio 6:1 (vs 4:1 with 64x32 tiles), 192-MMA runs per warp
// per period. XOR-swizzled smem, NBUF=3, 1 barrier per period,
// prefetch distance 2. Same accumulation order as the 8-warp version.
// Output modes: 0 = packed Q/K planes, 1 = V packed pair-of-rows planes,
//               2 = float row-major (final out).
// ---------------------------------------------------------------------------
#define RSU      16
#define PLANE_U  (128 * RSU)
#define BUF_U    (4 * PLANE_U)
#define NBUF     3
#define NPER     (D_MODEL / 32)
#define GEMM_SMEM_BYTES (NBUF * BUF_U * 4)   // 98304

__device__ __forceinline__ uint32_t sw_off(int row, int chunk)
{
    return (uint32_t)(row * RSU + ((chunk ^ ((row >> 1) & 3)) << 2));
}

__device__ __forceinline__ void gemm_tile(int m0, int n0,
                                          const uint32_t* __restrict__ Xh,
                                          const uint32_t* __restrict__ Xl,
                                          const uint32_t* __restrict__ Wh,
                                          const uint32_t* __restrict__ Wl,
                                          const float* __restrict__ bias,
                                          uint32_t* __restrict__ Yh,
                                          uint32_t* __restrict__ Yl,
                                          float* __restrict__ Yf,
                                          int mode)
{
    extern __shared__ uint32_t smem[];
    const uint32_t sbase = (uint32_t)__cvta_generic_to_shared(smem);

    const int tid  = threadIdx.x;
    const int lane = tid & 31;
    const int wid  = tid >> 5;       // 0..3
    const int wm   = wid >> 1;       // 0..1 (64 rows each)
    const int wn   = wid & 1;        // 0..1 (64 cols each)
    const int g    = lane >> 2;
    const int t    = lane & 3;

    // loader: per plane 512 chunks of 16B, 4 per thread
    const int lrow = tid >> 2;       // 0..31 (+32/64/96)
    const int lcix = tid & 3;
    uint32_t ldst[4];
#pragma unroll
    for (int r = 0; r < 4; r++) ldst[r] = sw_off(lrow + 32 * r, lcix);

    const uint32_t* srcs[4] = {
        Xh + (size_t)m0 * KPAIRS, Xl + (size_t)m0 * KPAIRS,
        Wh + (size_t)n0 * KPAIRS, Wl + (size_t)n0 * KPAIRS };

    // ldmatrix per-lane bases
    const int a_row = (lane & 7) + ((lane >> 3) & 1) * 8;
    const int hiA   = lane >> 4;
    int baseA[4], swA[4];
#pragma unroll
    for (int mt = 0; mt < 4; mt++) {
        int rg = wm * 64 + mt * 16 + a_row;
        baseA[mt] = rg * RSU;
        swA[mt]   = (rg >> 1) & 3;
    }
    const int b_row = (lane & 7) + ((lane >> 4) ? 8 : 0);
    const int hiB   = (lane >> 3) & 1;
    int baseB[4], swB[4];
#pragma unroll
    for (int bq = 0; bq < 4; bq++) {
        int rg = wn * 64 + bq * 16 + b_row;
        baseB[bq] = rg * RSU;
        swB[bq]   = (rg >> 1) & 3;
    }

    float acc[4][8][4];
#pragma unroll
    for (int i = 0; i < 4; i++)
#pragma unroll
        for (int j = 0; j < 8; j++)
#pragma unroll
            for (int q = 0; q < 4; q++) acc[i][j][q] = 0.f;

    auto load_buf = [&](int b, int p) {
        uint32_t* base = smem + b * BUF_U;
        const int koff = p * 16;
#pragma unroll
        for (int pi = 0; pi < 4; pi++) {
            const uint32_t* sp = srcs[pi] + koff + lcix * 4;
            uint32_t* dp = base + pi * PLANE_U;
#pragma unroll
            for (int r = 0; r < 4; r++)
                cp16(dp + ldst[r], sp + (size_t)(lrow + 32 * r) * KPAIRS);
        }
        cp_commit();
    };

    load_buf(0, 0);
    load_buf(1, 1);

    for (int p = 0; p < NPER; p++) {
        cp_wait<1>();
        __syncthreads();
        if (p + 2 < NPER) load_buf((p + 2) % 3, p + 2);
        else              cp_commit();

        const uint32_t stb = sbase + (uint32_t)((p % 3) * BUF_U) * 4;

#pragma unroll
        for (int ks = 0; ks < 2; ks++) {
            uint32_t Ah[4][4], Al[4][4];
#pragma unroll
            for (int mt = 0; mt < 4; mt++) {
                uint32_t offA = (uint32_t)(baseA[mt] +
                                (((2 * ks + hiA) ^ swA[mt]) << 2)) * 4;
                ldsm4(Ah[mt][0], Ah[mt][1], Ah[mt][2], Ah[mt][3], stb + offA);
                ldsm4(Al[mt][0], Al[mt][1], Al[mt][2], Al[mt][3],
                      stb + PLANE_U * 4 + offA);
            }
            uint32_t Bh[8][2], Bl[8][2];
#pragma unroll
            for (int bq = 0; bq < 4; bq++) {
                uint32_t offB = (uint32_t)(baseB[bq] +
                                (((2 * ks + hiB) ^ swB[bq]) << 2)) * 4;
                ldsm4(Bh[2 * bq][0], Bh[2 * bq][1],
                      Bh[2 * bq + 1][0], Bh[2 * bq + 1][1],
                      stb + 2 * PLANE_U * 4 + offB);
                ldsm4(Bl[2 * bq][0], Bl[2 * bq][1],
                      Bl[2 * bq + 1][0], Bl[2 * bq + 1][1],
                      stb + 3 * PLANE_U * 4 + offB);
            }

#pragma unroll
            for (int mt = 0; mt < 4; mt++)
#pragma unroll
                for (int nt = 0; nt < 8; nt++)
                    mma16(acc[mt][nt], Ah[mt][0], Ah[mt][1], Ah[mt][2], Ah[mt][3],
                          Bh[nt][0], Bh[nt][1]);
#pragma unroll
            for (int mt = 0; mt < 4; mt++)
#pragma unroll
                for (int nt = 0; nt < 8; nt++)
                    mma16(acc[mt][nt], Ah[mt][0], Ah[mt][1], Ah[mt][2], Ah[mt][3],
                          Bl[nt][0], Bl[nt][1]);
#pragma unroll
            for (int mt = 0; mt < 4; mt++)
#pragma unroll
                for (int nt = 0; nt < 8; nt++)
                    mma16(acc[mt][nt], Al[mt][0], Al[mt][1], Al[mt][2], Al[mt][3],
                          Bh[nt][0], Bh[nt][1]);
        }
    }

    // epilogue
#pragma unroll
    for (int mt = 0; mt < 4; mt++) {
        int rm = m0 + wm * 64 + mt * 16 + g;
#pragma unroll
        for (int nt = 0; nt < 8; nt++) {
            int cn = n0 + wn * 64 + nt * 8 + 2 * t;
            float bb0 = bias[cn];
            float bb1 = bias[cn + 1];
            float2 v0 = make_float2(acc[mt][nt][0] + bb0, acc[mt][nt][1] + bb1);
            float2 v1 = make_float2(acc[mt][nt][2] + bb0, acc[mt][nt][3] + bb1);
            if (mode == 0) {
                int head = cn >> 6;
                int pr   = (cn & 63) >> 1;
#pragma unroll
                for (int rr = 0; rr < 2; rr++) {
                    int row = rm + rr * 8;
                    float2 v = rr ? v1 : v0;
                    int bb = row >> 11;
                    int tt = row & (T_SEQ - 1);
                    size_t base = (((size_t)bb * N_HEADS + head) * T_SEQ + tt) * (HD / 2) + pr;
                    uint32_t hh, ll;
                    split2(v.x, v.y, hh, ll);
                    Yh[base] = hh;
                    Yl[base] = ll;
                }
            } else if (mode == 1) {
                int head = cn >> 6;
                int d    = cn & 63;
                float p0x = __shfl_down_sync(0xffffffffu, v0.x, 4);
                float p0y = __shfl_down_sync(0xffffffffu, v0.y, 4);
                float p1x = __shfl_down_sync(0xffffffffu, v1.x, 4);
                float p1y = __shfl_down_sync(0xffffffffu, v1.y, 4);
                if ((g & 1) == 0) {
                    int bb = rm >> 11;
                    int tt = rm & (T_SEQ - 1);
                    size_t idx0 = (((size_t)bb * N_HEADS + head) * (T_SEQ / 2)
                                   + (tt >> 1)) * HD + d;
                    size_t idx1 = idx0 + 4 * HD;
                    uint32_t hh, ll;
                    split2(v0.x, p0x, hh, ll); Yh[idx0] = hh;     Yl[idx0] = ll;
                    split2(v0.y, p0y, hh, ll); Yh[idx0 + 1] = hh; Yl[idx0 + 1] = ll;
                    split2(v1.x, p1x, hh, ll); Yh[idx1] = hh;     Yl[idx1] = ll;
                    split2(v1.y, p1y, hh, ll); Yh[idx1 + 1] = hh; Yl[idx1 + 1] = ll;
                }
            } else {
                *(float2*)(Yf + (size_t)rm * D_MODEL + cn) = v0;
                *(float2*)(Yf + (size_t)(rm + 8) * D_MODEL + cn) = v1;
            }
        }
    }
}

// grid-launched qkv: z = {Q,K,V}
__global__ void __launch_bounds__(128, 2)
qkv_kernel(const float* __restrict__ bq, const float* __restrict__ bk,
           const float* __restrict__ bv)
{
    const int z  = blockIdx.z;
    const int m0 = blockIdx.y * 128;
    const int n0 = blockIdx.x * 128;
    const float* bias = (z == 0) ? bq : (z == 1) ? bk : bv;
    const uint32_t* Wh = g_Wh + (size_t)z * D_MODEL * KPAIRS;
    const uint32_t* Wl = g_Wl + (size_t)z * D_MODEL * KPAIRS;
    if (z == 0)
        gemm_tile(m0, n0, g_Xh, g_Xl, Wh, Wl, bias, g_Qh, g_Ql, nullptr, 0);
    else if (z == 1)
        gemm_tile(m0, n0, g_Xh, g_Xl, Wh, Wl, bias, g_Kh, g_Kl, nullptr, 0);
    else
        gemm_tile(m0, n0, g_Xh, g_Xl, Wh, Wl, bias, g_Vph, g_Vpl, nullptr, 1);
}

__global__ void __launch_bounds__(128, 2)
out_kernel(const float* __restrict__ bo, float* __restrict__ out)
{
    gemm_tile(blockIdx.y * 128, blockIdx.x * 128,
              g_atth, g_attl,
              g_Wh + (size_t)3 * D_MODEL * KPAIRS,
              g_Wl + (size_t)3 * D_MODEL * KPAIRS,
              bo, nullptr, nullptr, out, 2);
}

// ---------------------------------------------------------------------------
// Tensor-core flash attention (frozen from R15): 3xBF16 mma.sync,
// FIXED-MAX softmax, WINDOWED kv sweep, Q-in-registers, double-buffered
// K/V prefetch, per-warp tile skip.
// ---------------------------------------------------------------------------
#define P_OFF   0        // Ph [128][36], Pl at +4608
#define KV0_OFF 9216     // per KV buf: Kh +0, Kl +2304, Vh +4608, Vl +6912
#define KV1_OFF 18432
#define ATT_U32 27648
#define ATT_SMEM_BYTES (ATT_U32 * 4)   // 110592

__global__ void __launch_bounds__(256, 2) attn_kernel()
{
    extern __shared__ uint32_t su[];
    uint32_t* Ph = su + P_OFF;
    uint32_t* Pl = su + P_OFF + 4608;

    const int tid  = threadIdx.x;
    const int lane = tid & 31;
    const int w    = tid >> 5;
    const int g    = lane >> 2;
    const int t    = lane & 3;

    const int bh = blockIdx.y;
    const int i0 = (int)blockIdx.x * 128;

    const uint32_t* Qh_g = g_Qh + (size_t)bh * T_SEQ * (HD / 2);
    const uint32_t* Ql_g = g_Ql + (size_t)bh * T_SEQ * (HD / 2);
    const uint32_t* Kh_g = g_Kh + (size_t)bh * T_SEQ * (HD / 2);
    const uint32_t* Kl_g = g_Kl + (size_t)bh * T_SEQ * (HD / 2);
    const uint32_t* Vph_g = g_Vph + (size_t)bh * (T_SEQ / 2) * HD;
    const uint32_t* Vpl_g = g_Vpl + (size_t)bh * (T_SEQ / 2) * HD;

    // ---- stage Q into KV1 region, then lift fragments to registers ----
#pragma unroll
    for (int rep = 0; rep < 4; rep++) {
        int idx = tid + rep * 256;
        int r = idx >> 3;
        int c = (idx & 7) * 4;
        cp16(su + KV1_OFF + r * 36 + c,        Qh_g + (size_t)(i0 + r) * 32 + c);
        cp16(su + KV1_OFF + 4608 + r * 36 + c, Ql_g + (size_t)(i0 + r) * 32 + c);
    }
    cp_commit();
    cp_wait<0>();
    __syncthreads();

    const int rw0 = w * 16 + g;
    const int rw1 = rw0 + 8;

    uint32_t qh[4][4], ql[4][4];
#pragma unroll
    for (int ks = 0; ks < 4; ks++) {
        const int kp = ks * 8 + t;
        qh[ks][0] = su[KV1_OFF + rw0 * 36 + kp];
        qh[ks][1] = su[KV1_OFF + rw1 * 36 + kp];
        qh[ks][2] = su[KV1_OFF + rw0 * 36 + kp + 4];
        qh[ks][3] = su[KV1_OFF + rw1 * 36 + kp + 4];
        ql[ks][0] = su[KV1_OFF + 4608 + rw0 * 36 + kp];
        ql[ks][1] = su[KV1_OFF + 4608 + rw1 * 36 + kp];
        ql[ks][2] = su[KV1_OFF + 4608 + rw0 * 36 + kp + 4];
        ql[ks][3] = su[KV1_OFF + 4608 + rw1 * 36 + kp + 4];
    }
    __syncthreads();   // everyone done reading Q before KV1 is reused

    const int i_r0 = i0 + w * 16 + g;
    const int i_r1 = i_r0 + 8;
    const int warp_lo = i0 + w * 16;
    const int warp_hi = warp_lo + 15;

    const float C1 = 0.18033688011f;   // 0.125 * log2(e)
    const float C2 = 1.44269504089f;   // log2(e)
    const float C3 = 5.77078016356f;   // 4 * log2(e)

    float l0r = 0.f, l1r = 0.f;
    float o[8][4];
#pragma unroll
    for (int nt = 0; nt < 8; nt++)
#pragma unroll
        for (int q = 0; q < 4; q++) o[nt][q] = 0.f;

    auto load_kv = [&](int kb, int j0) {
#pragma unroll
        for (int rep = 0; rep < 2; rep++) {
            int idx = tid + rep * 256;
            int r = idx >> 3;
            int c = (idx & 7) * 4;
            cp16(su + kb + r * 36 + c,        Kh_g + (size_t)(j0 + r) * 32 + c);
            cp16(su + kb + 2304 + r * 36 + c, Kl_g + (size_t)(j0 + r) * 32 + c);
        }
#pragma unroll
        for (int rep = 0; rep < 2; rep++) {
            int idx = tid + rep * 256;
            int p = idx >> 4;
            int c = (idx & 15) * 4;
            cp16(su + kb + 4608 + p * 72 + c,
                 Vph_g + ((size_t)(j0 >> 1) + p) * HD + c);
            cp16(su + kb + 6912 + p * 72 + c,
                 Vpl_g + ((size_t)(j0 >> 1) + p) * HD + c);
        }
        cp_commit();
    };

    const int j0_lo = (i0 >= 64) ? (i0 - 64) : 0;
    const int nT    = (i0 + 64 - j0_lo) / 64 + 1;   // 2 or 3 tiles

    load_kv(KV0_OFF, j0_lo);

    for (int jt = 0; jt < nT; jt++) {
        const int j0 = j0_lo + jt * 64;
        const int kb = (jt & 1) ? KV1_OFF : KV0_OFF;
        const int ko = (jt & 1) ? KV0_OFF : KV1_OFF;

        __syncthreads();
        if (jt + 1 < nT) load_kv(ko, j0 + 64);
        else             cp_commit();
        cp_wait<1>();
        __syncthreads();

        if (j0 > warp_hi || j0 < warp_lo - 127) continue;

        const uint32_t* Kh = su + kb;
        const uint32_t* Kl = su + kb + 2304;
        const uint32_t* Vh = su + kb + 4608;
        const uint32_t* Vl = su + kb + 6912;

        float s[8][4];
#pragma unroll
        for (int nt = 0; nt < 8; nt++)
#pragma unroll
            for (int q = 0; q < 4; q++) s[nt][q] = 0.f;

#pragma unroll
        for (int ks = 0; ks < 4; ks++) {
            const int kp = ks * 8 + t;
#pragma unroll
            for (int nt = 0; nt < 8; nt++) {
                int rn = nt * 8 + g;
                uint32_t b0h = Kh[rn * 36 + kp],     b0l = Kl[rn * 36 + kp];
                uint32_t b1h = Kh[rn * 36 + kp + 4], b1l = Kl[rn * 36 + kp + 4];
                mma16(s[nt], qh[ks][0], qh[ks][1], qh[ks][2], qh[ks][3], b0h, b1h);
                mma16(s[nt], qh[ks][0], qh[ks][1], qh[ks][2], qh[ks][3], b0l, b1l);
                mma16(s[nt], ql[ks][0], ql[ks][1], ql[ks][2], ql[ks][3], b0h, b1h);
            }
        }

#pragma unroll
        for (int nt = 0; nt < 8; nt++) {
            int jb = j0 + nt * 8 + 2 * t;
            float d0 = fmaf((float)(jb - i_r0), C2, -C3);
            float d1 = fmaf((float)(jb - i_r1), C2, -C3);
            float p0 = (jb     <= i_r0) ? exp2f(fmaf(s[nt][0], C1, d0))      : 0.f;
            float p1 = (jb + 1 <= i_r0) ? exp2f(fmaf(s[nt][1], C1, d0 + C2)) : 0.f;
            float p2 = (jb     <= i_r1) ? exp2f(fmaf(s[nt][2], C1, d1))      : 0.f;
            float p3 = (jb + 1 <= i_r1) ? exp2f(fmaf(s[nt][3], C1, d1 + C2)) : 0.f;
            l0r += p0 + p1;
            l1r += p2 + p3;
            uint32_t hh, ll;
            split2(p0, p1, hh, ll);
            Ph[rw0 * 36 + nt * 4 + t] = hh;
            Pl[rw0 * 36 + nt * 4 + t] = ll;
            split2(p2, p3, hh, ll);
            Ph[rw1 * 36 + nt * 4 + t] = hh;
            Pl[rw1 * 36 + nt * 4 + t] = ll;
        }

        __syncwarp();

#pragma unroll
        for (int ks = 0; ks < 4; ks++) {
            const int kp = ks * 8 + t;
            uint32_t a0h = Ph[rw0 * 36 + kp],     a0l = Pl[rw0 * 36 + kp];
            uint32_t a1h = Ph[rw1 * 36 + kp],     a1l = Pl[rw1 * 36 + kp];
            uint32_t a2h = Ph[rw0 * 36 + kp + 4], a2l = Pl[rw0 * 36 + kp + 4];
            uint32_t a3h = Ph[rw1 * 36 + kp + 4], a3l = Pl[rw1 * 36 + kp + 4];
#pragma unroll
            for (int nt = 0; nt < 8; nt++) {
                int n = nt * 8 + g;
                uint32_t b0h = Vh[kp * 72 + n],       b0l = Vl[kp * 72 + n];
                uint32_t b1h = Vh[(kp + 4) * 72 + n], b1l = Vl[(kp + 4) * 72 + n];
                mma16(o[nt], a0h, a1h, a2h, a3h, b0h, b1h);
                mma16(o[nt], a0h, a1h, a2h, a3h, b0l, b1l);
                mma16(o[nt], a0l, a1l, a2l, a3l, b0h, b1h);
            }
        }
        __syncwarp();
    }

    l0r += __shfl_xor_sync(0xffffffffu, l0r, 1);
    l0r += __shfl_xor_sync(0xffffffffu, l0r, 2);
    l1r += __shfl_xor_sync(0xffffffffu, l1r, 1);
    l1r += __shfl_xor_sync(0xffffffffu, l1r, 2);

    const int b = bh >> 4;
    const int hh_ = bh & 15;
    const float inv0 = 1.0f / l0r;
    const float inv1 = 1.0f / l1r;
    size_t pb0 = ((size_t)b * T_SEQ + i_r0) * KPAIRS + hh_ * 32;
    size_t pb1 = ((size_t)b * T_SEQ + i_r1) * KPAIRS + hh_ * 32;
#pragma unroll
    for (int nt = 0; nt < 8; nt++) {
        int p = nt * 4 + t;
        uint32_t uh, ul;
        split2(o[nt][0] * inv0, o[nt][1] * inv0, uh, ul);
        g_atth[pb0 + p] = uh;
        g_attl[pb0 + p] = ul;
        split2(o[nt][2] * inv1, o[nt][3] * inv1, uh, ul);
        g_atth[pb1 + p] = uh;
        g_attl[pb1 + p] = ul;
    }
}

// ---------------------------------------------------------------------------
// Launch
// ---------------------------------------------------------------------------
extern "C" void kernel_launch(void* const* d_in, const int* in_sizes, int n_in,
                              void* d_out, int out_size)
{
    const float* x  = (const float*)d_in[0];
    const float* Wq = (const float*)d_in[1];
    const float* bq = (const float*)d_in[2];
    const float* Wk = (const float*)d_in[3];
    const float* bk = (const float*)d_in[4];
    const float* Wv = (const float*)d_in[5];
    const float* bv = (const float*)d_in[6];
    const float* Wo = (const float*)d_in[7];
    const float* bo = (const float*)d_in[8];
    float* out = (float*)d_out;

    cudaFuncSetAttribute(qkv_kernel,
                         cudaFuncAttributeMaxDynamicSharedMemorySize, GEMM_SMEM_BYTES);
    cudaFuncSetAttribute(out_kernel,
                         cudaFuncAttributeMaxDynamicSharedMemorySize, GEMM_SMEM_BYTES);
    cudaFuncSetAttribute(attn_kernel,
                         cudaFuncAttributeMaxDynamicSharedMemorySize, ATT_SMEM_BYTES);

    // pre-split X and all weights to bf16 hi/lo planes (float4 per thread)
    dim3 gp(1024, 8);
    prep_kernel<<<gp, 256>>>(x, Wq, Wk, Wv, Wo);

    // QKV projections (grid-launched, z = {Q,K,V}), 128-thread blocks
    dim3 gq(D_MODEL / 128, M_ROWS / 128, 3);
    qkv_kernel<<<gq, 128, GEMM_SMEM_BYTES>>>(bq, bk, bv);

    // attention (windowed + double-buffered + per-warp skip)
    dim3 ga(T_SEQ / 128, BATCH * N_HEADS);
    attn_kernel<<<ga, 256, ATT_SMEM_BYTES>>>();

    // output projection
    dim3 go(D_MODEL / 128, M_ROWS / 128);
    out_kernel<<<go, 128, GEMM_SMEM_BYTES>>>(bo, out);
}

// round 17
// speedup vs baseline: 1.6923x; 1.0098x over previous
#include <cuda_runtime.h>
#include <cuda_bf16.h>
#include <cstdint>

#define D_MODEL 1024
#define N_HEADS 16
#define HD      64
#define T_SEQ   2048
#define BATCH   2
#define M_ROWS  (BATCH * T_SEQ)   // 4096
#define KPAIRS  (D_MODEL / 2)     // 512 pairs per row

// ---------------------------------------------------------------------------
// Scratch (device globals; no allocation allowed)
// ---------------------------------------------------------------------------
__device__ uint32_t g_Xh[M_ROWS * KPAIRS];          // X pre-split hi plane
__device__ uint32_t g_Xl[M_ROWS * KPAIRS];
__device__ uint32_t g_Wh[4 * D_MODEL * KPAIRS];     // Wq,Wk,Wv,Wo hi planes
__device__ uint32_t g_Wl[4 * D_MODEL * KPAIRS];
__device__ uint32_t g_Qh[BATCH * N_HEADS * T_SEQ * (HD / 2)];  // [b,h,t,dpair]
__device__ uint32_t g_Ql[BATCH * N_HEADS * T_SEQ * (HD / 2)];
__device__ uint32_t g_Kh[BATCH * N_HEADS * T_SEQ * (HD / 2)];
__device__ uint32_t g_Kl[BATCH * N_HEADS * T_SEQ * (HD / 2)];
// V packed pair-of-rows: [b,h,tpair,d] u32 = bf16x2(row 2p, row 2p+1) at col d
__device__ uint32_t g_Vph[BATCH * N_HEADS * (T_SEQ / 2) * HD];
__device__ uint32_t g_Vpl[BATCH * N_HEADS * (T_SEQ / 2) * HD];
__device__ uint32_t g_atth[M_ROWS * KPAIRS];        // attention output packed
__device__ uint32_t g_attl[M_ROWS * KPAIRS];

// ---------------------------------------------------------------------------
// helpers
// ---------------------------------------------------------------------------
__device__ __forceinline__ void split2(float x0, float x1, uint32_t& h, uint32_t& l)
{
    __nv_bfloat162 hh = __floats2bfloat162_rn(x0, x1);
    float2 hf = __bfloat1622float2(hh);
    __nv_bfloat162 ll = __floats2bfloat162_rn(x0 - hf.x, x1 - hf.y);
    h = *reinterpret_cast<uint32_t*>(&hh);
    l = *reinterpret_cast<uint32_t*>(&ll);
}

__device__ __forceinline__ void mma16(float* c,
                                      uint32_t a0, uint32_t a1, uint32_t a2, uint32_t a3,
                                      uint32_t b0, uint32_t b1)
{
    asm volatile(
        "mma.sync.aligned.m16n8k16.row.col.f32.bf16.bf16.f32 "
        "{%0,%1,%2,%3}, {%4,%5,%6,%7}, {%8,%9}, {%0,%1,%2,%3};"
        : "+f"(c[0]), "+f"(c[1]), "+f"(c[2]), "+f"(c[3])
        : "r"(a0), "r"(a1), "r"(a2), "r"(a3), "r"(b0), "r"(b1));
}

__device__ __forceinline__ void ldsm4(uint32_t& r0, uint32_t& r1,
                                      uint32_t& r2, uint32_t& r3, uint32_t addr)
{
    asm volatile("ldmatrix.sync.aligned.m8n8.x4.shared.b16 {%0,%1,%2,%3}, [%4];"
                 : "=r"(r0), "=r"(r1), "=r"(r2), "=r"(r3) : "r"(addr));
}

__device__ __forceinline__ void cp16(void* dst_smem, const void* src)
{
    uint32_t s = (uint32_t)__cvta_generic_to_shared(dst_smem);
    asm volatile("cp.async.cg.shared.global [%0], [%1], 16;\n" :: "r"(s), "l"(src));
}
__device__ __forceinline__ void cp_commit()
{
    asm volatile("cp.async.commit_group;\n" ::);
}
template<int N>
__device__ __forceinline__ void cp_wait()
{
    asm volatile("cp.async.wait_group %0;\n" :: "n"(N));
}

// ---------------------------------------------------------------------------
// Prep kernel: split X and Wq/Wk/Wv/Wo into bf16x2 hi/lo planes (once).
// float4 per thread (2 pairs).
// ---------------------------------------------------------------------------
__global__ void __launch_bounds__(256)
prep_kernel(const float* __restrict__ X,
            const float* __restrict__ Wq, const float* __restrict__ Wk,
            const float* __restrict__ Wv, const float* __restrict__ Wo)
{
    const int seg = blockIdx.y;
    const int idx = blockIdx.x * 256 + threadIdx.x;   // float4 index in segment
    const float* src;
    uint32_t *dh, *dl;
    if (seg < 4) {
        src = X + (size_t)seg * 1048576;
        dh = g_Xh + (size_t)seg * 524288;
        dl = g_Xl + (size_t)seg * 524288;
    } else {
        const float* ws[4] = {Wq, Wk, Wv, Wo};
        src = ws[seg - 4];
        dh = g_Wh + (size_t)(seg - 4) * 524288;
        dl = g_Wl + (size_t)(seg - 4) * 524288;
    }
    float4 v = *(const float4*)(src + 4 * (size_t)idx);
    uint32_t h0, l0, h1, l1;
    split2(v.x, v.y, h0, l0);
    split2(v.z, v.w, h1, l1);
    *(uint2*)(dh + 2 * (size_t)idx) = make_uint2(h0, h1);
    *(uint2*)(dl + 2 * (size_t)idx) = make_uint2(l0, l1);
}

// ---------------------------------------------------------------------------
// 3xBF16 mma.sync GEMM tile: Y[128,128 @ (m0,n0)] = X @ W^T + bias
// 256 threads, 8 warps (2x4), warp tile 64x32, acc 64 regs/thread.
// REGISTER-FRAGMENT DOUBLE BUFFERING: two full fragment sets; ks1 frags
// prefetched under ks0's MMAs, next period's ks0 frags prefetched from
// buffer p+1 under ks1's MMAs (NBUF=4 + issue-then-wait<1> keeps buffers
// p and p+1 resident). One barrier per 96-MMA period. 1 CTA/SM (128KB smem).
// Output modes: 0 = packed Q/K planes, 1 = V packed pair-of-rows planes,
//               2 = float row-major (final out).
// ---------------------------------------------------------------------------
#define RSU      16
#define PLANE_U  (128 * RSU)
#define BUF_U    (4 * PLANE_U)
#define NBUF     4
#define NPER     (D_MODEL / 32)
#define GEMM_SMEM_BYTES (NBUF * BUF_U * 4)   // 131072

__device__ __forceinline__ uint32_t sw_off(int row, int chunk)
{
    return (uint32_t)(row * RSU + ((chunk ^ ((row >> 1) & 3)) << 2));
}

#define LDFR(S, STB, KS)                                                      \
    {                                                                         \
        _Pragma("unroll")                                                     \
        for (int mt = 0; mt < 4; mt++) {                                      \
            uint32_t offA = (uint32_t)(baseA[mt] +                            \
                            (((2 * (KS) + hiA) ^ swA[mt]) << 2)) * 4;         \
            ldsm4(Ah##S[mt][0], Ah##S[mt][1], Ah##S[mt][2], Ah##S[mt][3],     \
                  (STB) + offA);                                              \
            ldsm4(Al##S[mt][0], Al##S[mt][1], Al##S[mt][2], Al##S[mt][3],     \
                  (STB) + PLANE_U * 4 + offA);                                \
        }                                                                     \
        uint32_t offB0 = (uint32_t)(baseB0 +                                  \
                         (((2 * (KS) + hiB) ^ swB0) << 2)) * 4;               \
        uint32_t offB1 = (uint32_t)(baseB1 +                                  \
                         (((2 * (KS) + hiB) ^ swB1) << 2)) * 4;               \
        ldsm4(Bh##S[0][0], Bh##S[0][1], Bh##S[1][0], Bh##S[1][1],             \
              (STB) + 2 * PLANE_U * 4 + offB0);                               \
        ldsm4(Bh##S[2][0], Bh##S[2][1], Bh##S[3][0], Bh##S[3][1],             \
              (STB) + 2 * PLANE_U * 4 + offB1);                               \
        ldsm4(Bl##S[0][0], Bl##S[0][1], Bl##S[1][0], Bl##S[1][1],             \
              (STB) + 3 * PLANE_U * 4 + offB0);                               \
        ldsm4(Bl##S[2][0], Bl##S[2][1], Bl##S[3][0], Bl##S[3][1],             \
              (STB) + 3 * PLANE_U * 4 + offB1);                               \
    }

#define MMAS(S)                                                               \
    {                                                                         \
        _Pragma("unroll")                                                     \
        for (int mt = 0; mt < 4; mt++)                                        \
            _Pragma("unroll")                                                 \
            for (int nt = 0; nt < 4; nt++)                                    \
                mma16(acc[mt][nt],                                            \
                      Ah##S[mt][0], Ah##S[mt][1], Ah##S[mt][2], Ah##S[mt][3], \
                      Bh##S[nt][0], Bh##S[nt][1]);                            \
        _Pragma("unroll")                                                     \
        for (int mt = 0; mt < 4; mt++)                                        \
            _Pragma("unroll")                                                 \
            for (int nt = 0; nt < 4; nt++)                                    \
                mma16(acc[mt][nt],                                            \
                      Ah##S[mt][0], Ah##S[mt][1], Ah##S[mt][2], Ah##S[mt][3], \
                      Bl##S[nt][0], Bl##S[nt][1]);                            \
        _Pragma("unroll")                                                     \
        for (int mt = 0; mt < 4; mt++)                                        \
            _Pragma("unroll")                                                 \
            for (int nt = 0; nt < 4; nt++)                                    \
                mma16(acc[mt][nt],                                            \
                      Al##S[mt][0], Al##S[mt][1], Al##S[mt][2], Al##S[mt][3], \
                      Bh##S[nt][0], Bh##S[nt][1]);                            \
    }

__device__ __forceinline__ void gemm_tile(int m0, int n0,
                                          const uint32_t* __restrict__ Xh,
                                          const uint32_t* __restrict__ Xl,
                                          const uint32_t* __restrict__ Wh,
                                          const uint32_t* __restrict__ Wl,
                                          const float* __restrict__ bias,
                                          uint32_t* __restrict__ Yh,
                                          uint32_t* __restrict__ Yl,
                                          float* __restrict__ Yf,
                                          int mode)
{
    extern __shared__ uint32_t smem[];
    const uint32_t sbase = (uint32_t)__cvta_generic_to_shared(smem);

    const int tid  = threadIdx.x;
    const int lane = tid & 31;
    const int wid  = tid >> 5;       // 0..7
    const int wm   = wid >> 2;       // 0..1
    const int wn   = wid & 3;        // 0..3
    const int g    = lane >> 2;
    const int t    = lane & 3;

    // loader: per plane 512 chunks of 16B, 2 per thread
    const int lrow = tid >> 2;       // 0..63 (+64)
    const int lcix = tid & 3;
    const uint32_t ldst0 = sw_off(lrow,      lcix);
    const uint32_t ldst1 = sw_off(lrow + 64, lcix);

    const uint32_t* srcs[4] = {
        Xh + (size_t)m0 * KPAIRS, Xl + (size_t)m0 * KPAIRS,
        Wh + (size_t)n0 * KPAIRS, Wl + (size_t)n0 * KPAIRS };

    // ldmatrix per-lane bases
    const int a_row = (lane & 7) + ((lane >> 3) & 1) * 8;
    const int hiA   = lane >> 4;
    int baseA[4], swA[4];
#pragma unroll
    for (int mt = 0; mt < 4; mt++) {
        int rg = wm * 64 + mt * 16 + a_row;
        baseA[mt] = rg * RSU;
        swA[mt]   = (rg >> 1) & 3;
    }
    const int b_row = (lane & 7) + ((lane >> 4) ? 8 : 0);
    const int hiB   = (lane >> 3) & 1;
    const int rgB0  = wn * 32 + b_row;
    const int rgB1  = rgB0 + 16;
    const int baseB0 = rgB0 * RSU, swB0 = (rgB0 >> 1) & 3;
    const int baseB1 = rgB1 * RSU, swB1 = (rgB1 >> 1) & 3;

    float acc[4][4][4];
#pragma unroll
    for (int i = 0; i < 4; i++)
#pragma unroll
        for (int j = 0; j < 4; j++)
#pragma unroll
            for (int q = 0; q < 4; q++) acc[i][j][q] = 0.f;

    auto load_buf = [&](int b, int p) {
        uint32_t* base = smem + b * BUF_U;
        const int koff = p * 16;
#pragma unroll
        for (int pi = 0; pi < 4; pi++) {
            const uint32_t* sp = srcs[pi] + koff + lcix * 4;
            uint32_t* dp = base + pi * PLANE_U;
            cp16(dp + ldst0, sp + (size_t)lrow * KPAIRS);
            cp16(dp + ldst1, sp + (size_t)(lrow + 64) * KPAIRS);
        }
        cp_commit();
    };

    // fragment register sets (0 = ks0 of current period, 1 = ks1)
    uint32_t Ah0[4][4], Al0[4][4], Bh0[4][2], Bl0[4][2];
    uint32_t Ah1[4][4], Al1[4][4], Bh1[4][2], Bl1[4][2];

    // prologue: buffers 0,1 in flight; buffer 0 ready after wait<1>
    load_buf(0, 0);
    load_buf(1, 1);
    cp_wait<1>();
    __syncthreads();
    LDFR(0, sbase, 0);               // (p=0, ks0)

    for (int p = 0; p < NPER; p++) {
        if (p + 2 < NPER) load_buf((p + 2) & 3, p + 2);
        else              cp_commit();
        cp_wait<1>();                // buffer p+1 complete
        __syncthreads();             // visible to all; buf (p+2)&3 safe to fill

        const uint32_t stb  = sbase + (uint32_t)((p & 3) * BUF_U) * 4;
        const uint32_t stb1 = sbase + (uint32_t)(((p + 1) & 3) * BUF_U) * 4;

        LDFR(1, stb, 1);             // prefetch (p, ks1) under ks0 MMAs
        MMAS(0);
        if (p + 1 < NPER) LDFR(0, stb1, 0);   // prefetch (p+1, ks0)
        MMAS(1);
    }

    // epilogue
#pragma unroll
    for (int mt = 0; mt < 4; mt++) {
        int rm = m0 + wm * 64 + mt * 16 + g;
#pragma unroll
        for (int nt = 0; nt < 4; nt++) {
            int cn = n0 + wn * 32 + nt * 8 + 2 * t;
            float bb0 = bias[cn];
            float bb1 = bias[cn + 1];
            float2 v0 = make_float2(acc[mt][nt][0] + bb0, acc[mt][nt][1] + bb1);
            float2 v1 = make_float2(acc[mt][nt][2] + bb0, acc[mt][nt][3] + bb1);
            if (mode == 0) {
                int head = cn >> 6;
                int pr   = (cn & 63) >> 1;
#pragma unroll
                for (int rr = 0; rr < 2; rr++) {
                    int row = rm + rr * 8;
                    float2 v = rr ? v1 : v0;
                    int bb = row >> 11;
                    int tt = row & (T_SEQ - 1);
                    size_t base = (((size_t)bb * N_HEADS + head) * T_SEQ + tt) * (HD / 2) + pr;
                    uint32_t hh, ll;
                    split2(v.x, v.y, hh, ll);
                    Yh[base] = hh;
                    Yl[base] = ll;
                }
            } else if (mode == 1) {
                int head = cn >> 6;
                int d    = cn & 63;
                float p0x = __shfl_down_sync(0xffffffffu, v0.x, 4);
                float p0y = __shfl_down_sync(0xffffffffu, v0.y, 4);
                float p1x = __shfl_down_sync(0xffffffffu, v1.x, 4);
                float p1y = __shfl_down_sync(0xffffffffu, v1.y, 4);
                if ((g & 1) == 0) {
                    int bb = rm >> 11;
                    int tt = rm & (T_SEQ - 1);
                    size_t idx0 = (((size_t)bb * N_HEADS + head) * (T_SEQ / 2)
                                   + (tt >> 1)) * HD + d;
                    size_t idx1 = idx0 + 4 * HD;
                    uint32_t hh, ll;
                    split2(v0.x, p0x, hh, ll); Yh[idx0] = hh;     Yl[idx0] = ll;
                    split2(v0.y, p0y, hh, ll); Yh[idx0 + 1] = hh; Yl[idx0 + 1] = ll;
                    split2(v1.x, p1x, hh, ll); Yh[idx1] = hh;     Yl[idx1] = ll;
                    split2(v1.y, p1y, hh, ll); Yh[idx1 + 1] = hh; Yl[idx1 + 1] = ll;
                }
            } else {
                *(float2*)(Yf + (size_t)rm * D_MODEL + cn) = v0;
                *(float2*)(Yf + (size_t)(rm + 8) * D_MODEL + cn) = v1;
            }
        }
    }
}

// grid-launched qkv: z = {Q,K,V}
__global__ void __launch_bounds__(256, 1)
qkv_kernel(const float* __restrict__ bq, const float* __restrict__ bk,
           const float* __restrict__ bv)
{
    const int z  = blockIdx.z;
    const int m0 = blockIdx.y * 128;
    const int n0 = blockIdx.x * 128;
    const float* bias = (z == 0) ? bq : (z == 1) ? bk : bv;
    const uint32_t* Wh = g_Wh + (size_t)z * D_MODEL * KPAIRS;
    const uint32_t* Wl = g_Wl + (size_t)z * D_MODEL * KPAIRS;
    if (z == 0)
        gemm_tile(m0, n0, g_Xh, g_Xl, Wh, Wl, bias, g_Qh, g_Ql, nullptr, 0);
    else if (z == 1)
        gemm_tile(m0, n0, g_Xh, g_Xl, Wh, Wl, bias, g_Kh, g_Kl, nullptr, 0);
    else
        gemm_tile(m0, n0, g_Xh, g_Xl, Wh, Wl, bias, g_Vph, g_Vpl, nullptr, 1);
}

__global__ void __launch_bounds__(256, 1)
out_kernel(const float* __restrict__ bo, float* __restrict__ out)
{
    gemm_tile(blockIdx.y * 128, blockIdx.x * 128,
              g_atth, g_attl,
              g_Wh + (size_t)3 * D_MODEL * KPAIRS,
              g_Wl + (size_t)3 * D_MODEL * KPAIRS,
              bo, nullptr, nullptr, out, 2);
}

// ---------------------------------------------------------------------------
// Tensor-core flash attention (frozen from R16): 3xBF16 mma.sync,
// FIXED-MAX softmax, WINDOWED kv sweep, Q-in-registers, double-buffered
// K/V prefetch, per-warp tile skip.
// ---------------------------------------------------------------------------
#define P_OFF   0        // Ph [128][36], Pl at +4608
#define KV0_OFF 9216     // per KV buf: Kh +0, Kl +2304, Vh +4608, Vl +6912
#define KV1_OFF 18432
#define ATT_U32 27648
#define ATT_SMEM_BYTES (ATT_U32 * 4)   // 110592

__global__ void __launch_bounds__(256, 2) attn_kernel()
{
    extern __shared__ uint32_t su[];
    uint32_t* Ph = su + P_OFF;
    uint32_t* Pl = su + P_OFF + 4608;

    const int tid  = threadIdx.x;
    const int lane = tid & 31;
    const int w    = tid >> 5;
    const int g    = lane >> 2;
    const int t    = lane & 3;

    const int bh = blockIdx.y;
    const int i0 = (int)blockIdx.x * 128;

    const uint32_t* Qh_g = g_Qh + (size_t)bh * T_SEQ * (HD / 2);
    const uint32_t* Ql_g = g_Ql + (size_t)bh * T_SEQ * (HD / 2);
    const uint32_t* Kh_g = g_Kh + (size_t)bh * T_SEQ * (HD / 2);
    const uint32_t* Kl_g = g_Kl + (size_t)bh * T_SEQ * (HD / 2);
    const uint32_t* Vph_g = g_Vph + (size_t)bh * (T_SEQ / 2) * HD;
    const uint32_t* Vpl_g = g_Vpl + (size_t)bh * (T_SEQ / 2) * HD;

    // ---- stage Q into KV1 region, then lift fragments to registers ----
#pragma unroll
    for (int rep = 0; rep < 4; rep++) {
        int idx = tid + rep * 256;
        int r = idx >> 3;
        int c = (idx & 7) * 4;
        cp16(su + KV1_OFF + r * 36 + c,        Qh_g + (size_t)(i0 + r) * 32 + c);
        cp16(su + KV1_OFF + 4608 + r * 36 + c, Ql_g + (size_t)(i0 + r) * 32 + c);
    }
    cp_commit();
    cp_wait<0>();
    __syncthreads();

    const int rw0 = w * 16 + g;
    const int rw1 = rw0 + 8;

    uint32_t qh[4][4], ql[4][4];
#pragma unroll
    for (int ks = 0; ks < 4; ks++) {
        const int kp = ks * 8 + t;
        qh[ks][0] = su[KV1_OFF + rw0 * 36 + kp];
        qh[ks][1] = su[KV1_OFF + rw1 * 36 + kp];
        qh[ks][2] = su[KV1_OFF + rw0 * 36 + kp + 4];
        qh[ks][3] = su[KV1_OFF + rw1 * 36 + kp + 4];
        ql[ks][0] = su[KV1_OFF + 4608 + rw0 * 36 + kp];
        ql[ks][1] = su[KV1_OFF + 4608 + rw1 * 36 + kp];
        ql[ks][2] = su[KV1_OFF + 4608 + rw0 * 36 + kp + 4];
        ql[ks][3] = su[KV1_OFF + 4608 + rw1 * 36 + kp + 4];
    }
    __syncthreads();   // everyone done reading Q before KV1 is reused

    const int i_r0 = i0 + w * 16 + g;
    const int i_r1 = i_r0 + 8;
    const int warp_lo = i0 + w * 16;
    const int warp_hi = warp_lo + 15;

    const float C1 = 0.18033688011f;   // 0.125 * log2(e)
    const float C2 = 1.44269504089f;   // log2(e)
    const float C3 = 5.77078016356f;   // 4 * log2(e)

    float l0r = 0.f, l1r = 0.f;
    float o[8][4];
#pragma unroll
    for (int nt = 0; nt < 8; nt++)
#pragma unroll
        for (int q = 0; q < 4; q++) o[nt][q] = 0.f;

    auto load_kv = [&](int kb, int j0) {
#pragma unroll
        for (int rep = 0; rep < 2; rep++) {
            int idx = tid + rep * 256;
            int r = idx >> 3;
            int c = (idx & 7) * 4;
            cp16(su + kb + r * 36 + c,        Kh_g + (size_t)(j0 + r) * 32 + c);
            cp16(su + kb + 2304 + r * 36 + c, Kl_g + (size_t)(j0 + r) * 32 + c);
        }
#pragma unroll
        for (int rep = 0; rep < 2; rep++) {
            int idx = tid + rep * 256;
            int p = idx >> 4;
            int c = (idx & 15) * 4;
            cp16(su + kb + 4608 + p * 72 + c,
                 Vph_g + ((size_t)(j0 >> 1) + p) * HD + c);
            cp16(su + kb + 6912 + p * 72 + c,
                 Vpl_g + ((size_t)(j0 >> 1) + p) * HD + c);
        }
        cp_commit();
    };

    const int j0_lo = (i0 >= 64) ? (i0 - 64) : 0;
    const int nT    = (i0 + 64 - j0_lo) / 64 + 1;   // 2 or 3 tiles

    load_kv(KV0_OFF, j0_lo);

    for (int jt = 0; jt < nT; jt++) {
        const int j0 = j0_lo + jt * 64;
        const int kb = (jt & 1) ? KV1_OFF : KV0_OFF;
        const int ko = (jt & 1) ? KV0_OFF : KV1_OFF;

        __syncthreads();
        if (jt + 1 < nT) load_kv(ko, j0 + 64);
        else             cp_commit();
        cp_wait<1>();
        __syncthreads();

        if (j0 > warp_hi || j0 < warp_lo - 127) continue;

        const uint32_t* Kh = su + kb;
        const uint32_t* Kl = su + kb + 2304;
        const uint32_t* Vh = su + kb + 4608;
        const uint32_t* Vl = su + kb + 6912;

        float s[8][4];
#pragma unroll
        for (int nt = 0; nt < 8; nt++)
#pragma unroll
            for (int q = 0; q < 4; q++) s[nt][q] = 0.f;

#pragma unroll
        for (int ks = 0; ks < 4; ks++) {
            const int kp = ks * 8 + t;
#pragma unroll
            for (int nt = 0; nt < 8; nt++) {
                int rn = nt * 8 + g;
                uint32_t b0h = Kh[rn * 36 + kp],     b0l = Kl[rn * 36 + kp];
                uint32_t b1h = Kh[rn * 36 + kp + 4], b1l = Kl[rn * 36 + kp + 4];
                mma16(s[nt], qh[ks][0], qh[ks][1], qh[ks][2], qh[ks][3], b0h, b1h);
                mma16(s[nt], qh[ks][0], qh[ks][1], qh[ks][2], qh[ks][3], b0l, b1l);
                mma16(s[nt], ql[ks][0], ql[ks][1], ql[ks][2], ql[ks][3], b0h, b1h);
            }
        }

#pragma unroll
        for (int nt = 0; nt < 8; nt++) {
            int jb = j0 + nt * 8 + 2 * t;
            float d0 = fmaf((float)(jb - i_r0), C2, -C3);
            float d1 = fmaf((float)(jb - i_r1), C2, -C3);
            float p0 = (jb     <= i_r0) ? exp2f(fmaf(s[nt][0], C1, d0))      : 0.f;
            float p1 = (jb + 1 <= i_r0) ? exp2f(fmaf(s[nt][1], C1, d0 + C2)) : 0.f;
            float p2 = (jb     <= i_r1) ? exp2f(fmaf(s[nt][2], C1, d1))      : 0.f;
            float p3 = (jb + 1 <= i_r1) ? exp2f(fmaf(s[nt][3], C1, d1 + C2)) : 0.f;
            l0r += p0 + p1;
            l1r += p2 + p3;
            uint32_t hh, ll;
            split2(p0, p1, hh, ll);
            Ph[rw0 * 36 + nt * 4 + t] = hh;
            Pl[rw0 * 36 + nt * 4 + t] = ll;
            split2(p2, p3, hh, ll);
            Ph[rw1 * 36 + nt * 4 + t] = hh;
            Pl[rw1 * 36 + nt * 4 + t] = ll;
        }

        __syncwarp();

#pragma unroll
        for (int ks = 0; ks < 4; ks++) {
            const int kp = ks * 8 + t;
            uint32_t a0h = Ph[rw0 * 36 + kp],     a0l = Pl[rw0 * 36 + kp];
            uint32_t a1h = Ph[rw1 * 36 + kp],     a1l = Pl[rw1 * 36 + kp];
            uint32_t a2h = Ph[rw0 * 36 + kp + 4], a2l = Pl[rw0 * 36 + kp + 4];
            uint32_t a3h = Ph[rw1 * 36 + kp + 4], a3l = Pl[rw1 * 36 + kp + 4];
#pragma unroll
            for (int nt = 0; nt < 8; nt++) {
                int n = nt * 8 + g;
                uint32_t b0h = Vh[kp * 72 + n],       b0l = Vl[kp * 72 + n];
                uint32_t b1h = Vh[(kp + 4) * 72 + n], b1l = Vl[(kp + 4) * 72 + n];
                mma16(o[nt], a0h, a1h, a2h, a3h, b0h, b1h);
                mma16(o[nt], a0h, a1h, a2h, a3h, b0l, b1l);
                mma16(o[nt], a0l, a1l, a2l, a3l, b0h, b1h);
            }
        }
        __syncwarp();
    }

    l0r += __shfl_xor_sync(0xffffffffu, l0r, 1);
    l0r += __shfl_xor_sync(0xffffffffu, l0r, 2);
    l1r += __shfl_xor_sync(0xffffffffu, l1r, 1);
    l1r += __shfl_xor_sync(0xffffffffu, l1r, 2);

    const int b = bh >> 4;
    const int hh_ = bh & 15;
    const float inv0 = 1.0f / l0r;
    const float inv1 = 1.0f / l1r;
    size_t pb0 = ((size_t)b * T_SEQ + i_r0) * KPAIRS + hh_ * 32;
    size_t pb1 = ((size_t)b * T_SEQ + i_r1) * KPAIRS + hh_ * 32;
#pragma unroll
    for (int nt = 0; nt < 8; nt++) {
        int p = nt * 4 + t;
        uint32_t uh, ul;
        split2(o[nt][0] * inv0, o[nt][1] * inv0, uh, ul);
        g_atth[pb0 + p] = uh;
        g_attl[pb0 + p] = ul;
        split2(o[nt][2] * inv1, o[nt][3] * inv1, uh, ul);
        g_atth[pb1 + p] = uh;
        g_attl[pb1 + p] = ul;
    }
}

// ---------------------------------------------------------------------------
// Launch
// ---------------------------------------------------------------------------
extern "C" void kernel_launch(void* const* d_in, const int* in_sizes, int n_in,
                              void* d_out, int out_size)
{
    const float* x  = (const float*)d_in[0];
    const float* Wq = (const float*)d_in[1];
    const float* bq = (const float*)d_in[2];
    const float* Wk = (const float*)d_in[3];
    const float* bk = (const float*)d_in[4];
    const float* Wv = (const float*)d_in[5];
    const float* bv = (const float*)d_in[6];
    const float* Wo = (const float*)d_in[7];
    const float* bo = (const float*)d_in[8];
    float* out = (float*)d_out;

    cudaFuncSetAttribute(qkv_kernel,
                         cudaFuncAttributeMaxDynamicSharedMemorySize, GEMM_SMEM_BYTES);
    cudaFuncSetAttribute(out_kernel,
                         cudaFuncAttributeMaxDynamicSharedMemorySize, GEMM_SMEM_BYTES);
    cudaFuncSetAttribute(attn_kernel,
                         cudaFuncAttributeMaxDynamicSharedMemorySize, ATT_SMEM_BYTES);

    // pre-split X and all weights to bf16 hi/lo planes (float4 per thread)
    dim3 gp(1024, 8);
    prep_kernel<<<gp, 256>>>(x, Wq, Wk, Wv, Wo);

    // QKV projections (grid-launched, z = {Q,K,V}), 256-thread blocks
    dim3 gq(D_MODEL / 128, M_ROWS / 128, 3);
    qkv_kernel<<<gq, 256, GEMM_SMEM_BYTES>>>(bq, bk, bv);

    // attention (windowed + double-buffered + per-warp skip)
    dim3 ga(T_SEQ / 128, BATCH * N_HEADS);
    attn_kernel<<<ga, 256, ATT_SMEM_BYTES>>>();

    // output projection
    dim3 go(D_MODEL / 128, M_ROWS / 128);
    out_kernel<<<go, 256, GEMM_SMEM_BYTES>>>(bo, out);
}